// round 1
// baseline (speedup 1.0000x reference)
#include <cuda_runtime.h>
#include <math.h>

#define N0    10000
#define NTOK  10001
#define DIM   512
#define NPAD  10240
#define PADR  239
#define HEADS 8
#define DH    64
#define MLM   256
#define HH    100

// ---------------- scratch (single device global, no allocations) -------------
constexpr size_t O_H0 = 0;                                  // NTOK*DIM
constexpr size_t O_H1 = O_H0 + (size_t)NTOK*DIM;
constexpr size_t O_XP = O_H1 + (size_t)NTOK*DIM;            // NPAD*DIM (LN+pad; final hn)
constexpr size_t O_QKV= O_XP + (size_t)NPAD*DIM;            // NPAD*1536
constexpr size_t O_AO = O_QKV+ (size_t)NPAD*3*DIM;          // NPAD*DIM
constexpr size_t O_QL = O_AO + (size_t)NPAD*DIM;
constexpr size_t O_KL = O_QL + (size_t)HEADS*MLM*DH;
constexpr size_t O_X  = O_KL + (size_t)HEADS*MLM*DH;        // attn2
constexpr size_t O_Z0 = O_X  + (size_t)HEADS*MLM*MLM;
constexpr size_t O_Z1 = O_Z0 + (size_t)HEADS*MLM*MLM;
constexpr size_t O_TA = O_Z1 + (size_t)HEADS*MLM*MLM;
constexpr size_t O_TU = O_TA + (size_t)HEADS*MLM*MLM;
constexpr size_t O_TT = O_TU + (size_t)HEADS*MLM*MLM;
constexpr size_t O_T3 = O_TT + (size_t)HEADS*MLM*MLM;       // attn3@v : H*256*64
constexpr size_t O_W  = O_T3 + (size_t)HEADS*MLM*DH;        // Z@(attn3@v)
constexpr size_t O_RED= O_W  + (size_t)HEADS*MLM*DH;
constexpr size_t SCRATCH_TOTAL = O_RED + 8;

__device__ float g_scratch[SCRATCH_TOTAL];

// ---------------- reduction helpers (blockDim.x == 256) ----------------------
__device__ __forceinline__ float warpRedSum(float v){
  #pragma unroll
  for (int s=16;s;s>>=1) v += __shfl_xor_sync(0xffffffffu, v, s);
  return v;
}
__device__ __forceinline__ float warpRedMax(float v){
  #pragma unroll
  for (int s=16;s;s>>=1) v = fmaxf(v, __shfl_xor_sync(0xffffffffu, v, s));
  return v;
}
__device__ __forceinline__ float blockRedSum(float v, float* red){
  int lane=threadIdx.x&31, wid=threadIdx.x>>5;
  v = warpRedSum(v);
  if (lane==0) red[wid]=v;
  __syncthreads();
  if (wid==0){
    float t = (lane<8)? red[lane] : 0.f;
    t = warpRedSum(t);
    if (lane==0) red[0]=t;
  }
  __syncthreads();
  float r = red[0];
  __syncthreads();
  return r;
}
__device__ __forceinline__ float blockRedMax(float v, float* red){
  int lane=threadIdx.x&31, wid=threadIdx.x>>5;
  v = warpRedMax(v);
  if (lane==0) red[wid]=v;
  __syncthreads();
  if (wid==0){
    float t = (lane<8)? red[lane] : -1e30f;
    t = warpRedMax(t);
    if (lane==0) red[0]=t;
  }
  __syncthreads();
  float r = red[0];
  __syncthreads();
  return r;
}

// ---------------- build h0 ---------------------------------------------------
__global__ void k_build(const float* __restrict__ x, const float* __restrict__ cls,
                        float* __restrict__ h){
  int idx = blockIdx.x*blockDim.x + threadIdx.x;
  if (idx >= NTOK*DIM) return;
  int r = idx >> 9, c = idx & 511;
  h[idx] = (r == 0) ? cls[c] : x[(size_t)(r-1)*DIM + c];
}

// ---------------- layernorm (+ optional front zero-pad) ----------------------
__global__ __launch_bounds__(256) void k_lnpad(const float* __restrict__ src,
    float* __restrict__ dst, const float* __restrict__ w, const float* __restrict__ b,
    int pad){
  __shared__ float red[32];
  int r = blockIdx.x, tid = threadIdx.x;
  if (r < pad){
    dst[(size_t)r*DIM + tid] = 0.f;
    dst[(size_t)r*DIM + tid + 256] = 0.f;
    return;
  }
  const float* row = src + (size_t)(r-pad)*DIM;
  float v0 = row[tid], v1 = row[tid+256];
  float mu = blockRedSum(v0+v1, red) * (1.f/DIM);
  float d0 = v0-mu, d1 = v1-mu;
  float var = blockRedSum(d0*d0 + d1*d1, red) * (1.f/DIM);
  float rs = 1.f / sqrtf(var + 1e-5f);
  dst[(size_t)r*DIM + tid]       = d0*rs*w[tid]     + b[tid];
  dst[(size_t)r*DIM + tid + 256] = d1*rs*w[tid+256] + b[tid+256];
}

// ---------------- SGEMM: C = A(MxK) @ B(KxN) [+bias][+Cres] ------------------
// N % 64 == 0, K % 16 == 0. 128x64 tile, 256 threads, 8x4 per thread.
__global__ __launch_bounds__(256) void k_sgemm(
    const float* __restrict__ A, const float* __restrict__ B,
    const float* __restrict__ bias, const float* __restrict__ Cres,
    float* __restrict__ C, int M, int N, int K){
  __shared__ float As[16][132];
  __shared__ float Bs[16][64];
  const int bm = blockIdx.y * 128;
  const int bn = blockIdx.x * 64;
  const int tid = threadIdx.x;
  const int tr = tid / 16;   // 0..15 -> rows tr*8..
  const int tc = tid % 16;   // 0..15 -> cols tc*4..
  float acc[8][4];
  #pragma unroll
  for (int i=0;i<8;i++)
    #pragma unroll
    for (int j=0;j<4;j++) acc[i][j]=0.f;

  for (int k0 = 0; k0 < K; k0 += 16){
    #pragma unroll
    for (int l = 0; l < 2; l++){
      int idx = tid + l*256;              // 512 float4 slots
      int row = idx >> 2;
      int cc  = (idx & 3) * 4;
      float4 v = make_float4(0.f,0.f,0.f,0.f);
      if (bm + row < M) v = *(const float4*)(A + (size_t)(bm+row)*K + k0 + cc);
      As[cc+0][row]=v.x; As[cc+1][row]=v.y; As[cc+2][row]=v.z; As[cc+3][row]=v.w;
    }
    {
      int row = tid / 16;
      int cc  = (tid % 16) * 4;
      float4 v = *(const float4*)(B + (size_t)(k0+row)*N + bn + cc);
      *(float4*)&Bs[row][cc] = v;
    }
    __syncthreads();
    #pragma unroll
    for (int k=0;k<16;k++){
      float a[8], bb[4];
      #pragma unroll
      for (int i=0;i<8;i++) a[i]=As[k][tr*8+i];
      #pragma unroll
      for (int j=0;j<4;j++) bb[j]=Bs[k][tc*4+j];
      #pragma unroll
      for (int i=0;i<8;i++)
        #pragma unroll
        for (int j=0;j<4;j++)
          acc[i][j] += a[i]*bb[j];
    }
    __syncthreads();
  }
  #pragma unroll
  for (int i=0;i<8;i++){
    int row = bm + tr*8 + i;
    if (row >= M) continue;
    #pragma unroll
    for (int j=0;j<4;j++){
      int col = bn + tc*4 + j;
      float v = acc[i][j];
      if (bias) v += bias[col];
      if (Cres) v += Cres[(size_t)row*N + col];
      C[(size_t)row*N + col] = v;
    }
  }
}

// ---------------- landmarks --------------------------------------------------
__global__ __launch_bounds__(64) void k_land(const float* __restrict__ qkv,
    float* __restrict__ ql, float* __restrict__ kl){
  int m = blockIdx.x, h = blockIdx.y, d = threadIdx.x;
  float sq = 0.f, sk = 0.f;
  #pragma unroll 8
  for (int j=0;j<40;j++){
    size_t base = (size_t)(m*40+j)*1536 + h*64 + d;
    sq += qkv[base];
    sk += qkv[base + 512];
  }
  ql[(size_t)(h*MLM+m)*64 + d] = sq * (0.125f/40.f);  // DH^-0.5 folded in
  kl[(size_t)(h*MLM+m)*64 + d] = sk * (1.f/40.f);
}

// ---------------- attn2 = softmax(ql @ kl^T) ---------------------------------
__global__ __launch_bounds__(256) void k_attn2(const float* __restrict__ ql,
    const float* __restrict__ kl, float* __restrict__ X){
  __shared__ float4 q4[16];
  __shared__ float red[32];
  int i = blockIdx.x, h = blockIdx.y, j = threadIdx.x;
  if (j < 16) q4[j] = ((const float4*)(ql + (size_t)(h*MLM+i)*64))[j];
  __syncthreads();
  const float4* kp = (const float4*)(kl + (size_t)(h*MLM+j)*64);
  float s = 0.f;
  #pragma unroll
  for (int t=0;t<16;t++){
    float4 kv = kp[t], q = q4[t];
    s += q.x*kv.x + q.y*kv.y + q.z*kv.z + q.w*kv.w;
  }
  float mx = blockRedMax(s, red);
  float e = expf(s - mx);
  float sm = blockRedSum(e, red);
  X[(size_t)(h*MLM+i)*MLM + j] = e / sm;
}

// ---------------- pinv init: abs row/col max ---------------------------------
__global__ void k_zero2(float* red){ if (threadIdx.x < 2) red[threadIdx.x] = 0.f; }

__global__ __launch_bounds__(256) void k_absmax(const float* __restrict__ X,
    float* __restrict__ red_out, int mode){
  __shared__ float red[32];
  int a = blockIdx.x, h = blockIdx.y, t = threadIdx.x;
  float v;
  if (mode == 0) v = fabsf(X[(size_t)(h*MLM+a)*MLM + t]);   // row sums
  else           v = fabsf(X[(size_t)(h*MLM+t)*MLM + a]);   // col sums
  float s = blockRedSum(v, red);
  if (t == 0) atomicMax((int*)(red_out + mode), __float_as_int(s));
}

__global__ void k_zinit(const float* __restrict__ X, float* __restrict__ Z,
                        const float* __restrict__ red){
  int idx = blockIdx.x*blockDim.x + threadIdx.x;
  if (idx >= HEADS*MLM*MLM) return;
  int h = idx >> 16, r = (idx >> 8) & 255, c = idx & 255;
  float inv = 1.f / (red[0] * red[1]);
  Z[idx] = X[(size_t)h*MLM*MLM + (size_t)c*MLM + r] * inv;
}

// ---------------- batched gemm: C[h] = scale * A[h] @ (bI*I + bS*B[h]) -------
// M=256, N in {256,64}, K=256.  64x64 tile, 256 threads, 4x4 per thread.
__global__ __launch_bounds__(256) void k_bgemm(
    const float* __restrict__ A, const float* __restrict__ B, float* __restrict__ C,
    int N, long long sA, long long sB, long long sC,
    float bI, float bS, float scale){
  __shared__ float As[32][68];
  __shared__ float Bs[32][64];
  const float* Ah = A + blockIdx.z * sA;
  const float* Bh = B + blockIdx.z * sB;
  float* Ch = C + blockIdx.z * sC;
  const int K = 256;
  int bm = blockIdx.y * 64, bn = blockIdx.x * 64;
  int tid = threadIdx.x;
  int tr = tid / 16, tc = tid % 16;
  float acc[4][4];
  #pragma unroll
  for (int i=0;i<4;i++)
    #pragma unroll
    for (int j=0;j<4;j++) acc[i][j]=0.f;

  for (int k0=0;k0<K;k0+=32){
    #pragma unroll
    for (int l=0;l<2;l++){
      int idx = tid + l*256;
      int row = idx >> 3;
      int cc  = (idx & 7) * 4;
      float4 v = *(const float4*)(Ah + (size_t)(bm+row)*K + k0 + cc);
      As[cc+0][row]=v.x; As[cc+1][row]=v.y; As[cc+2][row]=v.z; As[cc+3][row]=v.w;
    }
    #pragma unroll
    for (int l=0;l<8;l++){
      int idx = tid + l*256;
      int r = idx >> 6, c = idx & 63;
      int gk = k0 + r, gc = bn + c;
      float v = bS * Bh[(size_t)gk*N + gc];
      if (gk == gc) v += bI;
      Bs[r][c] = v;
    }
    __syncthreads();
    #pragma unroll
    for (int k=0;k<32;k++){
      float a[4], bb[4];
      #pragma unroll
      for (int i=0;i<4;i++) a[i]=As[k][tr*4+i];
      #pragma unroll
      for (int j=0;j<4;j++) bb[j]=Bs[k][tc*4+j];
      #pragma unroll
      for (int i=0;i<4;i++)
        #pragma unroll
        for (int j=0;j<4;j++)
          acc[i][j] += a[i]*bb[j];
    }
    __syncthreads();
  }
  #pragma unroll
  for (int i=0;i<4;i++)
    #pragma unroll
    for (int j=0;j<4;j++)
      Ch[(size_t)(bm+tr*4+i)*N + bn+tc*4+j] = scale * acc[i][j];
}

// ---------------- t3v = softmax(ql @ k^T) @ v  (4 landmark rows / block) -----
__global__ __launch_bounds__(256) void k_attn3v(const float* __restrict__ qkv,
    const float* __restrict__ ql, float* __restrict__ t3v){
  extern __shared__ float sc[];          // 4 * NPAD floats
  __shared__ float4 qs[4][16];
  __shared__ float red[32];
  __shared__ float4 red4[256];
  __shared__ float rowmax[4], rowsum[4];
  int h = blockIdx.y;
  int m0 = blockIdx.x * 4;
  int tid = threadIdx.x;
  if (tid < 64){
    int r = tid >> 4, t = tid & 15;
    qs[r][t] = ((const float4*)(ql + (size_t)(h*MLM+m0+r)*64))[t];
  }
  __syncthreads();
  float lmax0=-1e30f, lmax1=-1e30f, lmax2=-1e30f, lmax3=-1e30f;
  for (int n = tid; n < NPAD; n += 256){
    const float4* kp = (const float4*)(qkv + (size_t)n*1536 + 512 + h*64);
    float s0=0,s1=0,s2=0,s3=0;
    #pragma unroll
    for (int t=0;t<16;t++){
      float4 kv = kp[t];
      float4 a0=qs[0][t]; s0 += a0.x*kv.x+a0.y*kv.y+a0.z*kv.z+a0.w*kv.w;
      float4 a1=qs[1][t]; s1 += a1.x*kv.x+a1.y*kv.y+a1.z*kv.z+a1.w*kv.w;
      float4 a2=qs[2][t]; s2 += a2.x*kv.x+a2.y*kv.y+a2.z*kv.z+a2.w*kv.w;
      float4 a3=qs[3][t]; s3 += a3.x*kv.x+a3.y*kv.y+a3.z*kv.z+a3.w*kv.w;
    }
    sc[0*NPAD+n]=s0; sc[1*NPAD+n]=s1; sc[2*NPAD+n]=s2; sc[3*NPAD+n]=s3;
    lmax0=fmaxf(lmax0,s0); lmax1=fmaxf(lmax1,s1); lmax2=fmaxf(lmax2,s2); lmax3=fmaxf(lmax3,s3);
  }
  {
    float m;
    m = blockRedMax(lmax0, red); if (tid==0) rowmax[0]=m;
    m = blockRedMax(lmax1, red); if (tid==0) rowmax[1]=m;
    m = blockRedMax(lmax2, red); if (tid==0) rowmax[2]=m;
    m = blockRedMax(lmax3, red); if (tid==0) rowmax[3]=m;
  }
  __syncthreads();
  float ls0=0,ls1=0,ls2=0,ls3=0;
  for (int n = tid; n < NPAD; n += 256){
    float e;
    e = expf(sc[0*NPAD+n]-rowmax[0]); sc[0*NPAD+n]=e; ls0+=e;
    e = expf(sc[1*NPAD+n]-rowmax[1]); sc[1*NPAD+n]=e; ls1+=e;
    e = expf(sc[2*NPAD+n]-rowmax[2]); sc[2*NPAD+n]=e; ls2+=e;
    e = expf(sc[3*NPAD+n]-rowmax[3]); sc[3*NPAD+n]=e; ls3+=e;
  }
  {
    float s;
    s = blockRedSum(ls0, red); if (tid==0) rowsum[0]=s;
    s = blockRedSum(ls1, red); if (tid==0) rowsum[1]=s;
    s = blockRedSum(ls2, red); if (tid==0) rowsum[2]=s;
    s = blockRedSum(ls3, red); if (tid==0) rowsum[3]=s;
  }
  __syncthreads();
  // phase 2: weighted v sum
  int part = tid >> 4;      // 16 parts
  int d4 = tid & 15;        // 16 float4 lanes over 64 dims
  float4 acc0=make_float4(0,0,0,0), acc1=acc0, acc2=acc0, acc3=acc0;
  for (int n = part; n < NPAD; n += 16){
    float4 vv = *(const float4*)(qkv + (size_t)n*1536 + 1024 + h*64 + d4*4);
    float p;
    p = sc[0*NPAD+n]; acc0.x+=p*vv.x; acc0.y+=p*vv.y; acc0.z+=p*vv.z; acc0.w+=p*vv.w;
    p = sc[1*NPAD+n]; acc1.x+=p*vv.x; acc1.y+=p*vv.y; acc1.z+=p*vv.z; acc1.w+=p*vv.w;
    p = sc[2*NPAD+n]; acc2.x+=p*vv.x; acc2.y+=p*vv.y; acc2.z+=p*vv.z; acc2.w+=p*vv.w;
    p = sc[3*NPAD+n]; acc3.x+=p*vv.x; acc3.y+=p*vv.y; acc3.z+=p*vv.z; acc3.w+=p*vv.w;
  }
  #pragma unroll
  for (int r=0;r<4;r++){
    float4 a = (r==0)?acc0:(r==1)?acc1:(r==2)?acc2:acc3;
    red4[tid] = a;
    __syncthreads();
    if (part == 0){
      float4 s = red4[d4];
      #pragma unroll
      for (int pp=1;pp<16;pp++){
        float4 t = red4[pp*16+d4];
        s.x+=t.x; s.y+=t.y; s.z+=t.z; s.w+=t.w;
      }
      float inv = 1.f/rowsum[r];
      ((float4*)(t3v + (size_t)(h*MLM+m0+r)*64))[d4] =
          make_float4(s.x*inv, s.y*inv, s.z*inv, s.w*inv);
    }
    __syncthreads();
  }
}

// ---------------- out = softmax(q @ kl^T) @ W (8 tokens / block) -------------
__global__ __launch_bounds__(256) void k_attn1W(const float* __restrict__ qkv,
    const float* __restrict__ kl, const float* __restrict__ W, float* __restrict__ ao){
  __shared__ float4 qs[8][16];
  __shared__ float p[8][256];
  __shared__ float red[32];
  int h = blockIdx.y;
  int t0 = blockIdx.x * 8;
  int tid = threadIdx.x;
  for (int idx = tid; idx < 8*16; idx += 256){
    int r = idx >> 4, t = idx & 15;
    float4 v = ((const float4*)(qkv + (size_t)(t0+r)*1536 + h*64))[t];
    v.x*=0.125f; v.y*=0.125f; v.z*=0.125f; v.w*=0.125f;
    qs[r][t]=v;
  }
  __syncthreads();
  {
    int m = tid;
    const float4* kp = (const float4*)(kl + (size_t)(h*MLM+m)*64);
    float a[8];
    #pragma unroll
    for (int r=0;r<8;r++) a[r]=0.f;
    #pragma unroll
    for (int t=0;t<16;t++){
      float4 kv = kp[t];
      #pragma unroll
      for (int r=0;r<8;r++){
        float4 q = qs[r][t];
        a[r] += q.x*kv.x + q.y*kv.y + q.z*kv.z + q.w*kv.w;
      }
    }
    #pragma unroll
    for (int r=0;r<8;r++) p[r][m] = a[r];
  }
  __syncthreads();
  #pragma unroll
  for (int r=0;r<8;r++){
    float s = p[r][tid];
    float mx = blockRedMax(s, red);
    float e = expf(s - mx);
    float sm = blockRedSum(e, red);
    p[r][tid] = e / sm;
  }
  __syncthreads();
  int g = tid >> 6, d = tid & 63;
  float o0=0.f, o1=0.f;
  for (int m=0;m<256;m++){
    float w = W[(size_t)(h*MLM+m)*64 + d];
    o0 += p[g][m]*w;
    o1 += p[g+4][m]*w;
  }
  ao[(size_t)(t0+g)*DIM   + h*64 + d] = o0;
  ao[(size_t)(t0+g+4)*DIM + h*64 + d] = o1;
}

// ---------------- residual depthwise conv (kernel 33 along sequence) ---------
__global__ void k_convres(const float* __restrict__ qkv, const float* __restrict__ rw,
                          float* __restrict__ ao){
  int idx = blockIdx.x*blockDim.x + threadIdx.x;
  if (idx >= NPAD*DIM) return;
  int n = idx >> 9, c = idx & 511;
  int h = c >> 6;
  float acc = ao[idx];
  #pragma unroll
  for (int t=0;t<33;t++){
    int s = n + t - 16;
    if (s >= 0 && s < NPAD)
      acc += rw[h*33+t] * qkv[(size_t)s*1536 + 1024 + c];
  }
  ao[idx] = acc;
}

// ---------------- PPEG -------------------------------------------------------
__global__ void k_cls(const float* __restrict__ hin, float* __restrict__ hout){
  int c = blockIdx.x*blockDim.x + threadIdx.x;
  if (c < DIM) hout[c] = hin[c];
}

__global__ __launch_bounds__(128) void k_ppeg(const float* __restrict__ hin,
    const float* __restrict__ w7, const float* __restrict__ b7,
    const float* __restrict__ w5, const float* __restrict__ b5,
    const float* __restrict__ w3, const float* __restrict__ b3,
    float* __restrict__ hout){
  int pos = blockIdx.x;                 // 0..9999
  int c = blockIdx.y*128 + threadIdx.x;
  int i = pos / HH, j = pos % HH;
  float acc = hin[(size_t)(1+pos)*DIM + c] + b7[c] + b5[c] + b3[c];
  #pragma unroll
  for (int a=0;a<7;a++){
    int ii = i + a - 3;
    if (ii < 0 || ii >= HH) continue;
    #pragma unroll
    for (int bb=0;bb<7;bb++){
      int jj = j + bb - 3;
      if (jj < 0 || jj >= HH) continue;
      acc += hin[(size_t)(1+ii*HH+jj)*DIM + c] * w7[(size_t)c*49 + a*7 + bb];
    }
  }
  #pragma unroll
  for (int a=0;a<5;a++){
    int ii = i + a - 2;
    if (ii < 0 || ii >= HH) continue;
    #pragma unroll
    for (int bb=0;bb<5;bb++){
      int jj = j + bb - 2;
      if (jj < 0 || jj >= HH) continue;
      acc += hin[(size_t)(1+ii*HH+jj)*DIM + c] * w5[(size_t)c*25 + a*5 + bb];
    }
  }
  #pragma unroll
  for (int a=0;a<3;a++){
    int ii = i + a - 1;
    if (ii < 0 || ii >= HH) continue;
    #pragma unroll
    for (int bb=0;bb<3;bb++){
      int jj = j + bb - 1;
      if (jj < 0 || jj >= HH) continue;
      acc += hin[(size_t)(1+ii*HH+jj)*DIM + c] * w3[(size_t)c*9 + a*3 + bb];
    }
  }
  hout[(size_t)(1+pos)*DIM + c] = acc;
}

// ---------------- heads ------------------------------------------------------
__global__ void k_heads(const float* __restrict__ hn,
    const float* __restrict__ fcw, const float* __restrict__ fcb,
    const float* __restrict__ pcw, const float* __restrict__ pcb,
    float* __restrict__ out){
  int warp = (blockIdx.x*blockDim.x + threadIdx.x) >> 5;
  int lane = threadIdx.x & 31;
  if (warp >= NTOK) return;
  const float* hr = hn + (size_t)warp*DIM;
  const float* Wm = (warp == 0) ? fcw : pcw;
  float d0=0.f, d1=0.f;
  for (int k=lane;k<DIM;k+=32){
    float v = hr[k];
    d0 += v*Wm[2*k];
    d1 += v*Wm[2*k+1];
  }
  d0 = warpRedSum(d0);
  d1 = warpRedSum(d1);
  if (lane == 0){
    if (warp == 0){
      out[0] = d0 + fcb[0];
      out[1] = d1 + fcb[1];
    } else {
      float l0 = d0 + pcb[0], l1 = d1 + pcb[1];
      int r = warp - 1;
      out[2 + 2*r]     = l0;
      out[2 + 2*r + 1] = l1;
      float m = fmaxf(l0,l1);
      float e0 = expf(l0-m), e1 = expf(l1-m);
      float inv = 1.f/(e0+e1);
      out[2 + 2*N0 + 2*r]     = e0*inv;
      out[2 + 2*N0 + 2*r + 1] = e1*inv;
    }
  }
}

// ---------------- host side --------------------------------------------------
static void run_attn_block(const float* ln_w, const float* ln_b, const float* qkv_w,
    const float* out_w, const float* out_b, const float* res_w,
    float* h, float* S){
  float* XP  = S + O_XP;
  float* QKV = S + O_QKV;
  float* AO  = S + O_AO;
  float* QL  = S + O_QL;
  float* KL  = S + O_KL;
  float* X   = S + O_X;
  float* Z0  = S + O_Z0;
  float* Z1  = S + O_Z1;
  float* TA  = S + O_TA;
  float* TU  = S + O_TU;
  float* TT  = S + O_TT;
  float* T3  = S + O_T3;
  float* Wb  = S + O_W;
  float* RED = S + O_RED;

  k_lnpad<<<NPAD, 256>>>(h, XP, ln_w, ln_b, PADR);
  k_sgemm<<<dim3(1536/64, NPAD/128), 256>>>(XP, qkv_w, nullptr, nullptr, QKV, NPAD, 1536, DIM);
  k_land<<<dim3(MLM, HEADS), 64>>>(QKV, QL, KL);
  k_attn2<<<dim3(MLM, HEADS), 256>>>(QL, KL, X);
  k_zero2<<<1, 32>>>(RED);
  k_absmax<<<dim3(MLM, HEADS), 256>>>(X, RED, 0);
  k_absmax<<<dim3(MLM, HEADS), 256>>>(X, RED, 1);
  k_zinit<<<(HEADS*MLM*MLM + 255)/256, 256>>>(X, Z0, RED);

  const long long sM = (long long)MLM*MLM;
  float* zc = Z0; float* zn = Z1;
  for (int it=0; it<6; it++){
    k_bgemm<<<dim3(4,4,HEADS), 256>>>(X,  zc, TA, MLM, sM, sM, sM, 0.f,  1.f, 1.f);
    k_bgemm<<<dim3(4,4,HEADS), 256>>>(TA, TA, TU, MLM, sM, sM, sM, 7.f, -1.f, 1.f);
    k_bgemm<<<dim3(4,4,HEADS), 256>>>(TA, TU, TT, MLM, sM, sM, sM, 15.f,-1.f, 1.f);
    k_bgemm<<<dim3(4,4,HEADS), 256>>>(zc, TT, zn, MLM, sM, sM, sM, 13.f,-1.f, 0.25f);
    float* tmp = zc; zc = zn; zn = tmp;
  }

  k_attn3v<<<dim3(MLM/4, HEADS), 256, 4*NPAD*sizeof(float)>>>(QKV, QL, T3);
  const long long sS = (long long)MLM*DH;
  k_bgemm<<<dim3(1,4,HEADS), 256>>>(zc, T3, Wb, DH, sM, sS, sS, 0.f, 1.f, 1.f);
  k_attn1W<<<dim3(NPAD/8, HEADS), 256>>>(QKV, KL, Wb, AO);
  k_convres<<<(NPAD*DIM + 255)/256, 256>>>(QKV, res_w, AO);
  // out proj + residual into h (rows PADR.. of AO map to h rows 0..)
  k_sgemm<<<dim3(DIM/64, (NTOK+127)/128), 256>>>(AO + (size_t)PADR*DIM, out_w, out_b, h, h,
                                                  NTOK, DIM, DIM);
}

extern "C" void kernel_launch(void* const* d_in, const int* in_sizes, int n_in,
                              void* d_out, int out_size){
  const float* x      = (const float*)d_in[0];
  const float* cls    = (const float*)d_in[1];
  const float* ln1_w  = (const float*)d_in[2];
  const float* ln1_b  = (const float*)d_in[3];
  const float* qkv1_w = (const float*)d_in[4];
  const float* out1_w = (const float*)d_in[5];
  const float* out1_b = (const float*)d_in[6];
  const float* res1_w = (const float*)d_in[7];
  const float* p7_w   = (const float*)d_in[8];
  const float* p7_b   = (const float*)d_in[9];
  const float* p5_w   = (const float*)d_in[10];
  const float* p5_b   = (const float*)d_in[11];
  const float* p3_w   = (const float*)d_in[12];
  const float* p3_b   = (const float*)d_in[13];
  const float* ln2_w  = (const float*)d_in[14];
  const float* ln2_b  = (const float*)d_in[15];
  const float* qkv2_w = (const float*)d_in[16];
  const float* out2_w = (const float*)d_in[17];
  const float* out2_b = (const float*)d_in[18];
  const float* res2_w = (const float*)d_in[19];
  const float* norm_w = (const float*)d_in[20];
  const float* norm_b = (const float*)d_in[21];
  const float* fc2_w  = (const float*)d_in[22];
  const float* fc2_b  = (const float*)d_in[23];
  const float* pc_w   = (const float*)d_in[24];
  const float* pc_b   = (const float*)d_in[25];

  float* S = nullptr;
  cudaGetSymbolAddress((void**)&S, g_scratch);
  cudaFuncSetAttribute(k_attn3v, cudaFuncAttributeMaxDynamicSharedMemorySize,
                       4*NPAD*sizeof(float));

  float* H0 = S + O_H0;
  float* H1 = S + O_H1;
  float* XP = S + O_XP;

  k_build<<<(NTOK*DIM + 255)/256, 256>>>(x, cls, H0);

  run_attn_block(ln1_w, ln1_b, qkv1_w, out1_w, out1_b, res1_w, H0, S);

  k_cls<<<2, 256>>>(H0, H1);
  k_ppeg<<<dim3(N0, DIM/128), 128>>>(H0, p7_w, p7_b, p5_w, p5_b, p3_w, p3_b, H1);

  run_attn_block(ln2_w, ln2_b, qkv2_w, out2_w, out2_b, res2_w, H1, S);

  k_lnpad<<<NTOK, 256>>>(H1, XP, norm_w, norm_b, 0);
  k_heads<<<(NTOK + 7)/8, 256>>>(XP, fc2_w, fc2_b, pc_w, pc_b, (float*)d_out);
}

// round 2
// speedup vs baseline: 1.1128x; 1.1128x over previous
#include <cuda_runtime.h>
#include <math.h>

#define N0    10000
#define NTOK  10001
#define DIM   512
#define NPAD  10240
#define PADR  239
#define HEADS 8
#define DH    64
#define MLM   256
#define HH    100

// ---------------- scratch (single device global, no allocations) -------------
constexpr size_t O_H0 = 0;                                  // NTOK*DIM
constexpr size_t O_H1 = O_H0 + (size_t)NTOK*DIM;
constexpr size_t O_XP = O_H1 + (size_t)NTOK*DIM;            // NPAD*DIM (LN+pad; final hn)
constexpr size_t O_QKV= O_XP + (size_t)NPAD*DIM;            // NPAD*1536
constexpr size_t O_AO = O_QKV+ (size_t)NPAD*3*DIM;          // NPAD*DIM
constexpr size_t O_QL = O_AO + (size_t)NPAD*DIM;
constexpr size_t O_KL = O_QL + (size_t)HEADS*MLM*DH;
constexpr size_t O_X  = O_KL + (size_t)HEADS*MLM*DH;        // attn2
constexpr size_t O_Z0 = O_X  + (size_t)HEADS*MLM*MLM;
constexpr size_t O_Z1 = O_Z0 + (size_t)HEADS*MLM*MLM;
constexpr size_t O_TA = O_Z1 + (size_t)HEADS*MLM*MLM;
constexpr size_t O_TU = O_TA + (size_t)HEADS*MLM*MLM;
constexpr size_t O_TT = O_TU + (size_t)HEADS*MLM*MLM;
constexpr size_t O_T3 = O_TT + (size_t)HEADS*MLM*MLM;       // attn3@v : H*256*64
constexpr size_t O_W  = O_T3 + (size_t)HEADS*MLM*DH;        // Z@(attn3@v)
constexpr size_t O_RED= O_W  + (size_t)HEADS*MLM*DH;
constexpr size_t SCRATCH_TOTAL = O_RED + 8;

__device__ float g_scratch[SCRATCH_TOTAL];

// ---------------- helpers ----------------------------------------------------
__device__ __forceinline__ unsigned f2tf(float x){
  unsigned u; asm("cvt.rna.tf32.f32 %0, %1;" : "=r"(u) : "f"(x)); return u;
}

#define MMA_TF32(d, a, b0v, b1v) \
  asm("mma.sync.aligned.m16n8k8.row.col.f32.tf32.tf32.f32 " \
      "{%0,%1,%2,%3}, {%4,%5,%6,%7}, {%8,%9}, {%0,%1,%2,%3};\n" \
      : "+f"(d[0]),"+f"(d[1]),"+f"(d[2]),"+f"(d[3]) \
      : "r"(a[0]),"r"(a[1]),"r"(a[2]),"r"(a[3]),"r"(b0v),"r"(b1v))

__device__ __forceinline__ float warpRedSum(float v){
  #pragma unroll
  for (int s=16;s;s>>=1) v += __shfl_xor_sync(0xffffffffu, v, s);
  return v;
}
__device__ __forceinline__ float warpRedMax(float v){
  #pragma unroll
  for (int s=16;s;s>>=1) v = fmaxf(v, __shfl_xor_sync(0xffffffffu, v, s));
  return v;
}
__device__ __forceinline__ float blockRedSum(float v, float* red){
  int lane=threadIdx.x&31, wid=threadIdx.x>>5;
  v = warpRedSum(v);
  if (lane==0) red[wid]=v;
  __syncthreads();
  if (wid==0){
    float t = (lane<8)? red[lane] : 0.f;
    t = warpRedSum(t);
    if (lane==0) red[0]=t;
  }
  __syncthreads();
  float r = red[0];
  __syncthreads();
  return r;
}
__device__ __forceinline__ float blockRedMax(float v, float* red){
  int lane=threadIdx.x&31, wid=threadIdx.x>>5;
  v = warpRedMax(v);
  if (lane==0) red[wid]=v;
  __syncthreads();
  if (wid==0){
    float t = (lane<8)? red[lane] : -1e30f;
    t = warpRedMax(t);
    if (lane==0) red[0]=t;
  }
  __syncthreads();
  float r = red[0];
  __syncthreads();
  return r;
}

// ---------------- build h0 ---------------------------------------------------
__global__ void k_build(const float* __restrict__ x, const float* __restrict__ cls,
                        float* __restrict__ h){
  int idx = blockIdx.x*blockDim.x + threadIdx.x;
  if (idx >= NTOK*DIM) return;
  int r = idx >> 9, c = idx & 511;
  h[idx] = (r == 0) ? cls[c] : x[(size_t)(r-1)*DIM + c];
}

// ---------------- layernorm (+ optional front zero-pad) ----------------------
__global__ __launch_bounds__(256) void k_lnpad(const float* __restrict__ src,
    float* __restrict__ dst, const float* __restrict__ w, const float* __restrict__ b,
    int pad){
  __shared__ float red[32];
  int r = blockIdx.x, tid = threadIdx.x;
  if (r < pad){
    dst[(size_t)r*DIM + tid] = 0.f;
    dst[(size_t)r*DIM + tid + 256] = 0.f;
    return;
  }
  const float* row = src + (size_t)(r-pad)*DIM;
  float v0 = row[tid], v1 = row[tid+256];
  float mu = blockRedSum(v0+v1, red) * (1.f/DIM);
  float d0 = v0-mu, d1 = v1-mu;
  float var = blockRedSum(d0*d0 + d1*d1, red) * (1.f/DIM);
  float rs = 1.f / sqrtf(var + 1e-5f);
  dst[(size_t)r*DIM + tid]       = d0*rs*w[tid]     + b[tid];
  dst[(size_t)r*DIM + tid + 256] = d1*rs*w[tid+256] + b[tid+256];
}

// ---------------- TF32 tensor-core GEMM: C = A@B [+bias][+Cres] --------------
// 128x128 block tile, BK=16, 256 threads (8 warps 4x2), warp tile 32x64.
__global__ __launch_bounds__(256) void k_mma_gemm(
    const float* __restrict__ A, const float* __restrict__ B,
    const float* __restrict__ bias, const float* __restrict__ Cres,
    float* __restrict__ C, int M, int N, int K){
  __shared__ unsigned As[128][20];   // [m][k] + pad
  __shared__ unsigned Bs[16][132];   // [k][n] + pad
  const int bm = blockIdx.y * 128;
  const int bn = blockIdx.x * 128;
  const int tid = threadIdx.x;
  const int w = tid >> 5, lane = tid & 31;
  const int wm = (w & 3) * 32, wn = (w >> 2) * 64;
  const int g = lane >> 2, t = lane & 3;

  float acc[2][8][4];
  #pragma unroll
  for (int i=0;i<2;i++)
    #pragma unroll
    for (int j=0;j<8;j++)
      #pragma unroll
      for (int q=0;q<4;q++) acc[i][j][q]=0.f;

  float4 pa[2], pb[2];
  // prefetch first tile
  #pragma unroll
  for (int i=0;i<2;i++){
    int s = tid + i*256;
    int row = s>>2, kq = (s&3)*4;
    float4 v = make_float4(0,0,0,0);
    if (bm+row < M) v = *(const float4*)(A + (size_t)(bm+row)*K + kq);
    pa[i]=v;
    int rowb = s>>5, nq = (s&31)*4;
    float4 vb = make_float4(0,0,0,0);
    if (bn+nq < N) vb = *(const float4*)(B + (size_t)rowb*N + bn + nq);
    pb[i]=vb;
  }

  for (int k0 = 0; k0 < K; k0 += 16){
    // store prefetched tile
    #pragma unroll
    for (int i=0;i<2;i++){
      int s = tid + i*256;
      int row = s>>2, kq = (s&3)*4;
      uint4 u; u.x=f2tf(pa[i].x); u.y=f2tf(pa[i].y); u.z=f2tf(pa[i].z); u.w=f2tf(pa[i].w);
      *(uint4*)&As[row][kq] = u;
      int rowb = s>>5, nq = (s&31)*4;
      uint4 ub; ub.x=f2tf(pb[i].x); ub.y=f2tf(pb[i].y); ub.z=f2tf(pb[i].z); ub.w=f2tf(pb[i].w);
      *(uint4*)&Bs[rowb][nq] = ub;
    }
    __syncthreads();
    // prefetch next
    if (k0 + 16 < K){
      #pragma unroll
      for (int i=0;i<2;i++){
        int s = tid + i*256;
        int row = s>>2, kq = (s&3)*4;
        float4 v = make_float4(0,0,0,0);
        if (bm+row < M) v = *(const float4*)(A + (size_t)(bm+row)*K + k0+16 + kq);
        pa[i]=v;
        int rowb = s>>5, nq = (s&31)*4;
        float4 vb = make_float4(0,0,0,0);
        if (bn+nq < N) vb = *(const float4*)(B + (size_t)(k0+16+rowb)*N + bn + nq);
        pb[i]=vb;
      }
    }
    // compute
    #pragma unroll
    for (int kk=0; kk<16; kk+=8){
      unsigned af[2][4];
      #pragma unroll
      for (int mt=0; mt<2; mt++){
        int r = wm + mt*16 + g;
        af[mt][0]=As[r][kk+t];   af[mt][1]=As[r+8][kk+t];
        af[mt][2]=As[r][kk+t+4]; af[mt][3]=As[r+8][kk+t+4];
      }
      #pragma unroll
      for (int nt=0; nt<8; nt++){
        int c = wn + nt*8 + g;
        unsigned b0 = Bs[kk+t][c], b1 = Bs[kk+t+4][c];
        MMA_TF32(acc[0][nt], af[0], b0, b1);
        MMA_TF32(acc[1][nt], af[1], b0, b1);
      }
    }
    __syncthreads();
  }
  // epilogue
  #pragma unroll
  for (int mt=0; mt<2; mt++){
    #pragma unroll
    for (int nt=0; nt<8; nt++){
      int r0 = bm + wm + mt*16 + g;
      int c0 = bn + wn + nt*8 + t*2;
      #pragma unroll
      for (int q=0;q<4;q++){
        int row = r0 + (q>>1)*8;
        int col = c0 + (q&1);
        if (row < M && col < N){
          float v = acc[mt][nt][q];
          if (bias) v += bias[col];
          if (Cres) v += Cres[(size_t)row*N + col];
          C[(size_t)row*N + col] = v;
        }
      }
    }
  }
}

// -------- batched TF32 gemm: C[z] = scale * A[z] @ (bI*I + bS*B[z]) ----------
// M=K=256 fixed; N in {256,64}. Same 128x128 tiling.
__global__ __launch_bounds__(256) void k_mma_bgemm(
    const float* __restrict__ A, const float* __restrict__ B, float* __restrict__ C,
    int N, long long sA, long long sB, long long sC,
    float bI, float bS, float scale){
  __shared__ unsigned As[128][20];
  __shared__ unsigned Bs[16][132];
  const float* Ah = A + blockIdx.z * sA;
  const float* Bh = B + blockIdx.z * sB;
  float* Ch = C + blockIdx.z * sC;
  const int K = 256;
  const int bm = blockIdx.y * 128;
  const int bn = blockIdx.x * 128;
  const int tid = threadIdx.x;
  const int w = tid >> 5, lane = tid & 31;
  const int wm = (w & 3) * 32, wn = (w >> 2) * 64;
  const int g = lane >> 2, t = lane & 3;

  float acc[2][8][4];
  #pragma unroll
  for (int i=0;i<2;i++)
    #pragma unroll
    for (int j=0;j<8;j++)
      #pragma unroll
      for (int q=0;q<4;q++) acc[i][j][q]=0.f;

  float4 pa[2], pb[2];
  #pragma unroll
  for (int i=0;i<2;i++){
    int s = tid + i*256;
    int row = s>>2, kq = (s&3)*4;
    pa[i] = *(const float4*)(Ah + (size_t)(bm+row)*K + kq);
    int rowb = s>>5, nq = (s&31)*4;
    float4 vb = make_float4(0,0,0,0);
    if (bn+nq < N) vb = *(const float4*)(Bh + (size_t)rowb*N + bn + nq);
    pb[i]=vb;
  }

  for (int k0 = 0; k0 < K; k0 += 16){
    #pragma unroll
    for (int i=0;i<2;i++){
      int s = tid + i*256;
      int row = s>>2, kq = (s&3)*4;
      uint4 u; u.x=f2tf(pa[i].x); u.y=f2tf(pa[i].y); u.z=f2tf(pa[i].z); u.w=f2tf(pa[i].w);
      *(uint4*)&As[row][kq] = u;
      int rowb = s>>5, nq = (s&31)*4;
      int gk = k0 + rowb, gc = bn + nq;
      float bv[4] = {pb[i].x, pb[i].y, pb[i].z, pb[i].w};
      uint4 ub;
      unsigned uo[4];
      #pragma unroll
      for (int q=0;q<4;q++){
        float v = bS * bv[q];
        if (gk == gc + q) v += bI;
        uo[q] = f2tf(v);
      }
      ub.x=uo[0]; ub.y=uo[1]; ub.z=uo[2]; ub.w=uo[3];
      *(uint4*)&Bs[rowb][nq] = ub;
    }
    __syncthreads();
    if (k0 + 16 < K){
      #pragma unroll
      for (int i=0;i<2;i++){
        int s = tid + i*256;
        int row = s>>2, kq = (s&3)*4;
        pa[i] = *(const float4*)(Ah + (size_t)(bm+row)*K + k0+16 + kq);
        int rowb = s>>5, nq = (s&31)*4;
        float4 vb = make_float4(0,0,0,0);
        if (bn+nq < N) vb = *(const float4*)(Bh + (size_t)(k0+16+rowb)*N + bn + nq);
        pb[i]=vb;
      }
    }
    #pragma unroll
    for (int kk=0; kk<16; kk+=8){
      unsigned af[2][4];
      #pragma unroll
      for (int mt=0; mt<2; mt++){
        int r = wm + mt*16 + g;
        af[mt][0]=As[r][kk+t];   af[mt][1]=As[r+8][kk+t];
        af[mt][2]=As[r][kk+t+4]; af[mt][3]=As[r+8][kk+t+4];
      }
      #pragma unroll
      for (int nt=0; nt<8; nt++){
        int c = wn + nt*8 + g;
        unsigned b0 = Bs[kk+t][c], b1 = Bs[kk+t+4][c];
        MMA_TF32(acc[0][nt], af[0], b0, b1);
        MMA_TF32(acc[1][nt], af[1], b0, b1);
      }
    }
    __syncthreads();
  }
  #pragma unroll
  for (int mt=0; mt<2; mt++){
    #pragma unroll
    for (int nt=0; nt<8; nt++){
      int r0 = bm + wm + mt*16 + g;
      int c0 = bn + wn + nt*8 + t*2;
      #pragma unroll
      for (int q=0;q<4;q++){
        int row = r0 + (q>>1)*8;
        int col = c0 + (q&1);
        if (col < N)
          Ch[(size_t)row*N + col] = scale * acc[mt][nt][q];
      }
    }
  }
}

// ---------------- landmarks --------------------------------------------------
__global__ __launch_bounds__(64) void k_land(const float* __restrict__ qkv,
    float* __restrict__ ql, float* __restrict__ kl){
  int m = blockIdx.x, h = blockIdx.y, d = threadIdx.x;
  float sq = 0.f, sk = 0.f;
  #pragma unroll 8
  for (int j=0;j<40;j++){
    size_t base = (size_t)(m*40+j)*1536 + h*64 + d;
    sq += qkv[base];
    sk += qkv[base + 512];
  }
  ql[(size_t)(h*MLM+m)*64 + d] = sq * (0.125f/40.f);  // DH^-0.5 folded in
  kl[(size_t)(h*MLM+m)*64 + d] = sk * (1.f/40.f);
}

// ---------------- attn2 = softmax(ql @ kl^T) ---------------------------------
__global__ __launch_bounds__(256) void k_attn2(const float* __restrict__ ql,
    const float* __restrict__ kl, float* __restrict__ X){
  __shared__ float4 q4[16];
  __shared__ float red[32];
  int i = blockIdx.x, h = blockIdx.y, j = threadIdx.x;
  if (j < 16) q4[j] = ((const float4*)(ql + (size_t)(h*MLM+i)*64))[j];
  __syncthreads();
  const float4* kp = (const float4*)(kl + (size_t)(h*MLM+j)*64);
  float s = 0.f;
  #pragma unroll
  for (int t=0;t<16;t++){
    float4 kv = kp[t], q = q4[t];
    s += q.x*kv.x + q.y*kv.y + q.z*kv.z + q.w*kv.w;
  }
  float mx = blockRedMax(s, red);
  float e = expf(s - mx);
  float sm = blockRedSum(e, red);
  X[(size_t)(h*MLM+i)*MLM + j] = e / sm;
}

// ---------------- pinv init: abs row/col max ---------------------------------
__global__ void k_zero2(float* red){ if (threadIdx.x < 2) red[threadIdx.x] = 0.f; }

__global__ __launch_bounds__(256) void k_absmax(const float* __restrict__ X,
    float* __restrict__ red_out, int mode){
  __shared__ float red[32];
  int a = blockIdx.x, h = blockIdx.y, t = threadIdx.x;
  float v;
  if (mode == 0) v = fabsf(X[(size_t)(h*MLM+a)*MLM + t]);   // row sums
  else           v = fabsf(X[(size_t)(h*MLM+t)*MLM + a]);   // col sums
  float s = blockRedSum(v, red);
  if (t == 0) atomicMax((int*)(red_out + mode), __float_as_int(s));
}

__global__ void k_zinit(const float* __restrict__ X, float* __restrict__ Z,
                        const float* __restrict__ red){
  int idx = blockIdx.x*blockDim.x + threadIdx.x;
  if (idx >= HEADS*MLM*MLM) return;
  int h = idx >> 16, r = (idx >> 8) & 255, c = idx & 255;
  float inv = 1.f / (red[0] * red[1]);
  Z[idx] = X[(size_t)h*MLM*MLM + (size_t)c*MLM + r] * inv;
}

// ---------------- t3v = softmax(ql @ k^T) @ v  (4 landmark rows / block) -----
__global__ __launch_bounds__(256) void k_attn3v(const float* __restrict__ qkv,
    const float* __restrict__ ql, float* __restrict__ t3v){
  extern __shared__ float sc[];          // 4 * NPAD floats
  __shared__ float4 qs[4][16];
  __shared__ float red[32];
  __shared__ float4 red4[256];
  __shared__ float rowmax[4], rowsum[4];
  int h = blockIdx.y;
  int m0 = blockIdx.x * 4;
  int tid = threadIdx.x;
  if (tid < 64){
    int r = tid >> 4, t = tid & 15;
    qs[r][t] = ((const float4*)(ql + (size_t)(h*MLM+m0+r)*64))[t];
  }
  __syncthreads();
  float lmax0=-1e30f, lmax1=-1e30f, lmax2=-1e30f, lmax3=-1e30f;
  for (int n = tid; n < NPAD; n += 256){
    const float4* kp = (const float4*)(qkv + (size_t)n*1536 + 512 + h*64);
    float s0=0,s1=0,s2=0,s3=0;
    #pragma unroll
    for (int t=0;t<16;t++){
      float4 kv = kp[t];
      float4 a0=qs[0][t]; s0 += a0.x*kv.x+a0.y*kv.y+a0.z*kv.z+a0.w*kv.w;
      float4 a1=qs[1][t]; s1 += a1.x*kv.x+a1.y*kv.y+a1.z*kv.z+a1.w*kv.w;
      float4 a2=qs[2][t]; s2 += a2.x*kv.x+a2.y*kv.y+a2.z*kv.z+a2.w*kv.w;
      float4 a3=qs[3][t]; s3 += a3.x*kv.x+a3.y*kv.y+a3.z*kv.z+a3.w*kv.w;
    }
    sc[0*NPAD+n]=s0; sc[1*NPAD+n]=s1; sc[2*NPAD+n]=s2; sc[3*NPAD+n]=s3;
    lmax0=fmaxf(lmax0,s0); lmax1=fmaxf(lmax1,s1); lmax2=fmaxf(lmax2,s2); lmax3=fmaxf(lmax3,s3);
  }
  {
    float m;
    m = blockRedMax(lmax0, red); if (tid==0) rowmax[0]=m;
    m = blockRedMax(lmax1, red); if (tid==0) rowmax[1]=m;
    m = blockRedMax(lmax2, red); if (tid==0) rowmax[2]=m;
    m = blockRedMax(lmax3, red); if (tid==0) rowmax[3]=m;
  }
  __syncthreads();
  float ls0=0,ls1=0,ls2=0,ls3=0;
  for (int n = tid; n < NPAD; n += 256){
    float e;
    e = expf(sc[0*NPAD+n]-rowmax[0]); sc[0*NPAD+n]=e; ls0+=e;
    e = expf(sc[1*NPAD+n]-rowmax[1]); sc[1*NPAD+n]=e; ls1+=e;
    e = expf(sc[2*NPAD+n]-rowmax[2]); sc[2*NPAD+n]=e; ls2+=e;
    e = expf(sc[3*NPAD+n]-rowmax[3]); sc[3*NPAD+n]=e; ls3+=e;
  }
  {
    float s;
    s = blockRedSum(ls0, red); if (tid==0) rowsum[0]=s;
    s = blockRedSum(ls1, red); if (tid==0) rowsum[1]=s;
    s = blockRedSum(ls2, red); if (tid==0) rowsum[2]=s;
    s = blockRedSum(ls3, red); if (tid==0) rowsum[3]=s;
  }
  __syncthreads();
  // phase 2: weighted v sum
  int part = tid >> 4;      // 16 parts
  int d4 = tid & 15;        // 16 float4 lanes over 64 dims
  float4 acc0=make_float4(0,0,0,0), acc1=acc0, acc2=acc0, acc3=acc0;
  for (int n = part; n < NPAD; n += 16){
    float4 vv = *(const float4*)(qkv + (size_t)n*1536 + 1024 + h*64 + d4*4);
    float p;
    p = sc[0*NPAD+n]; acc0.x+=p*vv.x; acc0.y+=p*vv.y; acc0.z+=p*vv.z; acc0.w+=p*vv.w;
    p = sc[1*NPAD+n]; acc1.x+=p*vv.x; acc1.y+=p*vv.y; acc1.z+=p*vv.z; acc1.w+=p*vv.w;
    p = sc[2*NPAD+n]; acc2.x+=p*vv.x; acc2.y+=p*vv.y; acc2.z+=p*vv.z; acc2.w+=p*vv.w;
    p = sc[3*NPAD+n]; acc3.x+=p*vv.x; acc3.y+=p*vv.y; acc3.z+=p*vv.z; acc3.w+=p*vv.w;
  }
  #pragma unroll
  for (int r=0;r<4;r++){
    float4 a = (r==0)?acc0:(r==1)?acc1:(r==2)?acc2:acc3;
    red4[tid] = a;
    __syncthreads();
    if (part == 0){
      float4 s = red4[d4];
      #pragma unroll
      for (int pp=1;pp<16;pp++){
        float4 t = red4[pp*16+d4];
        s.x+=t.x; s.y+=t.y; s.z+=t.z; s.w+=t.w;
      }
      float inv = 1.f/rowsum[r];
      ((float4*)(t3v + (size_t)(h*MLM+m0+r)*64))[d4] =
          make_float4(s.x*inv, s.y*inv, s.z*inv, s.w*inv);
    }
    __syncthreads();
  }
}

// ---------------- out = softmax(q @ kl^T) @ W (8 tokens / block) -------------
__global__ __launch_bounds__(256) void k_attn1W(const float* __restrict__ qkv,
    const float* __restrict__ kl, const float* __restrict__ W, float* __restrict__ ao){
  __shared__ float4 qs[8][16];
  __shared__ float p[8][256];
  __shared__ float red[32];
  int h = blockIdx.y;
  int t0 = blockIdx.x * 8;
  int tid = threadIdx.x;
  for (int idx = tid; idx < 8*16; idx += 256){
    int r = idx >> 4, t = idx & 15;
    float4 v = ((const float4*)(qkv + (size_t)(t0+r)*1536 + h*64))[t];
    v.x*=0.125f; v.y*=0.125f; v.z*=0.125f; v.w*=0.125f;
    qs[r][t]=v;
  }
  __syncthreads();
  {
    int m = tid;
    const float4* kp = (const float4*)(kl + (size_t)(h*MLM+m)*64);
    float a[8];
    #pragma unroll
    for (int r=0;r<8;r++) a[r]=0.f;
    #pragma unroll
    for (int t=0;t<16;t++){
      float4 kv = kp[t];
      #pragma unroll
      for (int r=0;r<8;r++){
        float4 q = qs[r][t];
        a[r] += q.x*kv.x + q.y*kv.y + q.z*kv.z + q.w*kv.w;
      }
    }
    #pragma unroll
    for (int r=0;r<8;r++) p[r][m] = a[r];
  }
  __syncthreads();
  #pragma unroll
  for (int r=0;r<8;r++){
    float s = p[r][tid];
    float mx = blockRedMax(s, red);
    float e = expf(s - mx);
    float sm = blockRedSum(e, red);
    p[r][tid] = e / sm;
  }
  __syncthreads();
  int g = tid >> 6, d = tid & 63;
  float o0=0.f, o1=0.f;
  for (int m=0;m<256;m++){
    float w = W[(size_t)(h*MLM+m)*64 + d];
    o0 += p[g][m]*w;
    o1 += p[g+4][m]*w;
  }
  ao[(size_t)(t0+g)*DIM   + h*64 + d] = o0;
  ao[(size_t)(t0+g+4)*DIM + h*64 + d] = o1;
}

// ---------------- residual depthwise conv (kernel 33 along sequence) ---------
__global__ void k_convres(const float* __restrict__ qkv, const float* __restrict__ rw,
                          float* __restrict__ ao){
  int idx = blockIdx.x*blockDim.x + threadIdx.x;
  if (idx >= NPAD*DIM) return;
  int n = idx >> 9, c = idx & 511;
  int h = c >> 6;
  float acc = ao[idx];
  #pragma unroll
  for (int t=0;t<33;t++){
    int s = n + t - 16;
    if (s >= 0 && s < NPAD)
      acc += rw[h*33+t] * qkv[(size_t)s*1536 + 1024 + c];
  }
  ao[idx] = acc;
}

// ---------------- PPEG -------------------------------------------------------
__global__ void k_cls(const float* __restrict__ hin, float* __restrict__ hout){
  int c = blockIdx.x*blockDim.x + threadIdx.x;
  if (c < DIM) hout[c] = hin[c];
}

__global__ __launch_bounds__(128) void k_ppeg(const float* __restrict__ hin,
    const float* __restrict__ w7, const float* __restrict__ b7,
    const float* __restrict__ w5, const float* __restrict__ b5,
    const float* __restrict__ w3, const float* __restrict__ b3,
    float* __restrict__ hout){
  int pos = blockIdx.x;                 // 0..9999
  int c = blockIdx.y*128 + threadIdx.x;
  int i = pos / HH, j = pos % HH;
  float acc = hin[(size_t)(1+pos)*DIM + c] + b7[c] + b5[c] + b3[c];
  #pragma unroll
  for (int a=0;a<7;a++){
    int ii = i + a - 3;
    if (ii < 0 || ii >= HH) continue;
    #pragma unroll
    for (int bb=0;bb<7;bb++){
      int jj = j + bb - 3;
      if (jj < 0 || jj >= HH) continue;
      acc += hin[(size_t)(1+ii*HH+jj)*DIM + c] * w7[(size_t)c*49 + a*7 + bb];
    }
  }
  #pragma unroll
  for (int a=0;a<5;a++){
    int ii = i + a - 2;
    if (ii < 0 || ii >= HH) continue;
    #pragma unroll
    for (int bb=0;bb<5;bb++){
      int jj = j + bb - 2;
      if (jj < 0 || jj >= HH) continue;
      acc += hin[(size_t)(1+ii*HH+jj)*DIM + c] * w5[(size_t)c*25 + a*5 + bb];
    }
  }
  #pragma unroll
  for (int a=0;a<3;a++){
    int ii = i + a - 1;
    if (ii < 0 || ii >= HH) continue;
    #pragma unroll
    for (int bb=0;bb<3;bb++){
      int jj = j + bb - 1;
      if (jj < 0 || jj >= HH) continue;
      acc += hin[(size_t)(1+ii*HH+jj)*DIM + c] * w3[(size_t)c*9 + a*3 + bb];
    }
  }
  hout[(size_t)(1+pos)*DIM + c] = acc;
}

// ---------------- heads ------------------------------------------------------
__global__ void k_heads(const float* __restrict__ hn,
    const float* __restrict__ fcw, const float* __restrict__ fcb,
    const float* __restrict__ pcw, const float* __restrict__ pcb,
    float* __restrict__ out){
  int warp = (blockIdx.x*blockDim.x + threadIdx.x) >> 5;
  int lane = threadIdx.x & 31;
  if (warp >= NTOK) return;
  const float* hr = hn + (size_t)warp*DIM;
  const float* Wm = (warp == 0) ? fcw : pcw;
  float d0=0.f, d1=0.f;
  for (int k=lane;k<DIM;k+=32){
    float v = hr[k];
    d0 += v*Wm[2*k];
    d1 += v*Wm[2*k+1];
  }
  d0 = warpRedSum(d0);
  d1 = warpRedSum(d1);
  if (lane == 0){
    if (warp == 0){
      out[0] = d0 + fcb[0];
      out[1] = d1 + fcb[1];
    } else {
      float l0 = d0 + pcb[0], l1 = d1 + pcb[1];
      int r = warp - 1;
      out[2 + 2*r]     = l0;
      out[2 + 2*r + 1] = l1;
      float m = fmaxf(l0,l1);
      float e0 = expf(l0-m), e1 = expf(l1-m);
      float inv = 1.f/(e0+e1);
      out[2 + 2*N0 + 2*r]     = e0*inv;
      out[2 + 2*N0 + 2*r + 1] = e1*inv;
    }
  }
}

// ---------------- host side --------------------------------------------------
static void run_attn_block(const float* ln_w, const float* ln_b, const float* qkv_w,
    const float* out_w, const float* out_b, const float* res_w,
    float* h, float* S){
  float* XP  = S + O_XP;
  float* QKV = S + O_QKV;
  float* AO  = S + O_AO;
  float* QL  = S + O_QL;
  float* KL  = S + O_KL;
  float* X   = S + O_X;
  float* Z0  = S + O_Z0;
  float* Z1  = S + O_Z1;
  float* TA  = S + O_TA;
  float* TU  = S + O_TU;
  float* TT  = S + O_TT;
  float* T3  = S + O_T3;
  float* Wb  = S + O_W;
  float* RED = S + O_RED;

  k_lnpad<<<NPAD, 256>>>(h, XP, ln_w, ln_b, PADR);
  k_mma_gemm<<<dim3(1536/128, NPAD/128), 256>>>(XP, qkv_w, nullptr, nullptr, QKV,
                                                NPAD, 1536, DIM);
  k_land<<<dim3(MLM, HEADS), 64>>>(QKV, QL, KL);
  k_attn2<<<dim3(MLM, HEADS), 256>>>(QL, KL, X);
  k_zero2<<<1, 32>>>(RED);
  k_absmax<<<dim3(MLM, HEADS), 256>>>(X, RED, 0);
  k_absmax<<<dim3(MLM, HEADS), 256>>>(X, RED, 1);
  k_zinit<<<(HEADS*MLM*MLM + 255)/256, 256>>>(X, Z0, RED);

  const long long sM = (long long)MLM*MLM;
  float* zc = Z0; float* zn = Z1;
  for (int it=0; it<6; it++){
    k_mma_bgemm<<<dim3(2,2,HEADS), 256>>>(X,  zc, TA, MLM, sM, sM, sM, 0.f,  1.f, 1.f);
    k_mma_bgemm<<<dim3(2,2,HEADS), 256>>>(TA, TA, TU, MLM, sM, sM, sM, 7.f, -1.f, 1.f);
    k_mma_bgemm<<<dim3(2,2,HEADS), 256>>>(TA, TU, TT, MLM, sM, sM, sM, 15.f,-1.f, 1.f);
    k_mma_bgemm<<<dim3(2,2,HEADS), 256>>>(zc, TT, zn, MLM, sM, sM, sM, 13.f,-1.f, 0.25f);
    float* tmp = zc; zc = zn; zn = tmp;
  }

  k_attn3v<<<dim3(MLM/4, HEADS), 256, 4*NPAD*sizeof(float)>>>(QKV, QL, T3);
  const long long sS = (long long)MLM*DH;
  k_mma_bgemm<<<dim3(1,2,HEADS), 256>>>(zc, T3, Wb, DH, sM, sS, sS, 0.f, 1.f, 1.f);
  k_attn1W<<<dim3(NPAD/8, HEADS), 256>>>(QKV, KL, Wb, AO);
  k_convres<<<(NPAD*DIM + 255)/256, 256>>>(QKV, res_w, AO);
  // out proj + residual into h (rows PADR.. of AO map to h rows 0..)
  k_mma_gemm<<<dim3(DIM/128, (NTOK+127)/128), 256>>>(AO + (size_t)PADR*DIM, out_w,
                                                     out_b, h, h, NTOK, DIM, DIM);
}

extern "C" void kernel_launch(void* const* d_in, const int* in_sizes, int n_in,
                              void* d_out, int out_size){
  const float* x      = (const float*)d_in[0];
  const float* cls    = (const float*)d_in[1];
  const float* ln1_w  = (const float*)d_in[2];
  const float* ln1_b  = (const float*)d_in[3];
  const float* qkv1_w = (const float*)d_in[4];
  const float* out1_w = (const float*)d_in[5];
  const float* out1_b = (const float*)d_in[6];
  const float* res1_w = (const float*)d_in[7];
  const float* p7_w   = (const float*)d_in[8];
  const float* p7_b   = (const float*)d_in[9];
  const float* p5_w   = (const float*)d_in[10];
  const float* p5_b   = (const float*)d_in[11];
  const float* p3_w   = (const float*)d_in[12];
  const float* p3_b   = (const float*)d_in[13];
  const float* ln2_w  = (const float*)d_in[14];
  const float* ln2_b  = (const float*)d_in[15];
  const float* qkv2_w = (const float*)d_in[16];
  const float* out2_w = (const float*)d_in[17];
  const float* out2_b = (const float*)d_in[18];
  const float* res2_w = (const float*)d_in[19];
  const float* norm_w = (const float*)d_in[20];
  const float* norm_b = (const float*)d_in[21];
  const float* fc2_w  = (const float*)d_in[22];
  const float* fc2_b  = (const float*)d_in[23];
  const float* pc_w   = (const float*)d_in[24];
  const float* pc_b   = (const float*)d_in[25];

  float* S = nullptr;
  cudaGetSymbolAddress((void**)&S, g_scratch);
  cudaFuncSetAttribute(k_attn3v, cudaFuncAttributeMaxDynamicSharedMemorySize,
                       4*NPAD*sizeof(float));

  float* H0 = S + O_H0;
  float* H1 = S + O_H1;
  float* XP = S + O_XP;

  k_build<<<(NTOK*DIM + 255)/256, 256>>>(x, cls, H0);

  run_attn_block(ln1_w, ln1_b, qkv1_w, out1_w, out1_b, res1_w, H0, S);

  k_cls<<<2, 256>>>(H0, H1);
  k_ppeg<<<dim3(N0, DIM/128), 128>>>(H0, p7_w, p7_b, p5_w, p5_b, p3_w, p3_b, H1);

  run_attn_block(ln2_w, ln2_b, qkv2_w, out2_w, out2_b, res2_w, H1, S);

  k_lnpad<<<NTOK, 256>>>(H1, XP, norm_w, norm_b, 0);
  k_heads<<<(NTOK + 7)/8, 256>>>(XP, fc2_w, fc2_b, pc_w, pc_b, (float*)d_out);
}

// round 7
// speedup vs baseline: 1.1818x; 1.0620x over previous
#include <cuda_runtime.h>
#include <math.h>

#define N0    10000
#define NTOK  10001
#define DIM   512
#define NPAD  10240
#define PADR  239
#define HEADS 8
#define DH    64
#define MLM   256
#define HH    100

// ---------------- scratch (single device global, no allocations) -------------
constexpr size_t O_H0 = 0;                                  // NTOK*DIM
constexpr size_t O_H1 = O_H0 + (size_t)NTOK*DIM;
constexpr size_t O_XP = O_H1 + (size_t)NTOK*DIM;            // NPAD*DIM (LN+pad; final hn)
constexpr size_t O_QKV= O_XP + (size_t)NPAD*DIM;            // NPAD*1536
constexpr size_t O_AO = O_QKV+ (size_t)NPAD*3*DIM;          // NPAD*DIM
constexpr size_t O_QL = O_AO + (size_t)NPAD*DIM;
constexpr size_t O_KL = O_QL + (size_t)HEADS*MLM*DH;
constexpr size_t O_X  = O_KL + (size_t)HEADS*MLM*DH;        // attn2
constexpr size_t O_Z0 = O_X  + (size_t)HEADS*MLM*MLM;
constexpr size_t O_Z1 = O_Z0 + (size_t)HEADS*MLM*MLM;
constexpr size_t O_TA = O_Z1 + (size_t)HEADS*MLM*MLM;
constexpr size_t O_TU = O_TA + (size_t)HEADS*MLM*MLM;
constexpr size_t O_TT = O_TU + (size_t)HEADS*MLM*MLM;
constexpr size_t O_T3 = O_TT + (size_t)HEADS*MLM*MLM;       // attn3@v : H*256*64
constexpr size_t O_W  = O_T3 + (size_t)HEADS*MLM*DH;        // Z@(attn3@v)
constexpr size_t O_RED= O_W  + (size_t)HEADS*MLM*DH;
constexpr size_t SCRATCH_TOTAL = O_RED + 8;

__device__ float g_scratch[SCRATCH_TOTAL];

// ---------------- helpers ----------------------------------------------------
__device__ __forceinline__ unsigned f2tf(float x){
  unsigned u; asm("cvt.rna.tf32.f32 %0, %1;" : "=r"(u) : "f"(x)); return u;
}

#define MMA_TF32(d, a, b0v, b1v) \
  asm("mma.sync.aligned.m16n8k8.row.col.f32.tf32.tf32.f32 " \
      "{%0,%1,%2,%3}, {%4,%5,%6,%7}, {%8,%9}, {%0,%1,%2,%3};\n" \
      : "+f"(d[0]),"+f"(d[1]),"+f"(d[2]),"+f"(d[3]) \
      : "r"(a[0]),"r"(a[1]),"r"(a[2]),"r"(a[3]),"r"(b0v),"r"(b1v))

__device__ __forceinline__ float warpRedSum(float v){
  #pragma unroll
  for (int s=16;s;s>>=1) v += __shfl_xor_sync(0xffffffffu, v, s);
  return v;
}
__device__ __forceinline__ float warpRedMax(float v){
  #pragma unroll
  for (int s=16;s;s>>=1) v = fmaxf(v, __shfl_xor_sync(0xffffffffu, v, s));
  return v;
}
__device__ __forceinline__ float blockRedSum(float v, float* red){
  int lane=threadIdx.x&31, wid=threadIdx.x>>5;
  v = warpRedSum(v);
  if (lane==0) red[wid]=v;
  __syncthreads();
  if (wid==0){
    float t = (lane<8)? red[lane] : 0.f;
    t = warpRedSum(t);
    if (lane==0) red[0]=t;
  }
  __syncthreads();
  float r = red[0];
  __syncthreads();
  return r;
}
__device__ __forceinline__ float blockRedMax(float v, float* red){
  int lane=threadIdx.x&31, wid=threadIdx.x>>5;
  v = warpRedMax(v);
  if (lane==0) red[wid]=v;
  __syncthreads();
  if (wid==0){
    float t = (lane<8)? red[lane] : -1e30f;
    t = warpRedMax(t);
    if (lane==0) red[0]=t;
  }
  __syncthreads();
  float r = red[0];
  __syncthreads();
  return r;
}

// ---------------- build h0 ---------------------------------------------------
__global__ void k_build(const float* __restrict__ x, const float* __restrict__ cls,
                        float* __restrict__ h){
  int idx = blockIdx.x*blockDim.x + threadIdx.x;
  if (idx >= NTOK*DIM) return;
  int r = idx >> 9, c = idx & 511;
  h[idx] = (r == 0) ? cls[c] : x[(size_t)(r-1)*DIM + c];
}

// ---------------- layernorm (+ optional front zero-pad) ----------------------
__global__ __launch_bounds__(256) void k_lnpad(const float* __restrict__ src,
    float* __restrict__ dst, const float* __restrict__ w, const float* __restrict__ b,
    int pad){
  __shared__ float red[32];
  int r = blockIdx.x, tid = threadIdx.x;
  if (r < pad){
    dst[(size_t)r*DIM + tid] = 0.f;
    dst[(size_t)r*DIM + tid + 256] = 0.f;
    return;
  }
  const float* row = src + (size_t)(r-pad)*DIM;
  float v0 = row[tid], v1 = row[tid+256];
  float mu = blockRedSum(v0+v1, red) * (1.f/DIM);
  float d0 = v0-mu, d1 = v1-mu;
  float var = blockRedSum(d0*d0 + d1*d1, red) * (1.f/DIM);
  float rs = 1.f / sqrtf(var + 1e-5f);
  dst[(size_t)r*DIM + tid]       = d0*rs*w[tid]     + b[tid];
  dst[(size_t)r*DIM + tid + 256] = d1*rs*w[tid+256] + b[tid+256];
}

// ---------------- TF32 tensor-core GEMM: C = A@B [+bias][+Cres] --------------
// 128x128 block tile, BK=16, 256 threads (8 warps 4x2), warp tile 32x64.
__global__ __launch_bounds__(256) void k_mma_gemm(
    const float* __restrict__ A, const float* __restrict__ B,
    const float* __restrict__ bias, const float* __restrict__ Cres,
    float* __restrict__ C, int M, int N, int K){
  __shared__ unsigned As[128][20];   // [m][k] + pad
  __shared__ unsigned Bs[16][132];   // [k][n] + pad
  const int bm = blockIdx.y * 128;
  const int bn = blockIdx.x * 128;
  const int tid = threadIdx.x;
  const int w = tid >> 5, lane = tid & 31;
  const int wm = (w & 3) * 32, wn = (w >> 2) * 64;
  const int g = lane >> 2, t = lane & 3;

  float acc[2][8][4];
  #pragma unroll
  for (int i=0;i<2;i++)
    #pragma unroll
    for (int j=0;j<8;j++)
      #pragma unroll
      for (int q=0;q<4;q++) acc[i][j][q]=0.f;

  float4 pa[2], pb[2];
  // prefetch first tile
  #pragma unroll
  for (int i=0;i<2;i++){
    int s = tid + i*256;
    int row = s>>2, kq = (s&3)*4;
    float4 v = make_float4(0.f,0.f,0.f,0.f);
    if (bm+row < M) v = *(const float4*)(A + (size_t)(bm+row)*K + kq);
    pa[i]=v;
    int rowb = s>>5, nq = (s&31)*4;
    float4 vb = make_float4(0.f,0.f,0.f,0.f);
    if (bn+nq < N) vb = *(const float4*)(B + (size_t)rowb*N + bn + nq);
    pb[i]=vb;
  }

  for (int k0 = 0; k0 < K; k0 += 16){
    // store prefetched tile
    #pragma unroll
    for (int i=0;i<2;i++){
      int s = tid + i*256;
      int row = s>>2, kq = (s&3)*4;
      uint4 u; u.x=f2tf(pa[i].x); u.y=f2tf(pa[i].y); u.z=f2tf(pa[i].z); u.w=f2tf(pa[i].w);
      *(uint4*)&As[row][kq] = u;
      int rowb = s>>5, nq = (s&31)*4;
      uint4 ub; ub.x=f2tf(pb[i].x); ub.y=f2tf(pb[i].y); ub.z=f2tf(pb[i].z); ub.w=f2tf(pb[i].w);
      *(uint4*)&Bs[rowb][nq] = ub;
    }
    __syncthreads();
    // prefetch next
    if (k0 + 16 < K){
      #pragma unroll
      for (int i=0;i<2;i++){
        int s = tid + i*256;
        int row = s>>2, kq = (s&3)*4;
        float4 v = make_float4(0.f,0.f,0.f,0.f);
        if (bm+row < M) v = *(const float4*)(A + (size_t)(bm+row)*K + k0+16 + kq);
        pa[i]=v;
        int rowb = s>>5, nq = (s&31)*4;
        float4 vb = make_float4(0.f,0.f,0.f,0.f);
        if (bn+nq < N) vb = *(const float4*)(B + (size_t)(k0+16+rowb)*N + bn + nq);
        pb[i]=vb;
      }
    }
    // compute
    #pragma unroll
    for (int kk=0; kk<16; kk+=8){
      unsigned af[2][4];
      #pragma unroll
      for (int mt=0; mt<2; mt++){
        int r = wm + mt*16 + g;
        af[mt][0]=As[r][kk+t];   af[mt][1]=As[r+8][kk+t];
        af[mt][2]=As[r][kk+t+4]; af[mt][3]=As[r+8][kk+t+4];
      }
      #pragma unroll
      for (int nt=0; nt<8; nt++){
        int c = wn + nt*8 + g;
        unsigned b0 = Bs[kk+t][c], b1 = Bs[kk+t+4][c];
        MMA_TF32(acc[0][nt], af[0], b0, b1);
        MMA_TF32(acc[1][nt], af[1], b0, b1);
      }
    }
    __syncthreads();
  }
  // epilogue
  #pragma unroll
  for (int mt=0; mt<2; mt++){
    #pragma unroll
    for (int nt=0; nt<8; nt++){
      int r0 = bm + wm + mt*16 + g;
      int c0 = bn + wn + nt*8 + t*2;
      #pragma unroll
      for (int q=0;q<4;q++){
        int row = r0 + (q>>1)*8;
        int col = c0 + (q&1);
        if (row < M && col < N){
          float v = acc[mt][nt][q];
          if (bias) v += bias[col];
          if (Cres) v += Cres[(size_t)row*N + col];
          C[(size_t)row*N + col] = v;
        }
      }
    }
  }
}

// ----- batched TF32 gemm, 64x64 tile: C[z] = scale*A[z]@(bI*I + bS*B[z]) -----
// M=K=256 fixed; N in {256,64}. grid (N/64, 4, nbatch), 256 threads.
// BK=16, same per-thread K-summation order as the 128x128 version.
__global__ __launch_bounds__(256) void k_bgemm64(
    const float* __restrict__ A, const float* __restrict__ B, float* __restrict__ C,
    int N, long long sA, long long sB, long long sC,
    float bI, float bS, float scale){
  __shared__ unsigned As[64][20];    // [m][k] + pad
  __shared__ unsigned Bs[16][68];    // [k][n] + pad
  const float* Ah = A + blockIdx.z * sA;
  const float* Bh = B + blockIdx.z * sB;
  float* Ch = C + blockIdx.z * sC;
  const int K = 256;
  const int bm = blockIdx.y * 64;
  const int bn = blockIdx.x * 64;
  const int tid = threadIdx.x;
  const int w = tid >> 5, lane = tid & 31;
  const int wm = (w & 3) * 16, wn = (w >> 2) * 32;
  const int g = lane >> 2, t = lane & 3;

  float acc[4][4];
  #pragma unroll
  for (int j=0;j<4;j++)
    #pragma unroll
    for (int q=0;q<4;q++) acc[j][q]=0.f;

  for (int k0 = 0; k0 < K; k0 += 16){
    // A tile: 64 rows x 16 k = 256 float4 slots (one per thread)
    {
      int row = tid >> 2, kq = (tid & 3) * 4;
      float4 v = *(const float4*)(Ah + (size_t)(bm+row)*K + k0 + kq);
      As[row][kq+0]=f2tf(v.x); As[row][kq+1]=f2tf(v.y);
      As[row][kq+2]=f2tf(v.z); As[row][kq+3]=f2tf(v.w);
    }
    // B tile: 16 k-rows x 64 cols = 256 float4 slots (one per thread)
    {
      int rowb = tid >> 4, cq = (tid & 15) * 4;
      float4 vb = *(const float4*)(Bh + (size_t)(k0+rowb)*N + bn + cq);
      int gk = k0 + rowb;
      float bv[4] = {vb.x, vb.y, vb.z, vb.w};
      #pragma unroll
      for (int q=0;q<4;q++){
        float vv = bS * bv[q];
        if (gk == bn + cq + q) vv += bI;
        Bs[rowb][cq+q] = f2tf(vv);
      }
    }
    __syncthreads();
    #pragma unroll
    for (int kk=0; kk<16; kk+=8){
      unsigned af[4];
      af[0]=As[wm+g][kk+t];   af[1]=As[wm+g+8][kk+t];
      af[2]=As[wm+g][kk+t+4]; af[3]=As[wm+g+8][kk+t+4];
      #pragma unroll
      for (int nt=0; nt<4; nt++){
        int c = wn + nt*8 + g;
        unsigned b0 = Bs[kk+t][c], b1 = Bs[kk+t+4][c];
        MMA_TF32(acc[nt], af, b0, b1);
      }
    }
    __syncthreads();
  }
  #pragma unroll
  for (int nt=0; nt<4; nt++){
    #pragma unroll
    for (int q=0;q<4;q++){
      int row = bm + wm + g + (q>>1)*8;
      int col = bn + wn + nt*8 + t*2 + (q&1);
      Ch[(size_t)row*N + col] = scale * acc[nt][q];
    }
  }
}

// ---------------- landmarks --------------------------------------------------
__global__ __launch_bounds__(64) void k_land(const float* __restrict__ qkv,
    float* __restrict__ ql, float* __restrict__ kl){
  int m = blockIdx.x, h = blockIdx.y, d = threadIdx.x;
  float sq = 0.f, sk = 0.f;
  #pragma unroll 8
  for (int j=0;j<40;j++){
    size_t base = (size_t)(m*40+j)*1536 + h*64 + d;
    sq += qkv[base];
    sk += qkv[base + 512];
  }
  ql[(size_t)(h*MLM+m)*64 + d] = sq * (0.125f/40.f);  // DH^-0.5 folded in
  kl[(size_t)(h*MLM+m)*64 + d] = sk * (1.f/40.f);
}

// ---------------- attn2 = softmax(ql @ kl^T) ---------------------------------
__global__ __launch_bounds__(256) void k_attn2(const float* __restrict__ ql,
    const float* __restrict__ kl, float* __restrict__ X){
  __shared__ float4 q4[16];
  __shared__ float red[32];
  int i = blockIdx.x, h = blockIdx.y, j = threadIdx.x;
  if (j < 16) q4[j] = ((const float4*)(ql + (size_t)(h*MLM+i)*64))[j];
  __syncthreads();
  const float4* kp = (const float4*)(kl + (size_t)(h*MLM+j)*64);
  float s = 0.f;
  #pragma unroll
  for (int t=0;t<16;t++){
    float4 kv = kp[t], q = q4[t];
    s += q.x*kv.x + q.y*kv.y + q.z*kv.z + q.w*kv.w;
  }
  float mx = blockRedMax(s, red);
  float e = expf(s - mx);
  float sm = blockRedSum(e, red);
  X[(size_t)(h*MLM+i)*MLM + j] = e / sm;
}

// ---------------- pinv init: abs row/col max ---------------------------------
__global__ void k_zero2(float* red){ if (threadIdx.x < 2) red[threadIdx.x] = 0.f; }

__global__ __launch_bounds__(256) void k_absmax(const float* __restrict__ X,
    float* __restrict__ red_out, int mode){
  __shared__ float red[32];
  int a = blockIdx.x, h = blockIdx.y, t = threadIdx.x;
  float v;
  if (mode == 0) v = fabsf(X[(size_t)(h*MLM+a)*MLM + t]);   // row sums
  else           v = fabsf(X[(size_t)(h*MLM+t)*MLM + a]);   // col sums
  float s = blockRedSum(v, red);
  if (t == 0) atomicMax((int*)(red_out + mode), __float_as_int(s));
}

__global__ void k_zinit(const float* __restrict__ X, float* __restrict__ Z,
                        const float* __restrict__ red){
  int idx = blockIdx.x*blockDim.x + threadIdx.x;
  if (idx >= HEADS*MLM*MLM) return;
  int h = idx >> 16, r = (idx >> 8) & 255, c = idx & 255;
  float inv = 1.f / (red[0] * red[1]);
  Z[idx] = X[(size_t)h*MLM*MLM + (size_t)c*MLM + r] * inv;
}

// ---------------- t3v = softmax(ql @ k^T) @ v  (4 landmark rows / block) -----
__global__ __launch_bounds__(256) void k_attn3v(const float* __restrict__ qkv,
    const float* __restrict__ ql, float* __restrict__ t3v){
  extern __shared__ float sc[];          // 4 * NPAD floats
  __shared__ float4 qs[4][16];
  __shared__ float red[32];
  __shared__ float4 red4[256];
  __shared__ float rowmax[4], rowsum[4];
  int h = blockIdx.y;
  int m0 = blockIdx.x * 4;
  int tid = threadIdx.x;
  if (tid < 64){
    int r = tid >> 4, t = tid & 15;
    qs[r][t] = ((const float4*)(ql + (size_t)(h*MLM+m0+r)*64))[t];
  }
  __syncthreads();
  float lmax0=-1e30f, lmax1=-1e30f, lmax2=-1e30f, lmax3=-1e30f;
  for (int n = tid; n < NPAD; n += 256){
    const float4* kp = (const float4*)(qkv + (size_t)n*1536 + 512 + h*64);
    float s0=0,s1=0,s2=0,s3=0;
    #pragma unroll
    for (int t=0;t<16;t++){
      float4 kv = kp[t];
      float4 a0=qs[0][t]; s0 += a0.x*kv.x+a0.y*kv.y+a0.z*kv.z+a0.w*kv.w;
      float4 a1=qs[1][t]; s1 += a1.x*kv.x+a1.y*kv.y+a1.z*kv.z+a1.w*kv.w;
      float4 a2=qs[2][t]; s2 += a2.x*kv.x+a2.y*kv.y+a2.z*kv.z+a2.w*kv.w;
      float4 a3=qs[3][t]; s3 += a3.x*kv.x+a3.y*kv.y+a3.z*kv.z+a3.w*kv.w;
    }
    sc[0*NPAD+n]=s0; sc[1*NPAD+n]=s1; sc[2*NPAD+n]=s2; sc[3*NPAD+n]=s3;
    lmax0=fmaxf(lmax0,s0); lmax1=fmaxf(lmax1,s1); lmax2=fmaxf(lmax2,s2); lmax3=fmaxf(lmax3,s3);
  }
  {
    float m;
    m = blockRedMax(lmax0, red); if (tid==0) rowmax[0]=m;
    m = blockRedMax(lmax1, red); if (tid==0) rowmax[1]=m;
    m = blockRedMax(lmax2, red); if (tid==0) rowmax[2]=m;
    m = blockRedMax(lmax3, red); if (tid==0) rowmax[3]=m;
  }
  __syncthreads();
  float ls0=0,ls1=0,ls2=0,ls3=0;
  for (int n = tid; n < NPAD; n += 256){
    float e;
    e = expf(sc[0*NPAD+n]-rowmax[0]); sc[0*NPAD+n]=e; ls0+=e;
    e = expf(sc[1*NPAD+n]-rowmax[1]); sc[1*NPAD+n]=e; ls1+=e;
    e = expf(sc[2*NPAD+n]-rowmax[2]); sc[2*NPAD+n]=e; ls2+=e;
    e = expf(sc[3*NPAD+n]-rowmax[3]); sc[3*NPAD+n]=e; ls3+=e;
  }
  {
    float s;
    s = blockRedSum(ls0, red); if (tid==0) rowsum[0]=s;
    s = blockRedSum(ls1, red); if (tid==0) rowsum[1]=s;
    s = blockRedSum(ls2, red); if (tid==0) rowsum[2]=s;
    s = blockRedSum(ls3, red); if (tid==0) rowsum[3]=s;
  }
  __syncthreads();
  // phase 2: weighted v sum
  int part = tid >> 4;      // 16 parts
  int d4 = tid & 15;        // 16 float4 lanes over 64 dims
  float4 acc0=make_float4(0,0,0,0), acc1=acc0, acc2=acc0, acc3=acc0;
  for (int n = part; n < NPAD; n += 16){
    float4 vv = *(const float4*)(qkv + (size_t)n*1536 + 1024 + h*64 + d4*4);
    float p;
    p = sc[0*NPAD+n]; acc0.x+=p*vv.x; acc0.y+=p*vv.y; acc0.z+=p*vv.z; acc0.w+=p*vv.w;
    p = sc[1*NPAD+n]; acc1.x+=p*vv.x; acc1.y+=p*vv.y; acc1.z+=p*vv.z; acc1.w+=p*vv.w;
    p = sc[2*NPAD+n]; acc2.x+=p*vv.x; acc2.y+=p*vv.y; acc2.z+=p*vv.z; acc2.w+=p*vv.w;
    p = sc[3*NPAD+n]; acc3.x+=p*vv.x; acc3.y+=p*vv.y; acc3.z+=p*vv.z; acc3.w+=p*vv.w;
  }
  #pragma unroll
  for (int r=0;r<4;r++){
    float4 a = (r==0)?acc0:(r==1)?acc1:(r==2)?acc2:acc3;
    red4[tid] = a;
    __syncthreads();
    if (part == 0){
      float4 s = red4[d4];
      #pragma unroll
      for (int pp=1;pp<16;pp++){
        float4 t = red4[pp*16+d4];
        s.x+=t.x; s.y+=t.y; s.z+=t.z; s.w+=t.w;
      }
      float inv = 1.f/rowsum[r];
      ((float4*)(t3v + (size_t)(h*MLM+m0+r)*64))[d4] =
          make_float4(s.x*inv, s.y*inv, s.z*inv, s.w*inv);
    }
    __syncthreads();
  }
}

// ---------------- out = softmax(q @ kl^T) @ W (8 tokens / block) -------------
__global__ __launch_bounds__(256) void k_attn1W(const float* __restrict__ qkv,
    const float* __restrict__ kl, const float* __restrict__ W, float* __restrict__ ao){
  __shared__ float4 qs[8][16];
  __shared__ float p[8][256];
  __shared__ float red[32];
  int h = blockIdx.y;
  int t0 = blockIdx.x * 8;
  int tid = threadIdx.x;
  for (int idx = tid; idx < 8*16; idx += 256){
    int r = idx >> 4, t = idx & 15;
    float4 v = ((const float4*)(qkv + (size_t)(t0+r)*1536 + h*64))[t];
    v.x*=0.125f; v.y*=0.125f; v.z*=0.125f; v.w*=0.125f;
    qs[r][t]=v;
  }
  __syncthreads();
  {
    int m = tid;
    const float4* kp = (const float4*)(kl + (size_t)(h*MLM+m)*64);
    float a[8];
    #pragma unroll
    for (int r=0;r<8;r++) a[r]=0.f;
    #pragma unroll
    for (int t=0;t<16;t++){
      float4 kv = kp[t];
      #pragma unroll
      for (int r=0;r<8;r++){
        float4 q = qs[r][t];
        a[r] += q.x*kv.x + q.y*kv.y + q.z*kv.z + q.w*kv.w;
      }
    }
    #pragma unroll
    for (int r=0;r<8;r++) p[r][m] = a[r];
  }
  __syncthreads();
  #pragma unroll
  for (int r=0;r<8;r++){
    float s = p[r][tid];
    float mx = blockRedMax(s, red);
    float e = expf(s - mx);
    float sm = blockRedSum(e, red);
    p[r][tid] = e / sm;
  }
  __syncthreads();
  int g = tid >> 6, d = tid & 63;
  float o0=0.f, o1=0.f;
  for (int m=0;m<256;m++){
    float w = W[(size_t)(h*MLM+m)*64 + d];
    o0 += p[g][m]*w;
    o1 += p[g+4][m]*w;
  }
  ao[(size_t)(t0+g)*DIM   + h*64 + d] = o0;
  ao[(size_t)(t0+g+4)*DIM + h*64 + d] = o1;
}

// ---------------- residual depthwise conv (kernel 33 along sequence) ---------
__global__ void k_convres(const float* __restrict__ qkv, const float* __restrict__ rw,
                          float* __restrict__ ao){
  int idx = blockIdx.x*blockDim.x + threadIdx.x;
  if (idx >= NPAD*DIM) return;
  int n = idx >> 9, c = idx & 511;
  int h = c >> 6;
  float acc = ao[idx];
  #pragma unroll
  for (int t=0;t<33;t++){
    int s = n + t - 16;
    if (s >= 0 && s < NPAD)
      acc += rw[h*33+t] * qkv[(size_t)s*1536 + 1024 + c];
  }
  ao[idx] = acc;
}

// ---------------- PPEG -------------------------------------------------------
__global__ void k_cls(const float* __restrict__ hin, float* __restrict__ hout){
  int c = blockIdx.x*blockDim.x + threadIdx.x;
  if (c < DIM) hout[c] = hin[c];
}

__global__ __launch_bounds__(128) void k_ppeg(const float* __restrict__ hin,
    const float* __restrict__ w7, const float* __restrict__ b7,
    const float* __restrict__ w5, const float* __restrict__ b5,
    const float* __restrict__ w3, const float* __restrict__ b3,
    float* __restrict__ hout){
  int pos = blockIdx.x;                 // 0..9999
  int c = blockIdx.y*128 + threadIdx.x;
  int i = pos / HH, j = pos % HH;
  float acc = hin[(size_t)(1+pos)*DIM + c] + b7[c] + b5[c] + b3[c];
  #pragma unroll
  for (int a=0;a<7;a++){
    int ii = i + a - 3;
    if (ii < 0 || ii >= HH) continue;
    #pragma unroll
    for (int bb=0;bb<7;bb++){
      int jj = j + bb - 3;
      if (jj < 0 || jj >= HH) continue;
      acc += hin[(size_t)(1+ii*HH+jj)*DIM + c] * w7[(size_t)c*49 + a*7 + bb];
    }
  }
  #pragma unroll
  for (int a=0;a<5;a++){
    int ii = i + a - 2;
    if (ii < 0 || ii >= HH) continue;
    #pragma unroll
    for (int bb=0;bb<5;bb++){
      int jj = j + bb - 2;
      if (jj < 0 || jj >= HH) continue;
      acc += hin[(size_t)(1+ii*HH+jj)*DIM + c] * w5[(size_t)c*25 + a*5 + bb];
    }
  }
  #pragma unroll
  for (int a=0;a<3;a++){
    int ii = i + a - 1;
    if (ii < 0 || ii >= HH) continue;
    #pragma unroll
    for (int bb=0;bb<3;bb++){
      int jj = j + bb - 1;
      if (jj < 0 || jj >= HH) continue;
      acc += hin[(size_t)(1+ii*HH+jj)*DIM + c] * w3[(size_t)c*9 + a*3 + bb];
    }
  }
  hout[(size_t)(1+pos)*DIM + c] = acc;
}

// ---------------- heads ------------------------------------------------------
__global__ void k_heads(const float* __restrict__ hn,
    const float* __restrict__ fcw, const float* __restrict__ fcb,
    const float* __restrict__ pcw, const float* __restrict__ pcb,
    float* __restrict__ out){
  int warp = (blockIdx.x*blockDim.x + threadIdx.x) >> 5;
  int lane = threadIdx.x & 31;
  if (warp >= NTOK) return;
  const float* hr = hn + (size_t)warp*DIM;
  const float* Wm = (warp == 0) ? fcw : pcw;
  float d0=0.f, d1=0.f;
  for (int k=lane;k<DIM;k+=32){
    float v = hr[k];
    d0 += v*Wm[2*k];
    d1 += v*Wm[2*k+1];
  }
  d0 = warpRedSum(d0);
  d1 = warpRedSum(d1);
  if (lane == 0){
    if (warp == 0){
      out[0] = d0 + fcb[0];
      out[1] = d1 + fcb[1];
    } else {
      float l0 = d0 + pcb[0], l1 = d1 + pcb[1];
      int r = warp - 1;
      out[2 + 2*r]     = l0;
      out[2 + 2*r + 1] = l1;
      float m = fmaxf(l0,l1);
      float e0 = expf(l0-m), e1 = expf(l1-m);
      float inv = 1.f/(e0+e1);
      out[2 + 2*N0 + 2*r]     = e0*inv;
      out[2 + 2*N0 + 2*r + 1] = e1*inv;
    }
  }
}

// ---------------- host side --------------------------------------------------
static void run_attn_block(const float* ln_w, const float* ln_b, const float* qkv_w,
    const float* out_w, const float* out_b, const float* res_w,
    float* h, float* S){
  float* XP  = S + O_XP;
  float* QKV = S + O_QKV;
  float* AO  = S + O_AO;
  float* QL  = S + O_QL;
  float* KL  = S + O_KL;
  float* X   = S + O_X;
  float* Z0  = S + O_Z0;
  float* Z1  = S + O_Z1;
  float* TA  = S + O_TA;
  float* TU  = S + O_TU;
  float* TT  = S + O_TT;
  float* T3  = S + O_T3;
  float* Wb  = S + O_W;
  float* RED = S + O_RED;

  k_lnpad<<<NPAD, 256>>>(h, XP, ln_w, ln_b, PADR);
  k_mma_gemm<<<dim3(1536/128, NPAD/128), 256>>>(XP, qkv_w, nullptr, nullptr, QKV,
                                                NPAD, 1536, DIM);
  k_land<<<dim3(MLM, HEADS), 64>>>(QKV, QL, KL);
  k_attn2<<<dim3(MLM, HEADS), 256>>>(QL, KL, X);
  k_zero2<<<1, 32>>>(RED);
  k_absmax<<<dim3(MLM, HEADS), 256>>>(X, RED, 0);
  k_absmax<<<dim3(MLM, HEADS), 256>>>(X, RED, 1);
  k_zinit<<<(HEADS*MLM*MLM + 255)/256, 256>>>(X, Z0, RED);

  const long long sM = (long long)MLM*MLM;
  float* zc = Z0; float* zn = Z1;
  for (int it=0; it<6; it++){
    k_bgemm64<<<dim3(4,4,HEADS), 256>>>(X,  zc, TA, MLM, sM, sM, sM, 0.f,  1.f, 1.f);
    k_bgemm64<<<dim3(4,4,HEADS), 256>>>(TA, TA, TU, MLM, sM, sM, sM, 7.f, -1.f, 1.f);
    k_bgemm64<<<dim3(4,4,HEADS), 256>>>(TA, TU, TT, MLM, sM, sM, sM, 15.f,-1.f, 1.f);
    k_bgemm64<<<dim3(4,4,HEADS), 256>>>(zc, TT, zn, MLM, sM, sM, sM, 13.f,-1.f, 0.25f);
    float* tmp = zc; zc = zn; zn = tmp;
  }

  k_attn3v<<<dim3(MLM/4, HEADS), 256, 4*NPAD*sizeof(float)>>>(QKV, QL, T3);
  const long long sS = (long long)MLM*DH;
  k_bgemm64<<<dim3(1,4,HEADS), 256>>>(zc, T3, Wb, DH, sM, sS, sS, 0.f, 1.f, 1.f);
  k_attn1W<<<dim3(NPAD/8, HEADS), 256>>>(QKV, KL, Wb, AO);
  k_convres<<<(NPAD*DIM + 255)/256, 256>>>(QKV, res_w, AO);
  // out proj + residual into h (rows PADR.. of AO map to h rows 0..)
  k_mma_gemm<<<dim3(DIM/128, (NTOK+127)/128), 256>>>(AO + (size_t)PADR*DIM, out_w,
                                                     out_b, h, h, NTOK, DIM, DIM);
}

extern "C" void kernel_launch(void* const* d_in, const int* in_sizes, int n_in,
                              void* d_out, int out_size){
  const float* x      = (const float*)d_in[0];
  const float* cls    = (const float*)d_in[1];
  const float* ln1_w  = (const float*)d_in[2];
  const float* ln1_b  = (const float*)d_in[3];
  const float* qkv1_w = (const float*)d_in[4];
  const float* out1_w = (const float*)d_in[5];
  const float* out1_b = (const float*)d_in[6];
  const float* res1_w = (const float*)d_in[7];
  const float* p7_w   = (const float*)d_in[8];
  const float* p7_b   = (const float*)d_in[9];
  const float* p5_w   = (const float*)d_in[10];
  const float* p5_b   = (const float*)d_in[11];
  const float* p3_w   = (const float*)d_in[12];
  const float* p3_b   = (const float*)d_in[13];
  const float* ln2_w  = (const float*)d_in[14];
  const float* ln2_b  = (const float*)d_in[15];
  const float* qkv2_w = (const float*)d_in[16];
  const float* out2_w = (const float*)d_in[17];
  const float* out2_b = (const float*)d_in[18];
  const float* res2_w = (const float*)d_in[19];
  const float* norm_w = (const float*)d_in[20];
  const float* norm_b = (const float*)d_in[21];
  const float* fc2_w  = (const float*)d_in[22];
  const float* fc2_b  = (const float*)d_in[23];
  const float* pc_w   = (const float*)d_in[24];
  const float* pc_b   = (const float*)d_in[25];

  float* S = nullptr;
  cudaGetSymbolAddress((void**)&S, g_scratch);
  cudaFuncSetAttribute(k_attn3v, cudaFuncAttributeMaxDynamicSharedMemorySize,
                       4*NPAD*sizeof(float));

  float* H0 = S + O_H0;
  float* H1 = S + O_H1;
  float* XP = S + O_XP;

  k_build<<<(NTOK*DIM + 255)/256, 256>>>(x, cls, H0);

  run_attn_block(ln1_w, ln1_b, qkv1_w, out1_w, out1_b, res1_w, H0, S);

  k_cls<<<2, 256>>>(H0, H1);
  k_ppeg<<<dim3(N0, DIM/128), 128>>>(H0, p7_w, p7_b, p5_w, p5_b, p3_w, p3_b, H1);

  run_attn_block(ln2_w, ln2_b, qkv2_w, out2_w, out2_b, res2_w, H1, S);

  k_lnpad<<<NTOK, 256>>>(H1, XP, norm_w, norm_b, 0);
  k_heads<<<(NTOK + 7)/8, 256>>>(XP, fc2_w, fc2_b, pc_w, pc_b, (float*)d_out);
}

// round 8
// speedup vs baseline: 1.6749x; 1.4172x over previous
#include <cuda_runtime.h>
#include <math.h>

#define N0    10000
#define NTOK  10001
#define DIM   512
#define NPAD  10240
#define PADR  239
#define HEADS 8
#define DH    64
#define MLM   256
#define HH    100

// ---------------- scratch (single device global, no allocations) -------------
constexpr size_t O_H0 = 0;                                  // NTOK*DIM
constexpr size_t O_H1 = O_H0 + (size_t)NTOK*DIM;
constexpr size_t O_XP = O_H1 + (size_t)NTOK*DIM;            // NPAD*DIM (LN+pad; final hn)
constexpr size_t O_QKV= O_XP + (size_t)NPAD*DIM;            // NPAD*1536
constexpr size_t O_AO = O_QKV+ (size_t)NPAD*3*DIM;          // NPAD*DIM
constexpr size_t O_QL = O_AO + (size_t)NPAD*DIM;
constexpr size_t O_KL = O_QL + (size_t)HEADS*MLM*DH;
constexpr size_t O_X  = O_KL + (size_t)HEADS*MLM*DH;        // attn2
constexpr size_t O_Z0 = O_X  + (size_t)HEADS*MLM*MLM;
constexpr size_t O_Z1 = O_Z0 + (size_t)HEADS*MLM*MLM;
constexpr size_t O_TA = O_Z1 + (size_t)HEADS*MLM*MLM;       // doubles as attn3v oacc
constexpr size_t O_TU = O_TA + (size_t)HEADS*MLM*MLM;       // doubles as attn3v rsum
constexpr size_t O_TT = O_TU + (size_t)HEADS*MLM*MLM;
constexpr size_t O_T3 = O_TT + (size_t)HEADS*MLM*MLM;       // attn3@v : H*256*64
constexpr size_t O_W  = O_T3 + (size_t)HEADS*MLM*DH;        // Z@(attn3@v)
constexpr size_t O_RED= O_W  + (size_t)HEADS*MLM*DH;
constexpr size_t SCRATCH_TOTAL = O_RED + 8;

__device__ float g_scratch[SCRATCH_TOTAL];

// smem for k_attn3v_mma: Qh,Ql(128x68 ea) Kh,Kl,Vh,Vl(64x68 ea) Ph,Pl(128x68 ea)
#define ATT3_SMEM ((4*(128*68) + 4*(64*68)) * 4)

// ---------------- helpers ----------------------------------------------------
__device__ __forceinline__ unsigned f2tf(float x){
  unsigned u; asm("cvt.rna.tf32.f32 %0, %1;" : "=r"(u) : "f"(x)); return u;
}

#define MMA_TF32(d, a, b0v, b1v) \
  asm("mma.sync.aligned.m16n8k8.row.col.f32.tf32.tf32.f32 " \
      "{%0,%1,%2,%3}, {%4,%5,%6,%7}, {%8,%9}, {%0,%1,%2,%3};\n" \
      : "+f"(d[0]),"+f"(d[1]),"+f"(d[2]),"+f"(d[3]) \
      : "r"(a[0]),"r"(a[1]),"r"(a[2]),"r"(a[3]),"r"(b0v),"r"(b1v))

__device__ __forceinline__ float warpRedSum(float v){
  #pragma unroll
  for (int s=16;s;s>>=1) v += __shfl_xor_sync(0xffffffffu, v, s);
  return v;
}
__device__ __forceinline__ float warpRedMax(float v){
  #pragma unroll
  for (int s=16;s;s>>=1) v = fmaxf(v, __shfl_xor_sync(0xffffffffu, v, s));
  return v;
}
__device__ __forceinline__ float blockRedSum(float v, float* red){
  int lane=threadIdx.x&31, wid=threadIdx.x>>5;
  v = warpRedSum(v);
  if (lane==0) red[wid]=v;
  __syncthreads();
  if (wid==0){
    float t = (lane<8)? red[lane] : 0.f;
    t = warpRedSum(t);
    if (lane==0) red[0]=t;
  }
  __syncthreads();
  float r = red[0];
  __syncthreads();
  return r;
}
__device__ __forceinline__ float blockRedMax(float v, float* red){
  int lane=threadIdx.x&31, wid=threadIdx.x>>5;
  v = warpRedMax(v);
  if (lane==0) red[wid]=v;
  __syncthreads();
  if (wid==0){
    float t = (lane<8)? red[lane] : -1e30f;
    t = warpRedMax(t);
    if (lane==0) red[0]=t;
  }
  __syncthreads();
  float r = red[0];
  __syncthreads();
  return r;
}

// ---------------- build h0 ---------------------------------------------------
__global__ void k_build(const float* __restrict__ x, const float* __restrict__ cls,
                        float* __restrict__ h){
  int idx = blockIdx.x*blockDim.x + threadIdx.x;
  if (idx >= NTOK*DIM) return;
  int r = idx >> 9, c = idx & 511;
  h[idx] = (r == 0) ? cls[c] : x[(size_t)(r-1)*DIM + c];
}

// ---------------- layernorm (+ optional front zero-pad) ----------------------
__global__ __launch_bounds__(256) void k_lnpad(const float* __restrict__ src,
    float* __restrict__ dst, const float* __restrict__ w, const float* __restrict__ b,
    int pad){
  __shared__ float red[32];
  int r = blockIdx.x, tid = threadIdx.x;
  if (r < pad){
    dst[(size_t)r*DIM + tid] = 0.f;
    dst[(size_t)r*DIM + tid + 256] = 0.f;
    return;
  }
  const float* row = src + (size_t)(r-pad)*DIM;
  float v0 = row[tid], v1 = row[tid+256];
  float mu = blockRedSum(v0+v1, red) * (1.f/DIM);
  float d0 = v0-mu, d1 = v1-mu;
  float var = blockRedSum(d0*d0 + d1*d1, red) * (1.f/DIM);
  float rs = 1.f / sqrtf(var + 1e-5f);
  dst[(size_t)r*DIM + tid]       = d0*rs*w[tid]     + b[tid];
  dst[(size_t)r*DIM + tid + 256] = d1*rs*w[tid+256] + b[tid+256];
}

// ---------------- TF32 tensor-core GEMM: C = A@B [+bias][+Cres] --------------
// 128x128 block tile, BK=16, 256 threads (8 warps 4x2), warp tile 32x64.
__global__ __launch_bounds__(256) void k_mma_gemm(
    const float* __restrict__ A, const float* __restrict__ B,
    const float* __restrict__ bias, const float* __restrict__ Cres,
    float* __restrict__ C, int M, int N, int K){
  __shared__ unsigned As[128][20];   // [m][k] + pad
  __shared__ unsigned Bs[16][132];   // [k][n] + pad
  const int bm = blockIdx.y * 128;
  const int bn = blockIdx.x * 128;
  const int tid = threadIdx.x;
  const int w = tid >> 5, lane = tid & 31;
  const int wm = (w & 3) * 32, wn = (w >> 2) * 64;
  const int g = lane >> 2, t = lane & 3;

  float acc[2][8][4];
  #pragma unroll
  for (int i=0;i<2;i++)
    #pragma unroll
    for (int j=0;j<8;j++)
      #pragma unroll
      for (int q=0;q<4;q++) acc[i][j][q]=0.f;

  float4 pa[2], pb[2];
  // prefetch first tile
  #pragma unroll
  for (int i=0;i<2;i++){
    int s = tid + i*256;
    int row = s>>2, kq = (s&3)*4;
    float4 v = make_float4(0.f,0.f,0.f,0.f);
    if (bm+row < M) v = *(const float4*)(A + (size_t)(bm+row)*K + kq);
    pa[i]=v;
    int rowb = s>>5, nq = (s&31)*4;
    float4 vb = make_float4(0.f,0.f,0.f,0.f);
    if (bn+nq < N) vb = *(const float4*)(B + (size_t)rowb*N + bn + nq);
    pb[i]=vb;
  }

  for (int k0 = 0; k0 < K; k0 += 16){
    // store prefetched tile
    #pragma unroll
    for (int i=0;i<2;i++){
      int s = tid + i*256;
      int row = s>>2, kq = (s&3)*4;
      uint4 u; u.x=f2tf(pa[i].x); u.y=f2tf(pa[i].y); u.z=f2tf(pa[i].z); u.w=f2tf(pa[i].w);
      *(uint4*)&As[row][kq] = u;
      int rowb = s>>5, nq = (s&31)*4;
      uint4 ub; ub.x=f2tf(pb[i].x); ub.y=f2tf(pb[i].y); ub.z=f2tf(pb[i].z); ub.w=f2tf(pb[i].w);
      *(uint4*)&Bs[rowb][nq] = ub;
    }
    __syncthreads();
    // prefetch next
    if (k0 + 16 < K){
      #pragma unroll
      for (int i=0;i<2;i++){
        int s = tid + i*256;
        int row = s>>2, kq = (s&3)*4;
        float4 v = make_float4(0.f,0.f,0.f,0.f);
        if (bm+row < M) v = *(const float4*)(A + (size_t)(bm+row)*K + k0+16 + kq);
        pa[i]=v;
        int rowb = s>>5, nq = (s&31)*4;
        float4 vb = make_float4(0.f,0.f,0.f,0.f);
        if (bn+nq < N) vb = *(const float4*)(B + (size_t)(k0+16+rowb)*N + bn + nq);
        pb[i]=vb;
      }
    }
    // compute
    #pragma unroll
    for (int kk=0; kk<16; kk+=8){
      unsigned af[2][4];
      #pragma unroll
      for (int mt=0; mt<2; mt++){
        int r = wm + mt*16 + g;
        af[mt][0]=As[r][kk+t];   af[mt][1]=As[r+8][kk+t];
        af[mt][2]=As[r][kk+t+4]; af[mt][3]=As[r+8][kk+t+4];
      }
      #pragma unroll
      for (int nt=0; nt<8; nt++){
        int c = wn + nt*8 + g;
        unsigned b0 = Bs[kk+t][c], b1 = Bs[kk+t+4][c];
        MMA_TF32(acc[0][nt], af[0], b0, b1);
        MMA_TF32(acc[1][nt], af[1], b0, b1);
      }
    }
    __syncthreads();
  }
  // epilogue
  #pragma unroll
  for (int mt=0; mt<2; mt++){
    #pragma unroll
    for (int nt=0; nt<8; nt++){
      int r0 = bm + wm + mt*16 + g;
      int c0 = bn + wn + nt*8 + t*2;
      #pragma unroll
      for (int q=0;q<4;q++){
        int row = r0 + (q>>1)*8;
        int col = c0 + (q&1);
        if (row < M && col < N){
          float v = acc[mt][nt][q];
          if (bias) v += bias[col];
          if (Cres) v += Cres[(size_t)row*N + col];
          C[(size_t)row*N + col] = v;
        }
      }
    }
  }
}

// ----- batched TF32 gemm, 64x64 tile: C[z] = scale*A[z]@(bI*I + bS*B[z]) -----
// M=K=256 fixed; N in {256,64}. grid (N/64, 4, nbatch), 256 threads.
__global__ __launch_bounds__(256) void k_bgemm64(
    const float* __restrict__ A, const float* __restrict__ B, float* __restrict__ C,
    int N, long long sA, long long sB, long long sC,
    float bI, float bS, float scale){
  __shared__ unsigned As[64][20];    // [m][k] + pad
  __shared__ unsigned Bs[16][68];    // [k][n] + pad
  const float* Ah = A + blockIdx.z * sA;
  const float* Bh = B + blockIdx.z * sB;
  float* Ch = C + blockIdx.z * sC;
  const int K = 256;
  const int bm = blockIdx.y * 64;
  const int bn = blockIdx.x * 64;
  const int tid = threadIdx.x;
  const int w = tid >> 5, lane = tid & 31;
  const int wm = (w & 3) * 16, wn = (w >> 2) * 32;
  const int g = lane >> 2, t = lane & 3;

  float acc[4][4];
  #pragma unroll
  for (int j=0;j<4;j++)
    #pragma unroll
    for (int q=0;q<4;q++) acc[j][q]=0.f;

  for (int k0 = 0; k0 < K; k0 += 16){
    {
      int row = tid >> 2, kq = (tid & 3) * 4;
      float4 v = *(const float4*)(Ah + (size_t)(bm+row)*K + k0 + kq);
      As[row][kq+0]=f2tf(v.x); As[row][kq+1]=f2tf(v.y);
      As[row][kq+2]=f2tf(v.z); As[row][kq+3]=f2tf(v.w);
    }
    {
      int rowb = tid >> 4, cq = (tid & 15) * 4;
      float4 vb = *(const float4*)(Bh + (size_t)(k0+rowb)*N + bn + cq);
      int gk = k0 + rowb;
      float bv[4] = {vb.x, vb.y, vb.z, vb.w};
      #pragma unroll
      for (int q=0;q<4;q++){
        float vv = bS * bv[q];
        if (gk == bn + cq + q) vv += bI;
        Bs[rowb][cq+q] = f2tf(vv);
      }
    }
    __syncthreads();
    #pragma unroll
    for (int kk=0; kk<16; kk+=8){
      unsigned af[4];
      af[0]=As[wm+g][kk+t];   af[1]=As[wm+g+8][kk+t];
      af[2]=As[wm+g][kk+t+4]; af[3]=As[wm+g+8][kk+t+4];
      #pragma unroll
      for (int nt=0; nt<4; nt++){
        int c = wn + nt*8 + g;
        unsigned b0 = Bs[kk+t][c], b1 = Bs[kk+t+4][c];
        MMA_TF32(acc[nt], af, b0, b1);
      }
    }
    __syncthreads();
  }
  #pragma unroll
  for (int nt=0; nt<4; nt++){
    #pragma unroll
    for (int q=0;q<4;q++){
      int row = bm + wm + g + (q>>1)*8;
      int col = bn + wn + nt*8 + t*2 + (q&1);
      Ch[(size_t)row*N + col] = scale * acc[nt][q];
    }
  }
}

// ---------------- landmarks --------------------------------------------------
__global__ __launch_bounds__(64) void k_land(const float* __restrict__ qkv,
    float* __restrict__ ql, float* __restrict__ kl){
  int m = blockIdx.x, h = blockIdx.y, d = threadIdx.x;
  float sq = 0.f, sk = 0.f;
  #pragma unroll 8
  for (int j=0;j<40;j++){
    size_t base = (size_t)(m*40+j)*1536 + h*64 + d;
    sq += qkv[base];
    sk += qkv[base + 512];
  }
  ql[(size_t)(h*MLM+m)*64 + d] = sq * (0.125f/40.f);  // DH^-0.5 folded in
  kl[(size_t)(h*MLM+m)*64 + d] = sk * (1.f/40.f);
}

// ---------------- attn2 = softmax(ql @ kl^T) ---------------------------------
__global__ __launch_bounds__(256) void k_attn2(const float* __restrict__ ql,
    const float* __restrict__ kl, float* __restrict__ X){
  __shared__ float4 q4[16];
  __shared__ float red[32];
  int i = blockIdx.x, h = blockIdx.y, j = threadIdx.x;
  if (j < 16) q4[j] = ((const float4*)(ql + (size_t)(h*MLM+i)*64))[j];
  __syncthreads();
  const float4* kp = (const float4*)(kl + (size_t)(h*MLM+j)*64);
  float s = 0.f;
  #pragma unroll
  for (int t=0;t<16;t++){
    float4 kv = kp[t], q = q4[t];
    s += q.x*kv.x + q.y*kv.y + q.z*kv.z + q.w*kv.w;
  }
  float mx = blockRedMax(s, red);
  float e = expf(s - mx);
  float sm = blockRedSum(e, red);
  X[(size_t)(h*MLM+i)*MLM + j] = e / sm;
}

// ---------------- pinv init: abs row/col max ---------------------------------
__global__ void k_zero2(float* red){ if (threadIdx.x < 2) red[threadIdx.x] = 0.f; }

__global__ __launch_bounds__(256) void k_absmax(const float* __restrict__ X,
    float* __restrict__ red_out, int mode){
  __shared__ float red[32];
  int a = blockIdx.x, h = blockIdx.y, t = threadIdx.x;
  float v;
  if (mode == 0) v = fabsf(X[(size_t)(h*MLM+a)*MLM + t]);   // row sums
  else           v = fabsf(X[(size_t)(h*MLM+t)*MLM + a]);   // col sums
  float s = blockRedSum(v, red);
  if (t == 0) atomicMax((int*)(red_out + mode), __float_as_int(s));
}

__global__ void k_zinit(const float* __restrict__ X, float* __restrict__ Z,
                        const float* __restrict__ red){
  int idx = blockIdx.x*blockDim.x + threadIdx.x;
  if (idx >= HEADS*MLM*MLM) return;
  int h = idx >> 16, r = (idx >> 8) & 255, c = idx & 255;
  float inv = 1.f / (red[0] * red[1]);
  Z[idx] = X[(size_t)h*MLM*MLM + (size_t)c*MLM + r] * inv;
}

// ---------------- zero accumulators for attn3v -------------------------------
__global__ void k_zeroacc(float* oacc, float* rsum){
  int idx = blockIdx.x*blockDim.x + threadIdx.x;
  if (idx < HEADS*MLM*DH) oacc[idx] = 0.f;
  if (idx < HEADS*MLM) rsum[idx] = 0.f;
}

// ---- t3v partials: exp(ql@K^T) @ V over a 1280-key slice, split-TF32 mma ----
// grid (16, HEADS): bx&1 -> 128-row landmark half, bx>>1 -> key slice (8 slices).
// Scores are tiny (|s| < ~1): exp without max subtraction is exact here.
// Full hi/lo operand split keeps fp32-level accuracy. Partials via atomicAdd.
__global__ __launch_bounds__(256, 1) void k_attn3v_mma(
    const float* __restrict__ qkv, const float* __restrict__ ql,
    float* __restrict__ oacc, float* __restrict__ rsum){
  extern __shared__ unsigned dyn3[];
  unsigned* Qh = dyn3;                 // [128][68]
  unsigned* Qlo = Qh + 128*68;         // [128][68]
  unsigned* Kh = Qlo + 128*68;         // [64][68]
  unsigned* Kl = Kh + 64*68;
  unsigned* Vh = Kl + 64*68;
  unsigned* Vl = Vh + 64*68;
  unsigned* Ph = Vl + 64*68;           // [128][68]
  unsigned* Pl = Ph + 128*68;

  const int h = blockIdx.y;
  const int m0 = (blockIdx.x & 1) * 128;
  const int slice = blockIdx.x >> 1;   // 0..7, 1280 keys each
  const int tid = threadIdx.x;
  const int w = tid >> 5, lane = tid & 31;
  const int g = lane >> 2, t = lane & 3;
  const int wm = w * 16;               // warp owns rows wm..wm+15

  // load Q (128x64) hi/lo
  #pragma unroll
  for (int l=0;l<8;l++){
    int s = tid + l*256;
    int row = s>>4, dq = (s&15)*4;
    float4 v = *(const float4*)(ql + (size_t)(h*MLM + m0 + row)*64 + dq);
    float av[4] = {v.x, v.y, v.z, v.w};
    #pragma unroll
    for (int q=0;q<4;q++){
      unsigned hi = f2tf(av[q]);
      Qh[row*68+dq+q]  = hi;
      Qlo[row*68+dq+q] = f2tf(av[q] - __uint_as_float(hi));
    }
  }

  float acc_o[8][4];
  #pragma unroll
  for (int j=0;j<8;j++)
    #pragma unroll
    for (int q=0;q<4;q++) acc_o[j][q]=0.f;
  float rs0 = 0.f, rs1 = 0.f;          // rowsums for rows wm+g, wm+g+8

  const int key_base = slice * 1280;
  for (int cn = 0; cn < 20; cn++){
    int key0 = key_base + cn*64;
    __syncthreads();                   // K/V smem free of prior readers
    // load K,V chunk (64x64 each) hi/lo
    #pragma unroll
    for (int l=0;l<4;l++){
      int s = tid + l*256;
      int row = s>>4, dq = (s&15)*4;
      const float* base = qkv + (size_t)(key0+row)*1536 + h*64 + dq;
      float4 kv = *(const float4*)(base + 512);
      float4 vv = *(const float4*)(base + 1024);
      float ka[4] = {kv.x, kv.y, kv.z, kv.w};
      float va[4] = {vv.x, vv.y, vv.z, vv.w};
      #pragma unroll
      for (int q=0;q<4;q++){
        unsigned hi = f2tf(ka[q]);
        Kh[row*68+dq+q] = hi;
        Kl[row*68+dq+q] = f2tf(ka[q] - __uint_as_float(hi));
        unsigned hv = f2tf(va[q]);
        Vh[row*68+dq+q] = hv;
        Vl[row*68+dq+q] = f2tf(va[q] - __uint_as_float(hv));
      }
    }
    __syncthreads();
    // S = Q @ K^T : warp rows wm..wm+15, all 64 key cols
    float sacc[8][4];
    #pragma unroll
    for (int nt=0;nt<8;nt++)
      #pragma unroll
      for (int q=0;q<4;q++) sacc[nt][q]=0.f;
    #pragma unroll
    for (int kk=0; kk<64; kk+=8){
      unsigned ah[4], al[4];
      ah[0]=Qh[(wm+g)*68+kk+t];    ah[1]=Qh[(wm+g+8)*68+kk+t];
      ah[2]=Qh[(wm+g)*68+kk+t+4];  ah[3]=Qh[(wm+g+8)*68+kk+t+4];
      al[0]=Qlo[(wm+g)*68+kk+t];   al[1]=Qlo[(wm+g+8)*68+kk+t];
      al[2]=Qlo[(wm+g)*68+kk+t+4]; al[3]=Qlo[(wm+g+8)*68+kk+t+4];
      #pragma unroll
      for (int nt=0; nt<8; nt++){
        int c = nt*8 + g;            // key column
        unsigned bh0 = Kh[c*68+kk+t], bh1 = Kh[c*68+kk+t+4];
        unsigned bl0 = Kl[c*68+kk+t], bl1 = Kl[c*68+kk+t+4];
        MMA_TF32(sacc[nt], ah, bh0, bh1);
        MMA_TF32(sacc[nt], al, bh0, bh1);
        MMA_TF32(sacc[nt], ah, bl0, bl1);
      }
    }
    // exp, rowsums, store P hi/lo
    #pragma unroll
    for (int nt=0; nt<8; nt++){
      float e0 = expf(sacc[nt][0]), e1 = expf(sacc[nt][1]);
      float e2 = expf(sacc[nt][2]), e3 = expf(sacc[nt][3]);
      rs0 += e0 + e1; rs1 += e2 + e3;
      int c0 = nt*8 + t*2;
      unsigned h0 = f2tf(e0), h1 = f2tf(e1), h2 = f2tf(e2), h3 = f2tf(e3);
      Ph[(wm+g)*68 + c0]     = h0;
      Ph[(wm+g)*68 + c0+1]   = h1;
      Ph[(wm+g+8)*68 + c0]   = h2;
      Ph[(wm+g+8)*68 + c0+1] = h3;
      Pl[(wm+g)*68 + c0]     = f2tf(e0 - __uint_as_float(h0));
      Pl[(wm+g)*68 + c0+1]   = f2tf(e1 - __uint_as_float(h1));
      Pl[(wm+g+8)*68 + c0]   = f2tf(e2 - __uint_as_float(h2));
      Pl[(wm+g+8)*68 + c0+1] = f2tf(e3 - __uint_as_float(h3));
    }
    __syncwarp();                      // own-warp P rows only; warp-local sync
    // O += P @ V : rows wm..wm+15 x 64 dims, K = 64 keys
    #pragma unroll
    for (int kk=0; kk<64; kk+=8){
      unsigned ah[4], al[4];
      ah[0]=Ph[(wm+g)*68+kk+t];    ah[1]=Ph[(wm+g+8)*68+kk+t];
      ah[2]=Ph[(wm+g)*68+kk+t+4];  ah[3]=Ph[(wm+g+8)*68+kk+t+4];
      al[0]=Pl[(wm+g)*68+kk+t];    al[1]=Pl[(wm+g+8)*68+kk+t];
      al[2]=Pl[(wm+g)*68+kk+t+4];  al[3]=Pl[(wm+g+8)*68+kk+t+4];
      #pragma unroll
      for (int nt=0; nt<8; nt++){
        int c = nt*8 + g;            // dim column
        unsigned bh0 = Vh[(kk+t)*68+c], bh1 = Vh[(kk+t+4)*68+c];
        unsigned bl0 = Vl[(kk+t)*68+c], bl1 = Vl[(kk+t+4)*68+c];
        MMA_TF32(acc_o[nt], ah, bh0, bh1);
        MMA_TF32(acc_o[nt], al, bh0, bh1);
        MMA_TF32(acc_o[nt], ah, bl0, bl1);
      }
    }
  }
  // reduce rowsums across the 4 t-lanes sharing each g
  rs0 += __shfl_xor_sync(0xffffffffu, rs0, 1);
  rs0 += __shfl_xor_sync(0xffffffffu, rs0, 2);
  rs1 += __shfl_xor_sync(0xffffffffu, rs1, 1);
  rs1 += __shfl_xor_sync(0xffffffffu, rs1, 2);
  if (t == 0){
    atomicAdd(&rsum[h*MLM + m0 + wm + g], rs0);
    atomicAdd(&rsum[h*MLM + m0 + wm + g + 8], rs1);
  }
  // emit O partials
  #pragma unroll
  for (int nt=0; nt<8; nt++){
    #pragma unroll
    for (int q=0;q<4;q++){
      int row = m0 + wm + g + (q>>1)*8;
      int col = nt*8 + t*2 + (q&1);
      atomicAdd(&oacc[(size_t)(h*MLM + row)*64 + col], acc_o[nt][q]);
    }
  }
}

__global__ void k_t3fin(const float* __restrict__ oacc, const float* __restrict__ rsum,
                        float* __restrict__ t3v){
  int idx = blockIdx.x*blockDim.x + threadIdx.x;
  if (idx >= HEADS*MLM*DH) return;
  t3v[idx] = oacc[idx] / rsum[idx >> 6];
}

// ---------------- out = softmax(q @ kl^T) @ W (8 tokens / block) -------------
__global__ __launch_bounds__(256) void k_attn1W(const float* __restrict__ qkv,
    const float* __restrict__ kl, const float* __restrict__ W, float* __restrict__ ao){
  __shared__ float4 qs[8][16];
  __shared__ float p[8][256];
  __shared__ float red[32];
  int h = blockIdx.y;
  int t0 = blockIdx.x * 8;
  int tid = threadIdx.x;
  for (int idx = tid; idx < 8*16; idx += 256){
    int r = idx >> 4, t = idx & 15;
    float4 v = ((const float4*)(qkv + (size_t)(t0+r)*1536 + h*64))[t];
    v.x*=0.125f; v.y*=0.125f; v.z*=0.125f; v.w*=0.125f;
    qs[r][t]=v;
  }
  __syncthreads();
  {
    int m = tid;
    const float4* kp = (const float4*)(kl + (size_t)(h*MLM+m)*64);
    float a[8];
    #pragma unroll
    for (int r=0;r<8;r++) a[r]=0.f;
    #pragma unroll
    for (int t=0;t<16;t++){
      float4 kv = kp[t];
      #pragma unroll
      for (int r=0;r<8;r++){
        float4 q = qs[r][t];
        a[r] += q.x*kv.x + q.y*kv.y + q.z*kv.z + q.w*kv.w;
      }
    }
    #pragma unroll
    for (int r=0;r<8;r++) p[r][m] = a[r];
  }
  __syncthreads();
  #pragma unroll
  for (int r=0;r<8;r++){
    float s = p[r][tid];
    float mx = blockRedMax(s, red);
    float e = expf(s - mx);
    float sm = blockRedSum(e, red);
    p[r][tid] = e / sm;
  }
  __syncthreads();
  int g = tid >> 6, d = tid & 63;
  float o0=0.f, o1=0.f;
  for (int m=0;m<256;m++){
    float w = W[(size_t)(h*MLM+m)*64 + d];
    o0 += p[g][m]*w;
    o1 += p[g+4][m]*w;
  }
  ao[(size_t)(t0+g)*DIM   + h*64 + d] = o0;
  ao[(size_t)(t0+g+4)*DIM + h*64 + d] = o1;
}

// ---------------- residual depthwise conv (kernel 33 along sequence) ---------
__global__ void k_convres(const float* __restrict__ qkv, const float* __restrict__ rw,
                          float* __restrict__ ao){
  int idx = blockIdx.x*blockDim.x + threadIdx.x;
  if (idx >= NPAD*DIM) return;
  int n = idx >> 9, c = idx & 511;
  int h = c >> 6;
  float acc = ao[idx];
  #pragma unroll
  for (int t=0;t<33;t++){
    int s = n + t - 16;
    if (s >= 0 && s < NPAD)
      acc += rw[h*33+t] * qkv[(size_t)s*1536 + 1024 + c];
  }
  ao[idx] = acc;
}

// ---------------- PPEG -------------------------------------------------------
__global__ void k_cls(const float* __restrict__ hin, float* __restrict__ hout){
  int c = blockIdx.x*blockDim.x + threadIdx.x;
  if (c < DIM) hout[c] = hin[c];
}

__global__ __launch_bounds__(128) void k_ppeg(const float* __restrict__ hin,
    const float* __restrict__ w7, const float* __restrict__ b7,
    const float* __restrict__ w5, const float* __restrict__ b5,
    const float* __restrict__ w3, const float* __restrict__ b3,
    float* __restrict__ hout){
  int pos = blockIdx.x;                 // 0..9999
  int c = blockIdx.y*128 + threadIdx.x;
  int i = pos / HH, j = pos % HH;
  float acc = hin[(size_t)(1+pos)*DIM + c] + b7[c] + b5[c] + b3[c];
  #pragma unroll
  for (int a=0;a<7;a++){
    int ii = i + a - 3;
    if (ii < 0 || ii >= HH) continue;
    #pragma unroll
    for (int bb=0;bb<7;bb++){
      int jj = j + bb - 3;
      if (jj < 0 || jj >= HH) continue;
      acc += hin[(size_t)(1+ii*HH+jj)*DIM + c] * w7[(size_t)c*49 + a*7 + bb];
    }
  }
  #pragma unroll
  for (int a=0;a<5;a++){
    int ii = i + a - 2;
    if (ii < 0 || ii >= HH) continue;
    #pragma unroll
    for (int bb=0;bb<5;bb++){
      int jj = j + bb - 2;
      if (jj < 0 || jj >= HH) continue;
      acc += hin[(size_t)(1+ii*HH+jj)*DIM + c] * w5[(size_t)c*25 + a*5 + bb];
    }
  }
  #pragma unroll
  for (int a=0;a<3;a++){
    int ii = i + a - 1;
    if (ii < 0 || ii >= HH) continue;
    #pragma unroll
    for (int bb=0;bb<3;bb++){
      int jj = j + bb - 1;
      if (jj < 0 || jj >= HH) continue;
      acc += hin[(size_t)(1+ii*HH+jj)*DIM + c] * w3[(size_t)c*9 + a*3 + bb];
    }
  }
  hout[(size_t)(1+pos)*DIM + c] = acc;
}

// ---------------- heads ------------------------------------------------------
__global__ void k_heads(const float* __restrict__ hn,
    const float* __restrict__ fcw, const float* __restrict__ fcb,
    const float* __restrict__ pcw, const float* __restrict__ pcb,
    float* __restrict__ out){
  int warp = (blockIdx.x*blockDim.x + threadIdx.x) >> 5;
  int lane = threadIdx.x & 31;
  if (warp >= NTOK) return;
  const float* hr = hn + (size_t)warp*DIM;
  const float* Wm = (warp == 0) ? fcw : pcw;
  float d0=0.f, d1=0.f;
  for (int k=lane;k<DIM;k+=32){
    float v = hr[k];
    d0 += v*Wm[2*k];
    d1 += v*Wm[2*k+1];
  }
  d0 = warpRedSum(d0);
  d1 = warpRedSum(d1);
  if (lane == 0){
    if (warp == 0){
      out[0] = d0 + fcb[0];
      out[1] = d1 + fcb[1];
    } else {
      float l0 = d0 + pcb[0], l1 = d1 + pcb[1];
      int r = warp - 1;
      out[2 + 2*r]     = l0;
      out[2 + 2*r + 1] = l1;
      float m = fmaxf(l0,l1);
      float e0 = expf(l0-m), e1 = expf(l1-m);
      float inv = 1.f/(e0+e1);
      out[2 + 2*N0 + 2*r]     = e0*inv;
      out[2 + 2*N0 + 2*r + 1] = e1*inv;
    }
  }
}

// ---------------- host side --------------------------------------------------
static void run_attn_block(const float* ln_w, const float* ln_b, const float* qkv_w,
    const float* out_w, const float* out_b, const float* res_w,
    float* h, float* S){
  float* XP  = S + O_XP;
  float* QKV = S + O_QKV;
  float* AO  = S + O_AO;
  float* QL  = S + O_QL;
  float* KL  = S + O_KL;
  float* X   = S + O_X;
  float* Z0  = S + O_Z0;
  float* Z1  = S + O_Z1;
  float* TA  = S + O_TA;   // attn3v oacc
  float* TU  = S + O_TU;   // attn3v rsum
  float* TT  = S + O_TT;
  float* T3  = S + O_T3;
  float* Wb  = S + O_W;
  float* RED = S + O_RED;

  k_lnpad<<<NPAD, 256>>>(h, XP, ln_w, ln_b, PADR);
  k_mma_gemm<<<dim3(1536/128, NPAD/128), 256>>>(XP, qkv_w, nullptr, nullptr, QKV,
                                                NPAD, 1536, DIM);
  k_land<<<dim3(MLM, HEADS), 64>>>(QKV, QL, KL);
  k_attn2<<<dim3(MLM, HEADS), 256>>>(QL, KL, X);
  k_zero2<<<1, 32>>>(RED);
  k_absmax<<<dim3(MLM, HEADS), 256>>>(X, RED, 0);
  k_absmax<<<dim3(MLM, HEADS), 256>>>(X, RED, 1);
  k_zinit<<<(HEADS*MLM*MLM + 255)/256, 256>>>(X, Z0, RED);

  const long long sM = (long long)MLM*MLM;
  float* zc = Z0; float* zn = Z1;
  for (int it=0; it<6; it++){
    k_bgemm64<<<dim3(4,4,HEADS), 256>>>(X,  zc, TA, MLM, sM, sM, sM, 0.f,  1.f, 1.f);
    k_bgemm64<<<dim3(4,4,HEADS), 256>>>(TA, TA, TU, MLM, sM, sM, sM, 7.f, -1.f, 1.f);
    k_bgemm64<<<dim3(4,4,HEADS), 256>>>(TA, TU, TT, MLM, sM, sM, sM, 15.f,-1.f, 1.f);
    k_bgemm64<<<dim3(4,4,HEADS), 256>>>(zc, TT, zn, MLM, sM, sM, sM, 13.f,-1.f, 0.25f);
    float* tmp = zc; zc = zn; zn = tmp;
  }

  // attn3 @ v via split-TF32 tensor cores, key-sliced partials
  k_zeroacc<<<(HEADS*MLM*DH + 255)/256, 256>>>(TA, TU);
  k_attn3v_mma<<<dim3(16, HEADS), 256, ATT3_SMEM>>>(QKV, QL, TA, TU);
  k_t3fin<<<(HEADS*MLM*DH + 255)/256, 256>>>(TA, TU, T3);

  const long long sS = (long long)MLM*DH;
  k_bgemm64<<<dim3(1,4,HEADS), 256>>>(zc, T3, Wb, DH, sM, sS, sS, 0.f, 1.f, 1.f);
  k_attn1W<<<dim3(NPAD/8, HEADS), 256>>>(QKV, KL, Wb, AO);
  k_convres<<<(NPAD*DIM + 255)/256, 256>>>(QKV, res_w, AO);
  // out proj + residual into h (rows PADR.. of AO map to h rows 0..)
  k_mma_gemm<<<dim3(DIM/128, (NTOK+127)/128), 256>>>(AO + (size_t)PADR*DIM, out_w,
                                                     out_b, h, h, NTOK, DIM, DIM);
}

extern "C" void kernel_launch(void* const* d_in, const int* in_sizes, int n_in,
                              void* d_out, int out_size){
  const float* x      = (const float*)d_in[0];
  const float* cls    = (const float*)d_in[1];
  const float* ln1_w  = (const float*)d_in[2];
  const float* ln1_b  = (const float*)d_in[3];
  const float* qkv1_w = (const float*)d_in[4];
  const float* out1_w = (const float*)d_in[5];
  const float* out1_b = (const float*)d_in[6];
  const float* res1_w = (const float*)d_in[7];
  const float* p7_w   = (const float*)d_in[8];
  const float* p7_b   = (const float*)d_in[9];
  const float* p5_w   = (const float*)d_in[10];
  const float* p5_b   = (const float*)d_in[11];
  const float* p3_w   = (const float*)d_in[12];
  const float* p3_b   = (const float*)d_in[13];
  const float* ln2_w  = (const float*)d_in[14];
  const float* ln2_b  = (const float*)d_in[15];
  const float* qkv2_w = (const float*)d_in[16];
  const float* out2_w = (const float*)d_in[17];
  const float* out2_b = (const float*)d_in[18];
  const float* res2_w = (const float*)d_in[19];
  const float* norm_w = (const float*)d_in[20];
  const float* norm_b = (const float*)d_in[21];
  const float* fc2_w  = (const float*)d_in[22];
  const float* fc2_b  = (const float*)d_in[23];
  const float* pc_w   = (const float*)d_in[24];
  const float* pc_b   = (const float*)d_in[25];

  float* S = nullptr;
  cudaGetSymbolAddress((void**)&S, g_scratch);
  cudaFuncSetAttribute(k_attn3v_mma, cudaFuncAttributeMaxDynamicSharedMemorySize,
                       ATT3_SMEM);

  float* H0 = S + O_H0;
  float* H1 = S + O_H1;
  float* XP = S + O_XP;

  k_build<<<(NTOK*DIM + 255)/256, 256>>>(x, cls, H0);

  run_attn_block(ln1_w, ln1_b, qkv1_w, out1_w, out1_b, res1_w, H0, S);

  k_cls<<<2, 256>>>(H0, H1);
  k_ppeg<<<dim3(N0, DIM/128), 128>>>(H0, p7_w, p7_b, p5_w, p5_b, p3_w, p3_b, H1);

  run_attn_block(ln2_w, ln2_b, qkv2_w, out2_w, out2_b, res2_w, H1, S);

  k_lnpad<<<NTOK, 256>>>(H1, XP, norm_w, norm_b, 0);
  k_heads<<<(NTOK + 7)/8, 256>>>(XP, fc2_w, fc2_b, pc_w, pc_b, (float*)d_out);
}

// round 10
// speedup vs baseline: 2.1159x; 1.2633x over previous
#include <cuda_runtime.h>
#include <math.h>

#define N0    10000
#define NTOK  10001
#define DIM   512
#define NPAD  10240
#define PADR  239
#define HEADS 8
#define DH    64
#define MLM   256
#define HH    100

// ---------------- scratch (single device global, no allocations) -------------
constexpr size_t O_H0 = 0;                                  // NTOK*DIM
constexpr size_t O_H1 = O_H0 + (size_t)NTOK*DIM;
constexpr size_t O_XP = O_H1 + (size_t)NTOK*DIM;            // NPAD*DIM (LN+pad; final hn)
constexpr size_t O_QKV= O_XP + (size_t)NPAD*DIM;            // NPAD*1536
constexpr size_t O_AO = O_QKV+ (size_t)NPAD*3*DIM;          // NPAD*DIM
constexpr size_t O_QL = O_AO + (size_t)NPAD*DIM;
constexpr size_t O_KL = O_QL + (size_t)HEADS*MLM*DH;
constexpr size_t O_X  = O_KL + (size_t)HEADS*MLM*DH;        // attn2
constexpr size_t O_Z0 = O_X  + (size_t)HEADS*MLM*MLM;
constexpr size_t O_Z1 = O_Z0 + (size_t)HEADS*MLM*MLM;
constexpr size_t O_TA = O_Z1 + (size_t)HEADS*MLM*MLM;       // doubles as attn3v oacc
constexpr size_t O_TU = O_TA + (size_t)HEADS*MLM*MLM;       // doubles as attn3v rsum
constexpr size_t O_TT = O_TU + (size_t)HEADS*MLM*MLM;
constexpr size_t O_T3 = O_TT + (size_t)HEADS*MLM*MLM;       // attn3@v : H*256*64
constexpr size_t O_W  = O_T3 + (size_t)HEADS*MLM*DH;        // Z@(attn3@v)
constexpr size_t O_RED= O_W  + (size_t)HEADS*MLM*DH;
constexpr size_t SCRATCH_TOTAL = O_RED + 8;

__device__ float g_scratch[SCRATCH_TOTAL];

// smem layout (both mma-attention kernels):
// Qh,Ql(128x68 ea), Bh0,Bl0,Bh1,Bl1(64x68 ea), Ph,Pl(128x68 ea)
#define ATT3_SMEM ((4*(128*68) + 4*(64*68)) * 4)

// ---------------- helpers ----------------------------------------------------
__device__ __forceinline__ unsigned f2tf(float x){
  unsigned u; asm("cvt.rna.tf32.f32 %0, %1;" : "=r"(u) : "f"(x)); return u;
}

#define MMA_TF32(d, a, b0v, b1v) \
  asm("mma.sync.aligned.m16n8k8.row.col.f32.tf32.tf32.f32 " \
      "{%0,%1,%2,%3}, {%4,%5,%6,%7}, {%8,%9}, {%0,%1,%2,%3};\n" \
      : "+f"(d[0]),"+f"(d[1]),"+f"(d[2]),"+f"(d[3]) \
      : "r"(a[0]),"r"(a[1]),"r"(a[2]),"r"(a[3]),"r"(b0v),"r"(b1v))

__device__ __forceinline__ float warpRedSum(float v){
  #pragma unroll
  for (int s=16;s;s>>=1) v += __shfl_xor_sync(0xffffffffu, v, s);
  return v;
}
__device__ __forceinline__ float warpRedMax(float v){
  #pragma unroll
  for (int s=16;s;s>>=1) v = fmaxf(v, __shfl_xor_sync(0xffffffffu, v, s));
  return v;
}
__device__ __forceinline__ float blockRedSum(float v, float* red){
  int lane=threadIdx.x&31, wid=threadIdx.x>>5;
  v = warpRedSum(v);
  if (lane==0) red[wid]=v;
  __syncthreads();
  if (wid==0){
    float t = (lane<8)? red[lane] : 0.f;
    t = warpRedSum(t);
    if (lane==0) red[0]=t;
  }
  __syncthreads();
  float r = red[0];
  __syncthreads();
  return r;
}
__device__ __forceinline__ float blockRedMax(float v, float* red){
  int lane=threadIdx.x&31, wid=threadIdx.x>>5;
  v = warpRedMax(v);
  if (lane==0) red[wid]=v;
  __syncthreads();
  if (wid==0){
    float t = (lane<8)? red[lane] : -1e30f;
    t = warpRedMax(t);
    if (lane==0) red[0]=t;
  }
  __syncthreads();
  float r = red[0];
  __syncthreads();
  return r;
}

// ---------------- build h0 ---------------------------------------------------
__global__ void k_build(const float* __restrict__ x, const float* __restrict__ cls,
                        float* __restrict__ h){
  int idx = blockIdx.x*blockDim.x + threadIdx.x;
  if (idx >= NTOK*DIM) return;
  int r = idx >> 9, c = idx & 511;
  h[idx] = (r == 0) ? cls[c] : x[(size_t)(r-1)*DIM + c];
}

// ---------------- layernorm (+ optional front zero-pad) ----------------------
__global__ __launch_bounds__(256) void k_lnpad(const float* __restrict__ src,
    float* __restrict__ dst, const float* __restrict__ w, const float* __restrict__ b,
    int pad){
  __shared__ float red[32];
  int r = blockIdx.x, tid = threadIdx.x;
  if (r < pad){
    dst[(size_t)r*DIM + tid] = 0.f;
    dst[(size_t)r*DIM + tid + 256] = 0.f;
    return;
  }
  const float* row = src + (size_t)(r-pad)*DIM;
  float v0 = row[tid], v1 = row[tid+256];
  float mu = blockRedSum(v0+v1, red) * (1.f/DIM);
  float d0 = v0-mu, d1 = v1-mu;
  float var = blockRedSum(d0*d0 + d1*d1, red) * (1.f/DIM);
  float rs = 1.f / sqrtf(var + 1e-5f);
  dst[(size_t)r*DIM + tid]       = d0*rs*w[tid]     + b[tid];
  dst[(size_t)r*DIM + tid + 256] = d1*rs*w[tid+256] + b[tid+256];
}

// ---------------- TF32 tensor-core GEMM: C = A@B [+bias][+Cres] --------------
// 128x128 block tile, BK=16, 256 threads (8 warps 4x2), warp tile 32x64.
__global__ __launch_bounds__(256) void k_mma_gemm(
    const float* __restrict__ A, const float* __restrict__ B,
    const float* __restrict__ bias, const float* __restrict__ Cres,
    float* __restrict__ C, int M, int N, int K){
  __shared__ unsigned As[128][20];   // [m][k] + pad
  __shared__ unsigned Bs[16][132];   // [k][n] + pad
  const int bm = blockIdx.y * 128;
  const int bn = blockIdx.x * 128;
  const int tid = threadIdx.x;
  const int w = tid >> 5, lane = tid & 31;
  const int wm = (w & 3) * 32, wn = (w >> 2) * 64;
  const int g = lane >> 2, t = lane & 3;

  float acc[2][8][4];
  #pragma unroll
  for (int i=0;i<2;i++)
    #pragma unroll
    for (int j=0;j<8;j++)
      #pragma unroll
      for (int q=0;q<4;q++) acc[i][j][q]=0.f;

  float4 pa[2], pb[2];
  // prefetch first tile
  #pragma unroll
  for (int i=0;i<2;i++){
    int s = tid + i*256;
    int row = s>>2, kq = (s&3)*4;
    float4 v = make_float4(0.f,0.f,0.f,0.f);
    if (bm+row < M) v = *(const float4*)(A + (size_t)(bm+row)*K + kq);
    pa[i]=v;
    int rowb = s>>5, nq = (s&31)*4;
    float4 vb = make_float4(0.f,0.f,0.f,0.f);
    if (bn+nq < N) vb = *(const float4*)(B + (size_t)rowb*N + bn + nq);
    pb[i]=vb;
  }

  for (int k0 = 0; k0 < K; k0 += 16){
    // store prefetched tile
    #pragma unroll
    for (int i=0;i<2;i++){
      int s = tid + i*256;
      int row = s>>2, kq = (s&3)*4;
      uint4 u; u.x=f2tf(pa[i].x); u.y=f2tf(pa[i].y); u.z=f2tf(pa[i].z); u.w=f2tf(pa[i].w);
      *(uint4*)&As[row][kq] = u;
      int rowb = s>>5, nq = (s&31)*4;
      uint4 ub; ub.x=f2tf(pb[i].x); ub.y=f2tf(pb[i].y); ub.z=f2tf(pb[i].z); ub.w=f2tf(pb[i].w);
      *(uint4*)&Bs[rowb][nq] = ub;
    }
    __syncthreads();
    // prefetch next
    if (k0 + 16 < K){
      #pragma unroll
      for (int i=0;i<2;i++){
        int s = tid + i*256;
        int row = s>>2, kq = (s&3)*4;
        float4 v = make_float4(0.f,0.f,0.f,0.f);
        if (bm+row < M) v = *(const float4*)(A + (size_t)(bm+row)*K + k0+16 + kq);
        pa[i]=v;
        int rowb = s>>5, nq = (s&31)*4;
        float4 vb = make_float4(0.f,0.f,0.f,0.f);
        if (bn+nq < N) vb = *(const float4*)(B + (size_t)(k0+16+rowb)*N + bn + nq);
        pb[i]=vb;
      }
    }
    // compute
    #pragma unroll
    for (int kk=0; kk<16; kk+=8){
      unsigned af[2][4];
      #pragma unroll
      for (int mt=0; mt<2; mt++){
        int r = wm + mt*16 + g;
        af[mt][0]=As[r][kk+t];   af[mt][1]=As[r+8][kk+t];
        af[mt][2]=As[r][kk+t+4]; af[mt][3]=As[r+8][kk+t+4];
      }
      #pragma unroll
      for (int nt=0; nt<8; nt++){
        int c = wn + nt*8 + g;
        unsigned b0 = Bs[kk+t][c], b1 = Bs[kk+t+4][c];
        MMA_TF32(acc[0][nt], af[0], b0, b1);
        MMA_TF32(acc[1][nt], af[1], b0, b1);
      }
    }
    __syncthreads();
  }
  // epilogue
  #pragma unroll
  for (int mt=0; mt<2; mt++){
    #pragma unroll
    for (int nt=0; nt<8; nt++){
      int r0 = bm + wm + mt*16 + g;
      int c0 = bn + wn + nt*8 + t*2;
      #pragma unroll
      for (int q=0;q<4;q++){
        int row = r0 + (q>>1)*8;
        int col = c0 + (q&1);
        if (row < M && col < N){
          float v = acc[mt][nt][q];
          if (bias) v += bias[col];
          if (Cres) v += Cres[(size_t)row*N + col];
          C[(size_t)row*N + col] = v;
        }
      }
    }
  }
}

// ----- batched TF32 gemm, 64x64 tile: C[z] = scale*A[z]@(bI*I + bS*B[z]) -----
// M=K=256 fixed; N in {256,64}. grid (N/64, 4, nbatch), 256 threads.
__global__ __launch_bounds__(256) void k_bgemm64(
    const float* __restrict__ A, const float* __restrict__ B, float* __restrict__ C,
    int N, long long sA, long long sB, long long sC,
    float bI, float bS, float scale){
  __shared__ unsigned As[64][20];    // [m][k] + pad
  __shared__ unsigned Bs[16][68];    // [k][n] + pad
  const float* Ah = A + blockIdx.z * sA;
  const float* Bh = B + blockIdx.z * sB;
  float* Ch = C + blockIdx.z * sC;
  const int K = 256;
  const int bm = blockIdx.y * 64;
  const int bn = blockIdx.x * 64;
  const int tid = threadIdx.x;
  const int w = tid >> 5, lane = tid & 31;
  const int wm = (w & 3) * 16, wn = (w >> 2) * 32;
  const int g = lane >> 2, t = lane & 3;

  float acc[4][4];
  #pragma unroll
  for (int j=0;j<4;j++)
    #pragma unroll
    for (int q=0;q<4;q++) acc[j][q]=0.f;

  for (int k0 = 0; k0 < K; k0 += 16){
    {
      int row = tid >> 2, kq = (tid & 3) * 4;
      float4 v = *(const float4*)(Ah + (size_t)(bm+row)*K + k0 + kq);
      As[row][kq+0]=f2tf(v.x); As[row][kq+1]=f2tf(v.y);
      As[row][kq+2]=f2tf(v.z); As[row][kq+3]=f2tf(v.w);
    }
    {
      int rowb = tid >> 4, cq = (tid & 15) * 4;
      float4 vb = *(const float4*)(Bh + (size_t)(k0+rowb)*N + bn + cq);
      int gk = k0 + rowb;
      float bv[4] = {vb.x, vb.y, vb.z, vb.w};
      #pragma unroll
      for (int q=0;q<4;q++){
        float vv = bS * bv[q];
        if (gk == bn + cq + q) vv += bI;
        Bs[rowb][cq+q] = f2tf(vv);
      }
    }
    __syncthreads();
    #pragma unroll
    for (int kk=0; kk<16; kk+=8){
      unsigned af[4];
      af[0]=As[wm+g][kk+t];   af[1]=As[wm+g+8][kk+t];
      af[2]=As[wm+g][kk+t+4]; af[3]=As[wm+g+8][kk+t+4];
      #pragma unroll
      for (int nt=0; nt<4; nt++){
        int c = wn + nt*8 + g;
        unsigned b0 = Bs[kk+t][c], b1 = Bs[kk+t+4][c];
        MMA_TF32(acc[nt], af, b0, b1);
      }
    }
    __syncthreads();
  }
  #pragma unroll
  for (int nt=0; nt<4; nt++){
    #pragma unroll
    for (int q=0;q<4;q++){
      int row = bm + wm + g + (q>>1)*8;
      int col = bn + wn + nt*8 + t*2 + (q&1);
      Ch[(size_t)row*N + col] = scale * acc[nt][q];
    }
  }
}

// ---------------- landmarks --------------------------------------------------
__global__ __launch_bounds__(64) void k_land(const float* __restrict__ qkv,
    float* __restrict__ ql, float* __restrict__ kl){
  int m = blockIdx.x, h = blockIdx.y, d = threadIdx.x;
  float sq = 0.f, sk = 0.f;
  #pragma unroll 8
  for (int j=0;j<40;j++){
    size_t base = (size_t)(m*40+j)*1536 + h*64 + d;
    sq += qkv[base];
    sk += qkv[base + 512];
  }
  ql[(size_t)(h*MLM+m)*64 + d] = sq * (0.125f/40.f);  // DH^-0.5 folded in
  kl[(size_t)(h*MLM+m)*64 + d] = sk * (1.f/40.f);
}

// ---------------- attn2 = softmax(ql @ kl^T) ---------------------------------
__global__ __launch_bounds__(256) void k_attn2(const float* __restrict__ ql,
    const float* __restrict__ kl, float* __restrict__ X){
  __shared__ float4 q4[16];
  __shared__ float red[32];
  int i = blockIdx.x, h = blockIdx.y, j = threadIdx.x;
  if (j < 16) q4[j] = ((const float4*)(ql + (size_t)(h*MLM+i)*64))[j];
  __syncthreads();
  const float4* kp = (const float4*)(kl + (size_t)(h*MLM+j)*64);
  float s = 0.f;
  #pragma unroll
  for (int t=0;t<16;t++){
    float4 kv = kp[t], q = q4[t];
    s += q.x*kv.x + q.y*kv.y + q.z*kv.z + q.w*kv.w;
  }
  float mx = blockRedMax(s, red);
  float e = expf(s - mx);
  float sm = blockRedSum(e, red);
  X[(size_t)(h*MLM+i)*MLM + j] = e / sm;
}

// ---------------- pinv init: abs row/col max ---------------------------------
__global__ void k_zero2(float* red){ if (threadIdx.x < 2) red[threadIdx.x] = 0.f; }

__global__ __launch_bounds__(256) void k_absmax(const float* __restrict__ X,
    float* __restrict__ red_out, int mode){
  __shared__ float red[32];
  int a = blockIdx.x, h = blockIdx.y, t = threadIdx.x;
  float v;
  if (mode == 0) v = fabsf(X[(size_t)(h*MLM+a)*MLM + t]);   // row sums
  else           v = fabsf(X[(size_t)(h*MLM+t)*MLM + a]);   // col sums
  float s = blockRedSum(v, red);
  if (t == 0) atomicMax((int*)(red_out + mode), __float_as_int(s));
}

__global__ void k_zinit(const float* __restrict__ X, float* __restrict__ Z,
                        const float* __restrict__ red){
  int idx = blockIdx.x*blockDim.x + threadIdx.x;
  if (idx >= HEADS*MLM*MLM) return;
  int h = idx >> 16, r = (idx >> 8) & 255, c = idx & 255;
  float inv = 1.f / (red[0] * red[1]);
  Z[idx] = X[(size_t)h*MLM*MLM + (size_t)c*MLM + r] * inv;
}

// ---------------- zero accumulators for attn3v -------------------------------
__global__ void k_zeroacc(float* oacc, float* rsum){
  int idx = blockIdx.x*blockDim.x + threadIdx.x;
  if (idx < HEADS*MLM*DH) oacc[idx] = 0.f;
  if (idx < HEADS*MLM) rsum[idx] = 0.f;
}

// ---- t3v partials: exp(ql@K^T) @ V over a 1280-key slice, split-TF32 mma ----
// grid (16, HEADS): bx&1 -> 128-row landmark half, bx>>1 -> key slice (8 slices).
__global__ __launch_bounds__(256, 1) void k_attn3v_mma(
    const float* __restrict__ qkv, const float* __restrict__ ql,
    float* __restrict__ oacc, float* __restrict__ rsum){
  extern __shared__ unsigned dyn3[];
  unsigned* Qh = dyn3;                 // [128][68]
  unsigned* Qlo = Qh + 128*68;         // [128][68]
  unsigned* Kh = Qlo + 128*68;         // [64][68]
  unsigned* Kl = Kh + 64*68;
  unsigned* Vh = Kl + 64*68;
  unsigned* Vl = Vh + 64*68;
  unsigned* Ph = Vl + 64*68;           // [128][68]
  unsigned* Pl = Ph + 128*68;

  const int h = blockIdx.y;
  const int m0 = (blockIdx.x & 1) * 128;
  const int slice = blockIdx.x >> 1;   // 0..7, 1280 keys each
  const int tid = threadIdx.x;
  const int w = tid >> 5, lane = tid & 31;
  const int g = lane >> 2, t = lane & 3;
  const int wm = w * 16;               // warp owns rows wm..wm+15

  // load Q (128x64) hi/lo
  #pragma unroll
  for (int l=0;l<8;l++){
    int s = tid + l*256;
    int row = s>>4, dq = (s&15)*4;
    float4 v = *(const float4*)(ql + (size_t)(h*MLM + m0 + row)*64 + dq);
    float av[4] = {v.x, v.y, v.z, v.w};
    #pragma unroll
    for (int q=0;q<4;q++){
      unsigned hi = f2tf(av[q]);
      Qh[row*68+dq+q]  = hi;
      Qlo[row*68+dq+q] = f2tf(av[q] - __uint_as_float(hi));
    }
  }

  float acc_o[8][4];
  #pragma unroll
  for (int j=0;j<8;j++)
    #pragma unroll
    for (int q=0;q<4;q++) acc_o[j][q]=0.f;
  float rs0 = 0.f, rs1 = 0.f;          // rowsums for rows wm+g, wm+g+8

  const int key_base = slice * 1280;
  for (int cn = 0; cn < 20; cn++){
    int key0 = key_base + cn*64;
    __syncthreads();                   // K/V smem free of prior readers
    // load K,V chunk (64x64 each) hi/lo
    #pragma unroll
    for (int l=0;l<4;l++){
      int s = tid + l*256;
      int row = s>>4, dq = (s&15)*4;
      const float* base = qkv + (size_t)(key0+row)*1536 + h*64 + dq;
      float4 kv = *(const float4*)(base + 512);
      float4 vv = *(const float4*)(base + 1024);
      float ka[4] = {kv.x, kv.y, kv.z, kv.w};
      float va[4] = {vv.x, vv.y, vv.z, vv.w};
      #pragma unroll
      for (int q=0;q<4;q++){
        unsigned hi = f2tf(ka[q]);
        Kh[row*68+dq+q] = hi;
        Kl[row*68+dq+q] = f2tf(ka[q] - __uint_as_float(hi));
        unsigned hv = f2tf(va[q]);
        Vh[row*68+dq+q] = hv;
        Vl[row*68+dq+q] = f2tf(va[q] - __uint_as_float(hv));
      }
    }
    __syncthreads();
    // S = Q @ K^T
    float sacc[8][4];
    #pragma unroll
    for (int nt=0;nt<8;nt++)
      #pragma unroll
      for (int q=0;q<4;q++) sacc[nt][q]=0.f;
    #pragma unroll
    for (int kk=0; kk<64; kk+=8){
      unsigned ah[4], al[4];
      ah[0]=Qh[(wm+g)*68+kk+t];    ah[1]=Qh[(wm+g+8)*68+kk+t];
      ah[2]=Qh[(wm+g)*68+kk+t+4];  ah[3]=Qh[(wm+g+8)*68+kk+t+4];
      al[0]=Qlo[(wm+g)*68+kk+t];   al[1]=Qlo[(wm+g+8)*68+kk+t];
      al[2]=Qlo[(wm+g)*68+kk+t+4]; al[3]=Qlo[(wm+g+8)*68+kk+t+4];
      #pragma unroll
      for (int nt=0; nt<8; nt++){
        int c = nt*8 + g;
        unsigned bh0 = Kh[c*68+kk+t], bh1 = Kh[c*68+kk+t+4];
        unsigned bl0 = Kl[c*68+kk+t], bl1 = Kl[c*68+kk+t+4];
        MMA_TF32(sacc[nt], ah, bh0, bh1);
        MMA_TF32(sacc[nt], al, bh0, bh1);
        MMA_TF32(sacc[nt], ah, bl0, bl1);
      }
    }
    // exp, rowsums, store P hi/lo
    #pragma unroll
    for (int nt=0; nt<8; nt++){
      float e0 = expf(sacc[nt][0]), e1 = expf(sacc[nt][1]);
      float e2 = expf(sacc[nt][2]), e3 = expf(sacc[nt][3]);
      rs0 += e0 + e1; rs1 += e2 + e3;
      int c0 = nt*8 + t*2;
      unsigned h0 = f2tf(e0), h1 = f2tf(e1), h2 = f2tf(e2), h3 = f2tf(e3);
      Ph[(wm+g)*68 + c0]     = h0;
      Ph[(wm+g)*68 + c0+1]   = h1;
      Ph[(wm+g+8)*68 + c0]   = h2;
      Ph[(wm+g+8)*68 + c0+1] = h3;
      Pl[(wm+g)*68 + c0]     = f2tf(e0 - __uint_as_float(h0));
      Pl[(wm+g)*68 + c0+1]   = f2tf(e1 - __uint_as_float(h1));
      Pl[(wm+g+8)*68 + c0]   = f2tf(e2 - __uint_as_float(h2));
      Pl[(wm+g+8)*68 + c0+1] = f2tf(e3 - __uint_as_float(h3));
    }
    __syncwarp();                      // own-warp P rows only
    // O += P @ V
    #pragma unroll
    for (int kk=0; kk<64; kk+=8){
      unsigned ah[4], al[4];
      ah[0]=Ph[(wm+g)*68+kk+t];    ah[1]=Ph[(wm+g+8)*68+kk+t];
      ah[2]=Ph[(wm+g)*68+kk+t+4];  ah[3]=Ph[(wm+g+8)*68+kk+t+4];
      al[0]=Pl[(wm+g)*68+kk+t];    al[1]=Pl[(wm+g+8)*68+kk+t];
      al[2]=Pl[(wm+g)*68+kk+t+4];  al[3]=Pl[(wm+g+8)*68+kk+t+4];
      #pragma unroll
      for (int nt=0; nt<8; nt++){
        int c = nt*8 + g;
        unsigned bh0 = Vh[(kk+t)*68+c], bh1 = Vh[(kk+t+4)*68+c];
        unsigned bl0 = Vl[(kk+t)*68+c], bl1 = Vl[(kk+t+4)*68+c];
        MMA_TF32(acc_o[nt], ah, bh0, bh1);
        MMA_TF32(acc_o[nt], al, bh0, bh1);
        MMA_TF32(acc_o[nt], ah, bl0, bl1);
      }
    }
  }
  // reduce rowsums across the 4 t-lanes sharing each g
  rs0 += __shfl_xor_sync(0xffffffffu, rs0, 1);
  rs0 += __shfl_xor_sync(0xffffffffu, rs0, 2);
  rs1 += __shfl_xor_sync(0xffffffffu, rs1, 1);
  rs1 += __shfl_xor_sync(0xffffffffu, rs1, 2);
  if (t == 0){
    atomicAdd(&rsum[h*MLM + m0 + wm + g], rs0);
    atomicAdd(&rsum[h*MLM + m0 + wm + g + 8], rs1);
  }
  // emit O partials
  #pragma unroll
  for (int nt=0; nt<8; nt++){
    #pragma unroll
    for (int q=0;q<4;q++){
      int row = m0 + wm + g + (q>>1)*8;
      int col = nt*8 + t*2 + (q&1);
      atomicAdd(&oacc[(size_t)(h*MLM + row)*64 + col], acc_o[nt][q]);
    }
  }
}

__global__ void k_t3fin(const float* __restrict__ oacc, const float* __restrict__ rsum,
                        float* __restrict__ t3v){
  int idx = blockIdx.x*blockDim.x + threadIdx.x;
  if (idx >= HEADS*MLM*DH) return;
  t3v[idx] = oacc[idx] / rsum[idx >> 6];
}

// ---- attn1W: softmax(q@kl^T) @ W, split-TF32 mma, flash-style ---------------
// grid (NPAD/128, HEADS). 128 tokens/block; 4 chunks of 64 landmarks.
// One block covers all 256 landmarks -> rowsums in registers, no atomics.
__global__ __launch_bounds__(256, 1) void k_attn1W_mma(
    const float* __restrict__ qkv, const float* __restrict__ kl,
    const float* __restrict__ W, float* __restrict__ ao){
  extern __shared__ unsigned dyn1[];
  unsigned* Qh = dyn1;                 // [128][68]
  unsigned* Qlo = Qh + 128*68;         // [128][68]
  unsigned* Kh = Qlo + 128*68;         // [64][68] (kl chunk)
  unsigned* Kl = Kh + 64*68;
  unsigned* Vh = Kl + 64*68;           // [64][68] (W chunk)
  unsigned* Vl = Vh + 64*68;
  unsigned* Ph = Vl + 64*68;           // [128][68]
  unsigned* Pl = Ph + 128*68;

  const int h = blockIdx.y;
  const int t0 = blockIdx.x * 128;
  const int tid = threadIdx.x;
  const int w = tid >> 5, lane = tid & 31;
  const int g = lane >> 2, t = lane & 3;
  const int wm = w * 16;

  // load Q (128 tokens x 64 dims), scaled by 0.125, hi/lo
  #pragma unroll
  for (int l=0;l<8;l++){
    int s = tid + l*256;
    int row = s>>4, dq = (s&15)*4;
    float4 v = *(const float4*)(qkv + (size_t)(t0+row)*1536 + h*64 + dq);
    float av[4] = {v.x*0.125f, v.y*0.125f, v.z*0.125f, v.w*0.125f};
    #pragma unroll
    for (int q=0;q<4;q++){
      unsigned hi = f2tf(av[q]);
      Qh[row*68+dq+q]  = hi;
      Qlo[row*68+dq+q] = f2tf(av[q] - __uint_as_float(hi));
    }
  }

  float acc_o[8][4];
  #pragma unroll
  for (int j=0;j<8;j++)
    #pragma unroll
    for (int q=0;q<4;q++) acc_o[j][q]=0.f;
  float rs0 = 0.f, rs1 = 0.f;

  for (int cn = 0; cn < 4; cn++){
    int m0 = cn*64;                    // landmark chunk base
    __syncthreads();
    // load KL chunk + W chunk (64x64 each) hi/lo
    #pragma unroll
    for (int l=0;l<4;l++){
      int s = tid + l*256;
      int row = s>>4, dq = (s&15)*4;
      float4 kv = *(const float4*)(kl + (size_t)(h*MLM + m0 + row)*64 + dq);
      float4 vv = *(const float4*)(W  + (size_t)(h*MLM + m0 + row)*64 + dq);
      float ka[4] = {kv.x, kv.y, kv.z, kv.w};
      float va[4] = {vv.x, vv.y, vv.z, vv.w};
      #pragma unroll
      for (int q=0;q<4;q++){
        unsigned hi = f2tf(ka[q]);
        Kh[row*68+dq+q] = hi;
        Kl[row*68+dq+q] = f2tf(ka[q] - __uint_as_float(hi));
        unsigned hv = f2tf(va[q]);
        Vh[row*68+dq+q] = hv;
        Vl[row*68+dq+q] = f2tf(va[q] - __uint_as_float(hv));
      }
    }
    __syncthreads();
    // S = Q @ KL^T
    float sacc[8][4];
    #pragma unroll
    for (int nt=0;nt<8;nt++)
      #pragma unroll
      for (int q=0;q<4;q++) sacc[nt][q]=0.f;
    #pragma unroll
    for (int kk=0; kk<64; kk+=8){
      unsigned ah[4], al[4];
      ah[0]=Qh[(wm+g)*68+kk+t];    ah[1]=Qh[(wm+g+8)*68+kk+t];
      ah[2]=Qh[(wm+g)*68+kk+t+4];  ah[3]=Qh[(wm+g+8)*68+kk+t+4];
      al[0]=Qlo[(wm+g)*68+kk+t];   al[1]=Qlo[(wm+g+8)*68+kk+t];
      al[2]=Qlo[(wm+g)*68+kk+t+4]; al[3]=Qlo[(wm+g+8)*68+kk+t+4];
      #pragma unroll
      for (int nt=0; nt<8; nt++){
        int c = nt*8 + g;
        unsigned bh0 = Kh[c*68+kk+t], bh1 = Kh[c*68+kk+t+4];
        unsigned bl0 = Kl[c*68+kk+t], bl1 = Kl[c*68+kk+t+4];
        MMA_TF32(sacc[nt], ah, bh0, bh1);
        MMA_TF32(sacc[nt], al, bh0, bh1);
        MMA_TF32(sacc[nt], ah, bl0, bl1);
      }
    }
    // exp, rowsums, store P hi/lo
    #pragma unroll
    for (int nt=0; nt<8; nt++){
      float e0 = expf(sacc[nt][0]), e1 = expf(sacc[nt][1]);
      float e2 = expf(sacc[nt][2]), e3 = expf(sacc[nt][3]);
      rs0 += e0 + e1; rs1 += e2 + e3;
      int c0 = nt*8 + t*2;
      unsigned h0 = f2tf(e0), h1 = f2tf(e1), h2 = f2tf(e2), h3 = f2tf(e3);
      Ph[(wm+g)*68 + c0]     = h0;
      Ph[(wm+g)*68 + c0+1]   = h1;
      Ph[(wm+g+8)*68 + c0]   = h2;
      Ph[(wm+g+8)*68 + c0+1] = h3;
      Pl[(wm+g)*68 + c0]     = f2tf(e0 - __uint_as_float(h0));
      Pl[(wm+g)*68 + c0+1]   = f2tf(e1 - __uint_as_float(h1));
      Pl[(wm+g+8)*68 + c0]   = f2tf(e2 - __uint_as_float(h2));
      Pl[(wm+g+8)*68 + c0+1] = f2tf(e3 - __uint_as_float(h3));
    }
    __syncwarp();
    // O += P @ W_chunk
    #pragma unroll
    for (int kk=0; kk<64; kk+=8){
      unsigned ah[4], al[4];
      ah[0]=Ph[(wm+g)*68+kk+t];    ah[1]=Ph[(wm+g+8)*68+kk+t];
      ah[2]=Ph[(wm+g)*68+kk+t+4];  ah[3]=Ph[(wm+g+8)*68+kk+t+4];
      al[0]=Pl[(wm+g)*68+kk+t];    al[1]=Pl[(wm+g+8)*68+kk+t];
      al[2]=Pl[(wm+g)*68+kk+t+4];  al[3]=Pl[(wm+g+8)*68+kk+t+4];
      #pragma unroll
      for (int nt=0; nt<8; nt++){
        int c = nt*8 + g;
        unsigned bh0 = Vh[(kk+t)*68+c], bh1 = Vh[(kk+t+4)*68+c];
        unsigned bl0 = Vl[(kk+t)*68+c], bl1 = Vl[(kk+t+4)*68+c];
        MMA_TF32(acc_o[nt], ah, bh0, bh1);
        MMA_TF32(acc_o[nt], al, bh0, bh1);
        MMA_TF32(acc_o[nt], ah, bl0, bl1);
      }
    }
  }
  // full rowsums: reduce across the 4 t-lanes of each g (all lanes get result)
  rs0 += __shfl_xor_sync(0xffffffffu, rs0, 1);
  rs0 += __shfl_xor_sync(0xffffffffu, rs0, 2);
  rs1 += __shfl_xor_sync(0xffffffffu, rs1, 1);
  rs1 += __shfl_xor_sync(0xffffffffu, rs1, 2);
  float inv0 = 1.f / rs0, inv1 = 1.f / rs1;
  // write normalized output
  #pragma unroll
  for (int nt=0; nt<8; nt++){
    #pragma unroll
    for (int q=0;q<4;q++){
      int rl = wm + g + (q>>1)*8;
      int col = nt*8 + t*2 + (q&1);
      float inv = (q>>1) ? inv1 : inv0;
      ao[(size_t)(t0+rl)*DIM + h*64 + col] = acc_o[nt][q] * inv;
    }
  }
}

// ---------------- residual depthwise conv (kernel 33 along sequence) ---------
__global__ void k_convres(const float* __restrict__ qkv, const float* __restrict__ rw,
                          float* __restrict__ ao){
  int idx = blockIdx.x*blockDim.x + threadIdx.x;
  if (idx >= NPAD*DIM) return;
  int n = idx >> 9, c = idx & 511;
  int h = c >> 6;
  float acc = ao[idx];
  #pragma unroll
  for (int t=0;t<33;t++){
    int s = n + t - 16;
    if (s >= 0 && s < NPAD)
      acc += rw[h*33+t] * qkv[(size_t)s*1536 + 1024 + c];
  }
  ao[idx] = acc;
}

// ---------------- PPEG -------------------------------------------------------
__global__ void k_cls(const float* __restrict__ hin, float* __restrict__ hout){
  int c = blockIdx.x*blockDim.x + threadIdx.x;
  if (c < DIM) hout[c] = hin[c];
}

__global__ __launch_bounds__(128) void k_ppeg(const float* __restrict__ hin,
    const float* __restrict__ w7, const float* __restrict__ b7,
    const float* __restrict__ w5, const float* __restrict__ b5,
    const float* __restrict__ w3, const float* __restrict__ b3,
    float* __restrict__ hout){
  int pos = blockIdx.x;                 // 0..9999
  int c = blockIdx.y*128 + threadIdx.x;
  int i = pos / HH, j = pos % HH;
  float acc = hin[(size_t)(1+pos)*DIM + c] + b7[c] + b5[c] + b3[c];
  #pragma unroll
  for (int a=0;a<7;a++){
    int ii = i + a - 3;
    if (ii < 0 || ii >= HH) continue;
    #pragma unroll
    for (int bb=0;bb<7;bb++){
      int jj = j + bb - 3;
      if (jj < 0 || jj >= HH) continue;
      acc += hin[(size_t)(1+ii*HH+jj)*DIM + c] * w7[(size_t)c*49 + a*7 + bb];
    }
  }
  #pragma unroll
  for (int a=0;a<5;a++){
    int ii = i + a - 2;
    if (ii < 0 || ii >= HH) continue;
    #pragma unroll
    for (int bb=0;bb<5;bb++){
      int jj = j + bb - 2;
      if (jj < 0 || jj >= HH) continue;
      acc += hin[(size_t)(1+ii*HH+jj)*DIM + c] * w5[(size_t)c*25 + a*5 + bb];
    }
  }
  #pragma unroll
  for (int a=0;a<3;a++){
    int ii = i + a - 1;
    if (ii < 0 || ii >= HH) continue;
    #pragma unroll
    for (int bb=0;bb<3;bb++){
      int jj = j + bb - 1;
      if (jj < 0 || jj >= HH) continue;
      acc += hin[(size_t)(1+ii*HH+jj)*DIM + c] * w3[(size_t)c*9 + a*3 + bb];
    }
  }
  hout[(size_t)(1+pos)*DIM + c] = acc;
}

// ---------------- heads ------------------------------------------------------
__global__ void k_heads(const float* __restrict__ hn,
    const float* __restrict__ fcw, const float* __restrict__ fcb,
    const float* __restrict__ pcw, const float* __restrict__ pcb,
    float* __restrict__ out){
  int warp = (blockIdx.x*blockDim.x + threadIdx.x) >> 5;
  int lane = threadIdx.x & 31;
  if (warp >= NTOK) return;
  const float* hr = hn + (size_t)warp*DIM;
  const float* Wm = (warp == 0) ? fcw : pcw;
  float d0=0.f, d1=0.f;
  for (int k=lane;k<DIM;k+=32){
    float v = hr[k];
    d0 += v*Wm[2*k];
    d1 += v*Wm[2*k+1];
  }
  d0 = warpRedSum(d0);
  d1 = warpRedSum(d1);
  if (lane == 0){
    if (warp == 0){
      out[0] = d0 + fcb[0];
      out[1] = d1 + fcb[1];
    } else {
      float l0 = d0 + pcb[0], l1 = d1 + pcb[1];
      int r = warp - 1;
      out[2 + 2*r]     = l0;
      out[2 + 2*r + 1] = l1;
      float m = fmaxf(l0,l1);
      float e0 = expf(l0-m), e1 = expf(l1-m);
      float inv = 1.f/(e0+e1);
      out[2 + 2*N0 + 2*r]     = e0*inv;
      out[2 + 2*N0 + 2*r + 1] = e1*inv;
    }
  }
}

// ---------------- host side --------------------------------------------------
static void run_attn_block(const float* ln_w, const float* ln_b, const float* qkv_w,
    const float* out_w, const float* out_b, const float* res_w,
    float* h, float* S){
  float* XP  = S + O_XP;
  float* QKV = S + O_QKV;
  float* AO  = S + O_AO;
  float* QL  = S + O_QL;
  float* KL  = S + O_KL;
  float* X   = S + O_X;
  float* Z0  = S + O_Z0;
  float* Z1  = S + O_Z1;
  float* TA  = S + O_TA;   // attn3v oacc
  float* TU  = S + O_TU;   // attn3v rsum
  float* TT  = S + O_TT;
  float* T3  = S + O_T3;
  float* Wb  = S + O_W;
  float* RED = S + O_RED;

  k_lnpad<<<NPAD, 256>>>(h, XP, ln_w, ln_b, PADR);
  k_mma_gemm<<<dim3(1536/128, NPAD/128), 256>>>(XP, qkv_w, nullptr, nullptr, QKV,
                                                NPAD, 1536, DIM);
  k_land<<<dim3(MLM, HEADS), 64>>>(QKV, QL, KL);
  k_attn2<<<dim3(MLM, HEADS), 256>>>(QL, KL, X);
  k_zero2<<<1, 32>>>(RED);
  k_absmax<<<dim3(MLM, HEADS), 256>>>(X, RED, 0);
  k_absmax<<<dim3(MLM, HEADS), 256>>>(X, RED, 1);
  k_zinit<<<(HEADS*MLM*MLM + 255)/256, 256>>>(X, Z0, RED);

  const long long sM = (long long)MLM*MLM;
  float* zc = Z0; float* zn = Z1;
  for (int it=0; it<6; it++){
    k_bgemm64<<<dim3(4,4,HEADS), 256>>>(X,  zc, TA, MLM, sM, sM, sM, 0.f,  1.f, 1.f);
    k_bgemm64<<<dim3(4,4,HEADS), 256>>>(TA, TA, TU, MLM, sM, sM, sM, 7.f, -1.f, 1.f);
    k_bgemm64<<<dim3(4,4,HEADS), 256>>>(TA, TU, TT, MLM, sM, sM, sM, 15.f,-1.f, 1.f);
    k_bgemm64<<<dim3(4,4,HEADS), 256>>>(zc, TT, zn, MLM, sM, sM, sM, 13.f,-1.f, 0.25f);
    float* tmp = zc; zc = zn; zn = tmp;
  }

  // attn3 @ v via split-TF32 tensor cores, key-sliced partials
  k_zeroacc<<<(HEADS*MLM*DH + 255)/256, 256>>>(TA, TU);
  k_attn3v_mma<<<dim3(16, HEADS), 256, ATT3_SMEM>>>(QKV, QL, TA, TU);
  k_t3fin<<<(HEADS*MLM*DH + 255)/256, 256>>>(TA, TU, T3);

  const long long sS = (long long)MLM*DH;
  k_bgemm64<<<dim3(1,4,HEADS), 256>>>(zc, T3, Wb, DH, sM, sS, sS, 0.f, 1.f, 1.f);
  k_attn1W_mma<<<dim3(NPAD/128, HEADS), 256, ATT3_SMEM>>>(QKV, KL, Wb, AO);
  k_convres<<<(NPAD*DIM + 255)/256, 256>>>(QKV, res_w, AO);
  // out proj + residual into h (rows PADR.. of AO map to h rows 0..)
  k_mma_gemm<<<dim3(DIM/128, (NTOK+127)/128), 256>>>(AO + (size_t)PADR*DIM, out_w,
                                                     out_b, h, h, NTOK, DIM, DIM);
}

extern "C" void kernel_launch(void* const* d_in, const int* in_sizes, int n_in,
                              void* d_out, int out_size){
  const float* x      = (const float*)d_in[0];
  const float* cls    = (const float*)d_in[1];
  const float* ln1_w  = (const float*)d_in[2];
  const float* ln1_b  = (const float*)d_in[3];
  const float* qkv1_w = (const float*)d_in[4];
  const float* out1_w = (const float*)d_in[5];
  const float* out1_b = (const float*)d_in[6];
  const float* res1_w = (const float*)d_in[7];
  const float* p7_w   = (const float*)d_in[8];
  const float* p7_b   = (const float*)d_in[9];
  const float* p5_w   = (const float*)d_in[10];
  const float* p5_b   = (const float*)d_in[11];
  const float* p3_w   = (const float*)d_in[12];
  const float* p3_b   = (const float*)d_in[13];
  const float* ln2_w  = (const float*)d_in[14];
  const float* ln2_b  = (const float*)d_in[15];
  const float* qkv2_w = (const float*)d_in[16];
  const float* out2_w = (const float*)d_in[17];
  const float* out2_b = (const float*)d_in[18];
  const float* res2_w = (const float*)d_in[19];
  const float* norm_w = (const float*)d_in[20];
  const float* norm_b = (const float*)d_in[21];
  const float* fc2_w  = (const float*)d_in[22];
  const float* fc2_b  = (const float*)d_in[23];
  const float* pc_w   = (const float*)d_in[24];
  const float* pc_b   = (const float*)d_in[25];

  float* S = nullptr;
  cudaGetSymbolAddress((void**)&S, g_scratch);
  cudaFuncSetAttribute(k_attn3v_mma, cudaFuncAttributeMaxDynamicSharedMemorySize,
                       ATT3_SMEM);
  cudaFuncSetAttribute(k_attn1W_mma, cudaFuncAttributeMaxDynamicSharedMemorySize,
                       ATT3_SMEM);

  float* H0 = S + O_H0;
  float* H1 = S + O_H1;
  float* XP = S + O_XP;

  k_build<<<(NTOK*DIM + 255)/256, 256>>>(x, cls, H0);

  run_attn_block(ln1_w, ln1_b, qkv1_w, out1_w, out1_b, res1_w, H0, S);

  k_cls<<<2, 256>>>(H0, H1);
  k_ppeg<<<dim3(N0, DIM/128), 128>>>(H0, p7_w, p7_b, p5_w, p5_b, p3_w, p3_b, H1);

  run_attn_block(ln2_w, ln2_b, qkv2_w, out2_w, out2_b, res2_w, H1, S);

  k_lnpad<<<NTOK, 256>>>(H1, XP, norm_w, norm_b, 0);
  k_heads<<<(NTOK + 7)/8, 256>>>(XP, fc2_w, fc2_b, pc_w, pc_b, (float*)d_out);
}

// round 11
// speedup vs baseline: 2.1945x; 1.0372x over previous
#include <cuda_runtime.h>
#include <math.h>

#define N0    10000
#define NTOK  10001
#define DIM   512
#define NPAD  10240
#define PADR  239
#define HEADS 8
#define DH    64
#define MLM   256
#define HH    100

// ---------------- scratch (single device global, no allocations) -------------
constexpr size_t O_H0 = 0;                                  // NTOK*DIM
constexpr size_t O_H1 = O_H0 + (size_t)NTOK*DIM;
constexpr size_t O_XP = O_H1 + (size_t)NTOK*DIM;            // NPAD*DIM (LN+pad; final hn)
constexpr size_t O_QKV= O_XP + (size_t)NPAD*DIM;            // NPAD*1536
constexpr size_t O_AO = O_QKV+ (size_t)NPAD*3*DIM;          // NPAD*DIM
constexpr size_t O_QL = O_AO + (size_t)NPAD*DIM;
constexpr size_t O_KL = O_QL + (size_t)HEADS*MLM*DH;
constexpr size_t O_X  = O_KL + (size_t)HEADS*MLM*DH;        // attn2
constexpr size_t O_Z0 = O_X  + (size_t)HEADS*MLM*MLM;
constexpr size_t O_Z1 = O_Z0 + (size_t)HEADS*MLM*MLM;
constexpr size_t O_TA = O_Z1 + (size_t)HEADS*MLM*MLM;       // doubles as attn3v oacc
constexpr size_t O_TU = O_TA + (size_t)HEADS*MLM*MLM;       // doubles as attn3v rsum
constexpr size_t O_TT = O_TU + (size_t)HEADS*MLM*MLM;
constexpr size_t O_T3 = O_TT + (size_t)HEADS*MLM*MLM;       // attn3@v : H*256*64
constexpr size_t O_W  = O_T3 + (size_t)HEADS*MLM*DH;        // Z@(attn3@v)
constexpr size_t O_RED= O_W  + (size_t)HEADS*MLM*DH;
constexpr size_t SCRATCH_TOTAL = O_RED + 8;

__device__ float g_scratch[SCRATCH_TOTAL];

// smem layout (both mma-attention kernels):
// Qh,Ql(128x68 ea), Bh0,Bl0,Bh1,Bl1(64x68 ea), Ph,Pl(128x68 ea)
#define ATT3_SMEM ((4*(128*68) + 4*(64*68)) * 4)
// double-buffered GEMM smem: 2 x A(128x36) + 2 x B(32x136)
#define GEMM_SMEM ((2*128*36 + 2*32*136) * 4)

// ---------------- helpers ----------------------------------------------------
__device__ __forceinline__ unsigned f2tf(float x){
  unsigned u; asm("cvt.rna.tf32.f32 %0, %1;" : "=r"(u) : "f"(x)); return u;
}

#define MMA_TF32(d, a, b0v, b1v) \
  asm("mma.sync.aligned.m16n8k8.row.col.f32.tf32.tf32.f32 " \
      "{%0,%1,%2,%3}, {%4,%5,%6,%7}, {%8,%9}, {%0,%1,%2,%3};\n" \
      : "+f"(d[0]),"+f"(d[1]),"+f"(d[2]),"+f"(d[3]) \
      : "r"(a[0]),"r"(a[1]),"r"(a[2]),"r"(a[3]),"r"(b0v),"r"(b1v))

__device__ __forceinline__ float warpRedSum(float v){
  #pragma unroll
  for (int s=16;s;s>>=1) v += __shfl_xor_sync(0xffffffffu, v, s);
  return v;
}
__device__ __forceinline__ float warpRedMax(float v){
  #pragma unroll
  for (int s=16;s;s>>=1) v = fmaxf(v, __shfl_xor_sync(0xffffffffu, v, s));
  return v;
}
__device__ __forceinline__ float blockRedSum(float v, float* red){
  int lane=threadIdx.x&31, wid=threadIdx.x>>5;
  v = warpRedSum(v);
  if (lane==0) red[wid]=v;
  __syncthreads();
  if (wid==0){
    float t = (lane<8)? red[lane] : 0.f;
    t = warpRedSum(t);
    if (lane==0) red[0]=t;
  }
  __syncthreads();
  float r = red[0];
  __syncthreads();
  return r;
}
__device__ __forceinline__ float blockRedMax(float v, float* red){
  int lane=threadIdx.x&31, wid=threadIdx.x>>5;
  v = warpRedMax(v);
  if (lane==0) red[wid]=v;
  __syncthreads();
  if (wid==0){
    float t = (lane<8)? red[lane] : -1e30f;
    t = warpRedMax(t);
    if (lane==0) red[0]=t;
  }
  __syncthreads();
  float r = red[0];
  __syncthreads();
  return r;
}

// ---------------- build h0 ---------------------------------------------------
__global__ void k_build(const float* __restrict__ x, const float* __restrict__ cls,
                        float* __restrict__ h){
  int idx = blockIdx.x*blockDim.x + threadIdx.x;
  if (idx >= NTOK*DIM) return;
  int r = idx >> 9, c = idx & 511;
  h[idx] = (r == 0) ? cls[c] : x[(size_t)(r-1)*DIM + c];
}

// ---------------- layernorm (+ optional front zero-pad) ----------------------
__global__ __launch_bounds__(256) void k_lnpad(const float* __restrict__ src,
    float* __restrict__ dst, const float* __restrict__ w, const float* __restrict__ b,
    int pad){
  __shared__ float red[32];
  int r = blockIdx.x, tid = threadIdx.x;
  if (r < pad){
    dst[(size_t)r*DIM + tid] = 0.f;
    dst[(size_t)r*DIM + tid + 256] = 0.f;
    return;
  }
  const float* row = src + (size_t)(r-pad)*DIM;
  float v0 = row[tid], v1 = row[tid+256];
  float mu = blockRedSum(v0+v1, red) * (1.f/DIM);
  float d0 = v0-mu, d1 = v1-mu;
  float var = blockRedSum(d0*d0 + d1*d1, red) * (1.f/DIM);
  float rs = 1.f / sqrtf(var + 1e-5f);
  dst[(size_t)r*DIM + tid]       = d0*rs*w[tid]     + b[tid];
  dst[(size_t)r*DIM + tid + 256] = d1*rs*w[tid+256] + b[tid+256];
}

// ------ TF32 tensor-core GEMM, double-buffered: C = A@B [+bias][+Cres] -------
// 128x128 block tile, BK=32, 256 threads (8 warps 4x2), warp tile 32x64.
// Per-thread K-summation order identical to the single-buffered BK=16 version
// (8-wide MMA k-chunks, ascending) -> bit-identical results.
__global__ __launch_bounds__(256) void k_mma_gemm(
    const float* __restrict__ A, const float* __restrict__ B,
    const float* __restrict__ bias, const float* __restrict__ Cres,
    float* __restrict__ C, int M, int N, int K){
  extern __shared__ unsigned gsm[];
  unsigned* AsBase = gsm;                 // 2 stages of 128*36 ([m][k], pad 4)
  unsigned* BsBase = gsm + 2*128*36;      // 2 stages of 32*136 ([k][n], pad 8)
  const int bm = blockIdx.y * 128;
  const int bn = blockIdx.x * 128;
  const int tid = threadIdx.x;
  const int w = tid >> 5, lane = tid & 31;
  const int wm = (w & 3) * 32, wn = (w >> 2) * 64;
  const int g = lane >> 2, t = lane & 3;

  float acc[2][8][4];
  #pragma unroll
  for (int i=0;i<2;i++)
    #pragma unroll
    for (int j=0;j<8;j++)
      #pragma unroll
      for (int q=0;q<4;q++) acc[i][j][q]=0.f;

  float4 pa[4], pb[4];
  // prefetch tile 0 into registers
  #pragma unroll
  for (int i=0;i<4;i++){
    int s = tid + i*256;
    int row = s>>3, kq = (s&7)*4;
    float4 v = make_float4(0.f,0.f,0.f,0.f);
    if (bm+row < M) v = *(const float4*)(A + (size_t)(bm+row)*K + kq);
    pa[i]=v;
    int rowb = s>>5, nq = (s&31)*4;
    float4 vb = make_float4(0.f,0.f,0.f,0.f);
    if (bn+nq < N) vb = *(const float4*)(B + (size_t)rowb*N + bn + nq);
    pb[i]=vb;
  }
  // store tile 0 to stage 0
  {
    unsigned* As_ = AsBase;
    unsigned* Bs_ = BsBase;
    #pragma unroll
    for (int i=0;i<4;i++){
      int s = tid + i*256;
      int row = s>>3, kq = (s&7)*4;
      uint4 u; u.x=f2tf(pa[i].x); u.y=f2tf(pa[i].y); u.z=f2tf(pa[i].z); u.w=f2tf(pa[i].w);
      *(uint4*)&As_[row*36 + kq] = u;
      int rowb = s>>5, nq = (s&31)*4;
      uint4 ub; ub.x=f2tf(pb[i].x); ub.y=f2tf(pb[i].y); ub.z=f2tf(pb[i].z); ub.w=f2tf(pb[i].w);
      *(uint4*)&Bs_[rowb*136 + nq] = ub;
    }
  }
  __syncthreads();

  int cur = 0;
  for (int k0 = 0; k0 < K; k0 += 32){
    // prefetch next tile (LDG latency overlaps compute)
    if (k0 + 32 < K){
      #pragma unroll
      for (int i=0;i<4;i++){
        int s = tid + i*256;
        int row = s>>3, kq = (s&7)*4;
        float4 v = make_float4(0.f,0.f,0.f,0.f);
        if (bm+row < M) v = *(const float4*)(A + (size_t)(bm+row)*K + k0+32 + kq);
        pa[i]=v;
        int rowb = s>>5, nq = (s&31)*4;
        float4 vb = make_float4(0.f,0.f,0.f,0.f);
        if (bn+nq < N) vb = *(const float4*)(B + (size_t)(k0+32+rowb)*N + bn + nq);
        pb[i]=vb;
      }
    }
    // compute on stage cur
    {
      unsigned* As_ = AsBase + cur*(128*36);
      unsigned* Bs_ = BsBase + cur*(32*136);
      #pragma unroll
      for (int kk=0; kk<32; kk+=8){
        unsigned af[2][4];
        #pragma unroll
        for (int mt=0; mt<2; mt++){
          int r = wm + mt*16 + g;
          af[mt][0]=As_[r*36 + kk+t];       af[mt][1]=As_[(r+8)*36 + kk+t];
          af[mt][2]=As_[r*36 + kk+t+4];     af[mt][3]=As_[(r+8)*36 + kk+t+4];
        }
        #pragma unroll
        for (int nt=0; nt<8; nt++){
          int c = wn + nt*8 + g;
          unsigned b0 = Bs_[(kk+t)*136 + c], b1 = Bs_[(kk+t+4)*136 + c];
          MMA_TF32(acc[0][nt], af[0], b0, b1);
          MMA_TF32(acc[1][nt], af[1], b0, b1);
        }
      }
    }
    // store prefetched tile to alternate stage
    if (k0 + 32 < K){
      unsigned* As_ = AsBase + (cur^1)*(128*36);
      unsigned* Bs_ = BsBase + (cur^1)*(32*136);
      #pragma unroll
      for (int i=0;i<4;i++){
        int s = tid + i*256;
        int row = s>>3, kq = (s&7)*4;
        uint4 u; u.x=f2tf(pa[i].x); u.y=f2tf(pa[i].y); u.z=f2tf(pa[i].z); u.w=f2tf(pa[i].w);
        *(uint4*)&As_[row*36 + kq] = u;
        int rowb = s>>5, nq = (s&31)*4;
        uint4 ub; ub.x=f2tf(pb[i].x); ub.y=f2tf(pb[i].y); ub.z=f2tf(pb[i].z); ub.w=f2tf(pb[i].w);
        *(uint4*)&Bs_[rowb*136 + nq] = ub;
      }
    }
    __syncthreads();
    cur ^= 1;
  }
  // epilogue
  #pragma unroll
  for (int mt=0; mt<2; mt++){
    #pragma unroll
    for (int nt=0; nt<8; nt++){
      int r0 = bm + wm + mt*16 + g;
      int c0 = bn + wn + nt*8 + t*2;
      #pragma unroll
      for (int q=0;q<4;q++){
        int row = r0 + (q>>1)*8;
        int col = c0 + (q&1);
        if (row < M && col < N){
          float v = acc[mt][nt][q];
          if (bias) v += bias[col];
          if (Cres) v += Cres[(size_t)row*N + col];
          C[(size_t)row*N + col] = v;
        }
      }
    }
  }
}

// ----- batched TF32 gemm, 64x64 tile: C[z] = scale*A[z]@(bI*I + bS*B[z]) -----
// M=K=256 fixed; N in {256,64}. grid (N/64, 4, nbatch), 256 threads.
__global__ __launch_bounds__(256) void k_bgemm64(
    const float* __restrict__ A, const float* __restrict__ B, float* __restrict__ C,
    int N, long long sA, long long sB, long long sC,
    float bI, float bS, float scale){
  __shared__ unsigned As[64][20];    // [m][k] + pad
  __shared__ unsigned Bs[16][68];    // [k][n] + pad
  const float* Ah = A + blockIdx.z * sA;
  const float* Bh = B + blockIdx.z * sB;
  float* Ch = C + blockIdx.z * sC;
  const int K = 256;
  const int bm = blockIdx.y * 64;
  const int bn = blockIdx.x * 64;
  const int tid = threadIdx.x;
  const int w = tid >> 5, lane = tid & 31;
  const int wm = (w & 3) * 16, wn = (w >> 2) * 32;
  const int g = lane >> 2, t = lane & 3;

  float acc[4][4];
  #pragma unroll
  for (int j=0;j<4;j++)
    #pragma unroll
    for (int q=0;q<4;q++) acc[j][q]=0.f;

  for (int k0 = 0; k0 < K; k0 += 16){
    {
      int row = tid >> 2, kq = (tid & 3) * 4;
      float4 v = *(const float4*)(Ah + (size_t)(bm+row)*K + k0 + kq);
      As[row][kq+0]=f2tf(v.x); As[row][kq+1]=f2tf(v.y);
      As[row][kq+2]=f2tf(v.z); As[row][kq+3]=f2tf(v.w);
    }
    {
      int rowb = tid >> 4, cq = (tid & 15) * 4;
      float4 vb = *(const float4*)(Bh + (size_t)(k0+rowb)*N + bn + cq);
      int gk = k0 + rowb;
      float bv[4] = {vb.x, vb.y, vb.z, vb.w};
      #pragma unroll
      for (int q=0;q<4;q++){
        float vv = bS * bv[q];
        if (gk == bn + cq + q) vv += bI;
        Bs[rowb][cq+q] = f2tf(vv);
      }
    }
    __syncthreads();
    #pragma unroll
    for (int kk=0; kk<16; kk+=8){
      unsigned af[4];
      af[0]=As[wm+g][kk+t];   af[1]=As[wm+g+8][kk+t];
      af[2]=As[wm+g][kk+t+4]; af[3]=As[wm+g+8][kk+t+4];
      #pragma unroll
      for (int nt=0; nt<4; nt++){
        int c = wn + nt*8 + g;
        unsigned b0 = Bs[kk+t][c], b1 = Bs[kk+t+4][c];
        MMA_TF32(acc[nt], af, b0, b1);
      }
    }
    __syncthreads();
  }
  #pragma unroll
  for (int nt=0; nt<4; nt++){
    #pragma unroll
    for (int q=0;q<4;q++){
      int row = bm + wm + g + (q>>1)*8;
      int col = bn + wn + nt*8 + t*2 + (q&1);
      Ch[(size_t)row*N + col] = scale * acc[nt][q];
    }
  }
}

// ---------------- landmarks --------------------------------------------------
__global__ __launch_bounds__(64) void k_land(const float* __restrict__ qkv,
    float* __restrict__ ql, float* __restrict__ kl){
  int m = blockIdx.x, h = blockIdx.y, d = threadIdx.x;
  float sq = 0.f, sk = 0.f;
  #pragma unroll 8
  for (int j=0;j<40;j++){
    size_t base = (size_t)(m*40+j)*1536 + h*64 + d;
    sq += qkv[base];
    sk += qkv[base + 512];
  }
  ql[(size_t)(h*MLM+m)*64 + d] = sq * (0.125f/40.f);  // DH^-0.5 folded in
  kl[(size_t)(h*MLM+m)*64 + d] = sk * (1.f/40.f);
}

// ---------------- attn2 = softmax(ql @ kl^T) ---------------------------------
__global__ __launch_bounds__(256) void k_attn2(const float* __restrict__ ql,
    const float* __restrict__ kl, float* __restrict__ X){
  __shared__ float4 q4[16];
  __shared__ float red[32];
  int i = blockIdx.x, h = blockIdx.y, j = threadIdx.x;
  if (j < 16) q4[j] = ((const float4*)(ql + (size_t)(h*MLM+i)*64))[j];
  __syncthreads();
  const float4* kp = (const float4*)(kl + (size_t)(h*MLM+j)*64);
  float s = 0.f;
  #pragma unroll
  for (int t=0;t<16;t++){
    float4 kv = kp[t], q = q4[t];
    s += q.x*kv.x + q.y*kv.y + q.z*kv.z + q.w*kv.w;
  }
  float mx = blockRedMax(s, red);
  float e = expf(s - mx);
  float sm = blockRedSum(e, red);
  X[(size_t)(h*MLM+i)*MLM + j] = e / sm;
}

// ---------------- pinv init: abs row/col max ---------------------------------
__global__ void k_zero2(float* red){ if (threadIdx.x < 2) red[threadIdx.x] = 0.f; }

__global__ __launch_bounds__(256) void k_absmax(const float* __restrict__ X,
    float* __restrict__ red_out, int mode){
  __shared__ float red[32];
  int a = blockIdx.x, h = blockIdx.y, t = threadIdx.x;
  float v;
  if (mode == 0) v = fabsf(X[(size_t)(h*MLM+a)*MLM + t]);   // row sums
  else           v = fabsf(X[(size_t)(h*MLM+t)*MLM + a]);   // col sums
  float s = blockRedSum(v, red);
  if (t == 0) atomicMax((int*)(red_out + mode), __float_as_int(s));
}

__global__ void k_zinit(const float* __restrict__ X, float* __restrict__ Z,
                        const float* __restrict__ red){
  int idx = blockIdx.x*blockDim.x + threadIdx.x;
  if (idx >= HEADS*MLM*MLM) return;
  int h = idx >> 16, r = (idx >> 8) & 255, c = idx & 255;
  float inv = 1.f / (red[0] * red[1]);
  Z[idx] = X[(size_t)h*MLM*MLM + (size_t)c*MLM + r] * inv;
}

// ---------------- zero accumulators for attn3v -------------------------------
__global__ void k_zeroacc(float* oacc, float* rsum){
  int idx = blockIdx.x*blockDim.x + threadIdx.x;
  if (idx < HEADS*MLM*DH) oacc[idx] = 0.f;
  if (idx < HEADS*MLM) rsum[idx] = 0.f;
}

// ---- t3v partials: exp(ql@K^T) @ V over a 1280-key slice, split-TF32 mma ----
// grid (16, HEADS): bx&1 -> 128-row landmark half, bx>>1 -> key slice (8 slices).
__global__ __launch_bounds__(256, 1) void k_attn3v_mma(
    const float* __restrict__ qkv, const float* __restrict__ ql,
    float* __restrict__ oacc, float* __restrict__ rsum){
  extern __shared__ unsigned dyn3[];
  unsigned* Qh = dyn3;                 // [128][68]
  unsigned* Qlo = Qh + 128*68;         // [128][68]
  unsigned* Kh = Qlo + 128*68;         // [64][68]
  unsigned* Kl = Kh + 64*68;
  unsigned* Vh = Kl + 64*68;
  unsigned* Vl = Vh + 64*68;
  unsigned* Ph = Vl + 64*68;           // [128][68]
  unsigned* Pl = Ph + 128*68;

  const int h = blockIdx.y;
  const int m0 = (blockIdx.x & 1) * 128;
  const int slice = blockIdx.x >> 1;   // 0..7, 1280 keys each
  const int tid = threadIdx.x;
  const int w = tid >> 5, lane = tid & 31;
  const int g = lane >> 2, t = lane & 3;
  const int wm = w * 16;               // warp owns rows wm..wm+15

  // load Q (128x64) hi/lo
  #pragma unroll
  for (int l=0;l<8;l++){
    int s = tid + l*256;
    int row = s>>4, dq = (s&15)*4;
    float4 v = *(const float4*)(ql + (size_t)(h*MLM + m0 + row)*64 + dq);
    float av[4] = {v.x, v.y, v.z, v.w};
    #pragma unroll
    for (int q=0;q<4;q++){
      unsigned hi = f2tf(av[q]);
      Qh[row*68+dq+q]  = hi;
      Qlo[row*68+dq+q] = f2tf(av[q] - __uint_as_float(hi));
    }
  }

  float acc_o[8][4];
  #pragma unroll
  for (int j=0;j<8;j++)
    #pragma unroll
    for (int q=0;q<4;q++) acc_o[j][q]=0.f;
  float rs0 = 0.f, rs1 = 0.f;          // rowsums for rows wm+g, wm+g+8

  const int key_base = slice * 1280;
  for (int cn = 0; cn < 20; cn++){
    int key0 = key_base + cn*64;
    __syncthreads();                   // K/V smem free of prior readers
    // load K,V chunk (64x64 each) hi/lo
    #pragma unroll
    for (int l=0;l<4;l++){
      int s = tid + l*256;
      int row = s>>4, dq = (s&15)*4;
      const float* base = qkv + (size_t)(key0+row)*1536 + h*64 + dq;
      float4 kv = *(const float4*)(base + 512);
      float4 vv = *(const float4*)(base + 1024);
      float ka[4] = {kv.x, kv.y, kv.z, kv.w};
      float va[4] = {vv.x, vv.y, vv.z, vv.w};
      #pragma unroll
      for (int q=0;q<4;q++){
        unsigned hi = f2tf(ka[q]);
        Kh[row*68+dq+q] = hi;
        Kl[row*68+dq+q] = f2tf(ka[q] - __uint_as_float(hi));
        unsigned hv = f2tf(va[q]);
        Vh[row*68+dq+q] = hv;
        Vl[row*68+dq+q] = f2tf(va[q] - __uint_as_float(hv));
      }
    }
    __syncthreads();
    // S = Q @ K^T
    float sacc[8][4];
    #pragma unroll
    for (int nt=0;nt<8;nt++)
      #pragma unroll
      for (int q=0;q<4;q++) sacc[nt][q]=0.f;
    #pragma unroll
    for (int kk=0; kk<64; kk+=8){
      unsigned ah[4], al[4];
      ah[0]=Qh[(wm+g)*68+kk+t];    ah[1]=Qh[(wm+g+8)*68+kk+t];
      ah[2]=Qh[(wm+g)*68+kk+t+4];  ah[3]=Qh[(wm+g+8)*68+kk+t+4];
      al[0]=Qlo[(wm+g)*68+kk+t];   al[1]=Qlo[(wm+g+8)*68+kk+t];
      al[2]=Qlo[(wm+g)*68+kk+t+4]; al[3]=Qlo[(wm+g+8)*68+kk+t+4];
      #pragma unroll
      for (int nt=0; nt<8; nt++){
        int c = nt*8 + g;
        unsigned bh0 = Kh[c*68+kk+t], bh1 = Kh[c*68+kk+t+4];
        unsigned bl0 = Kl[c*68+kk+t], bl1 = Kl[c*68+kk+t+4];
        MMA_TF32(sacc[nt], ah, bh0, bh1);
        MMA_TF32(sacc[nt], al, bh0, bh1);
        MMA_TF32(sacc[nt], ah, bl0, bl1);
      }
    }
    // exp, rowsums, store P hi/lo
    #pragma unroll
    for (int nt=0; nt<8; nt++){
      float e0 = expf(sacc[nt][0]), e1 = expf(sacc[nt][1]);
      float e2 = expf(sacc[nt][2]), e3 = expf(sacc[nt][3]);
      rs0 += e0 + e1; rs1 += e2 + e3;
      int c0 = nt*8 + t*2;
      unsigned h0 = f2tf(e0), h1 = f2tf(e1), h2 = f2tf(e2), h3 = f2tf(e3);
      Ph[(wm+g)*68 + c0]     = h0;
      Ph[(wm+g)*68 + c0+1]   = h1;
      Ph[(wm+g+8)*68 + c0]   = h2;
      Ph[(wm+g+8)*68 + c0+1] = h3;
      Pl[(wm+g)*68 + c0]     = f2tf(e0 - __uint_as_float(h0));
      Pl[(wm+g)*68 + c0+1]   = f2tf(e1 - __uint_as_float(h1));
      Pl[(wm+g+8)*68 + c0]   = f2tf(e2 - __uint_as_float(h2));
      Pl[(wm+g+8)*68 + c0+1] = f2tf(e3 - __uint_as_float(h3));
    }
    __syncwarp();                      // own-warp P rows only
    // O += P @ V
    #pragma unroll
    for (int kk=0; kk<64; kk+=8){
      unsigned ah[4], al[4];
      ah[0]=Ph[(wm+g)*68+kk+t];    ah[1]=Ph[(wm+g+8)*68+kk+t];
      ah[2]=Ph[(wm+g)*68+kk+t+4];  ah[3]=Ph[(wm+g+8)*68+kk+t+4];
      al[0]=Pl[(wm+g)*68+kk+t];    al[1]=Pl[(wm+g+8)*68+kk+t];
      al[2]=Pl[(wm+g)*68+kk+t+4]; al[3]=Pl[(wm+g+8)*68+kk+t+4];
      #pragma unroll
      for (int nt=0; nt<8; nt++){
        int c = nt*8 + g;
        unsigned bh0 = Vh[(kk+t)*68+c], bh1 = Vh[(kk+t+4)*68+c];
        unsigned bl0 = Vl[(kk+t)*68+c], bl1 = Vl[(kk+t+4)*68+c];
        MMA_TF32(acc_o[nt], ah, bh0, bh1);
        MMA_TF32(acc_o[nt], al, bh0, bh1);
        MMA_TF32(acc_o[nt], ah, bl0, bl1);
      }
    }
  }
  // reduce rowsums across the 4 t-lanes sharing each g
  rs0 += __shfl_xor_sync(0xffffffffu, rs0, 1);
  rs0 += __shfl_xor_sync(0xffffffffu, rs0, 2);
  rs1 += __shfl_xor_sync(0xffffffffu, rs1, 1);
  rs1 += __shfl_xor_sync(0xffffffffu, rs1, 2);
  if (t == 0){
    atomicAdd(&rsum[h*MLM + m0 + wm + g], rs0);
    atomicAdd(&rsum[h*MLM + m0 + wm + g + 8], rs1);
  }
  // emit O partials
  #pragma unroll
  for (int nt=0; nt<8; nt++){
    #pragma unroll
    for (int q=0;q<4;q++){
      int row = m0 + wm + g + (q>>1)*8;
      int col = nt*8 + t*2 + (q&1);
      atomicAdd(&oacc[(size_t)(h*MLM + row)*64 + col], acc_o[nt][q]);
    }
  }
}

__global__ void k_t3fin(const float* __restrict__ oacc, const float* __restrict__ rsum,
                        float* __restrict__ t3v){
  int idx = blockIdx.x*blockDim.x + threadIdx.x;
  if (idx >= HEADS*MLM*DH) return;
  t3v[idx] = oacc[idx] / rsum[idx >> 6];
}

// ---- attn1W: softmax(q@kl^T) @ W, split-TF32 mma, flash-style ---------------
// grid (NPAD/128, HEADS). 128 tokens/block; 4 chunks of 64 landmarks.
__global__ __launch_bounds__(256, 1) void k_attn1W_mma(
    const float* __restrict__ qkv, const float* __restrict__ kl,
    const float* __restrict__ W, float* __restrict__ ao){
  extern __shared__ unsigned dyn1[];
  unsigned* Qh = dyn1;                 // [128][68]
  unsigned* Qlo = Qh + 128*68;         // [128][68]
  unsigned* Kh = Qlo + 128*68;         // [64][68] (kl chunk)
  unsigned* Kl = Kh + 64*68;
  unsigned* Vh = Kl + 64*68;           // [64][68] (W chunk)
  unsigned* Vl = Vh + 64*68;
  unsigned* Ph = Vl + 64*68;           // [128][68]
  unsigned* Pl = Ph + 128*68;

  const int h = blockIdx.y;
  const int t0 = blockIdx.x * 128;
  const int tid = threadIdx.x;
  const int w = tid >> 5, lane = tid & 31;
  const int g = lane >> 2, t = lane & 3;
  const int wm = w * 16;

  // load Q (128 tokens x 64 dims), scaled by 0.125, hi/lo
  #pragma unroll
  for (int l=0;l<8;l++){
    int s = tid + l*256;
    int row = s>>4, dq = (s&15)*4;
    float4 v = *(const float4*)(qkv + (size_t)(t0+row)*1536 + h*64 + dq);
    float av[4] = {v.x*0.125f, v.y*0.125f, v.z*0.125f, v.w*0.125f};
    #pragma unroll
    for (int q=0;q<4;q++){
      unsigned hi = f2tf(av[q]);
      Qh[row*68+dq+q]  = hi;
      Qlo[row*68+dq+q] = f2tf(av[q] - __uint_as_float(hi));
    }
  }

  float acc_o[8][4];
  #pragma unroll
  for (int j=0;j<8;j++)
    #pragma unroll
    for (int q=0;q<4;q++) acc_o[j][q]=0.f;
  float rs0 = 0.f, rs1 = 0.f;

  for (int cn = 0; cn < 4; cn++){
    int m0 = cn*64;                    // landmark chunk base
    __syncthreads();
    // load KL chunk + W chunk (64x64 each) hi/lo
    #pragma unroll
    for (int l=0;l<4;l++){
      int s = tid + l*256;
      int row = s>>4, dq = (s&15)*4;
      float4 kv = *(const float4*)(kl + (size_t)(h*MLM + m0 + row)*64 + dq);
      float4 vv = *(const float4*)(W  + (size_t)(h*MLM + m0 + row)*64 + dq);
      float ka[4] = {kv.x, kv.y, kv.z, kv.w};
      float va[4] = {vv.x, vv.y, vv.z, vv.w};
      #pragma unroll
      for (int q=0;q<4;q++){
        unsigned hi = f2tf(ka[q]);
        Kh[row*68+dq+q] = hi;
        Kl[row*68+dq+q] = f2tf(ka[q] - __uint_as_float(hi));
        unsigned hv = f2tf(va[q]);
        Vh[row*68+dq+q] = hv;
        Vl[row*68+dq+q] = f2tf(va[q] - __uint_as_float(hv));
      }
    }
    __syncthreads();
    // S = Q @ KL^T
    float sacc[8][4];
    #pragma unroll
    for (int nt=0;nt<8;nt++)
      #pragma unroll
      for (int q=0;q<4;q++) sacc[nt][q]=0.f;
    #pragma unroll
    for (int kk=0; kk<64; kk+=8){
      unsigned ah[4], al[4];
      ah[0]=Qh[(wm+g)*68+kk+t];    ah[1]=Qh[(wm+g+8)*68+kk+t];
      ah[2]=Qh[(wm+g)*68+kk+t+4];  ah[3]=Qh[(wm+g+8)*68+kk+t+4];
      al[0]=Qlo[(wm+g)*68+kk+t];   al[1]=Qlo[(wm+g+8)*68+kk+t];
      al[2]=Qlo[(wm+g)*68+kk+t+4]; al[3]=Qlo[(wm+g+8)*68+kk+t+4];
      #pragma unroll
      for (int nt=0; nt<8; nt++){
        int c = nt*8 + g;
        unsigned bh0 = Kh[c*68+kk+t], bh1 = Kh[c*68+kk+t+4];
        unsigned bl0 = Kl[c*68+kk+t], bl1 = Kl[c*68+kk+t+4];
        MMA_TF32(sacc[nt], ah, bh0, bh1);
        MMA_TF32(sacc[nt], al, bh0, bh1);
        MMA_TF32(sacc[nt], ah, bl0, bl1);
      }
    }
    // exp, rowsums, store P hi/lo
    #pragma unroll
    for (int nt=0; nt<8; nt++){
      float e0 = expf(sacc[nt][0]), e1 = expf(sacc[nt][1]);
      float e2 = expf(sacc[nt][2]), e3 = expf(sacc[nt][3]);
      rs0 += e0 + e1; rs1 += e2 + e3;
      int c0 = nt*8 + t*2;
      unsigned h0 = f2tf(e0), h1 = f2tf(e1), h2 = f2tf(e2), h3 = f2tf(e3);
      Ph[(wm+g)*68 + c0]     = h0;
      Ph[(wm+g)*68 + c0+1]   = h1;
      Ph[(wm+g+8)*68 + c0]   = h2;
      Ph[(wm+g+8)*68 + c0+1] = h3;
      Pl[(wm+g)*68 + c0]     = f2tf(e0 - __uint_as_float(h0));
      Pl[(wm+g)*68 + c0+1]   = f2tf(e1 - __uint_as_float(h1));
      Pl[(wm+g+8)*68 + c0]   = f2tf(e2 - __uint_as_float(h2));
      Pl[(wm+g+8)*68 + c0+1] = f2tf(e3 - __uint_as_float(h3));
    }
    __syncwarp();
    // O += P @ W_chunk
    #pragma unroll
    for (int kk=0; kk<64; kk+=8){
      unsigned ah[4], al[4];
      ah[0]=Ph[(wm+g)*68+kk+t];    ah[1]=Ph[(wm+g+8)*68+kk+t];
      ah[2]=Ph[(wm+g)*68+kk+t+4];  ah[3]=Ph[(wm+g+8)*68+kk+t+4];
      al[0]=Pl[(wm+g)*68+kk+t];    al[1]=Pl[(wm+g+8)*68+kk+t];
      al[2]=Pl[(wm+g)*68+kk+t+4]; al[3]=Pl[(wm+g+8)*68+kk+t+4];
      #pragma unroll
      for (int nt=0; nt<8; nt++){
        int c = nt*8 + g;
        unsigned bh0 = Vh[(kk+t)*68+c], bh1 = Vh[(kk+t+4)*68+c];
        unsigned bl0 = Vl[(kk+t)*68+c], bl1 = Vl[(kk+t+4)*68+c];
        MMA_TF32(acc_o[nt], ah, bh0, bh1);
        MMA_TF32(acc_o[nt], al, bh0, bh1);
        MMA_TF32(acc_o[nt], ah, bl0, bl1);
      }
    }
  }
  // full rowsums: reduce across the 4 t-lanes of each g
  rs0 += __shfl_xor_sync(0xffffffffu, rs0, 1);
  rs0 += __shfl_xor_sync(0xffffffffu, rs0, 2);
  rs1 += __shfl_xor_sync(0xffffffffu, rs1, 1);
  rs1 += __shfl_xor_sync(0xffffffffu, rs1, 2);
  float inv0 = 1.f / rs0, inv1 = 1.f / rs1;
  // write normalized output
  #pragma unroll
  for (int nt=0; nt<8; nt++){
    #pragma unroll
    for (int q=0;q<4;q++){
      int rl = wm + g + (q>>1)*8;
      int col = nt*8 + t*2 + (q&1);
      float inv = (q>>1) ? inv1 : inv0;
      ao[(size_t)(t0+rl)*DIM + h*64 + col] = acc_o[nt][q] * inv;
    }
  }
}

// ---------------- residual depthwise conv (kernel 33 along sequence) ---------
__global__ void k_convres(const float* __restrict__ qkv, const float* __restrict__ rw,
                          float* __restrict__ ao){
  int idx = blockIdx.x*blockDim.x + threadIdx.x;
  if (idx >= NPAD*DIM) return;
  int n = idx >> 9, c = idx & 511;
  int h = c >> 6;
  float acc = ao[idx];
  #pragma unroll
  for (int t=0;t<33;t++){
    int s = n + t - 16;
    if (s >= 0 && s < NPAD)
      acc += rw[h*33+t] * qkv[(size_t)s*1536 + 1024 + c];
  }
  ao[idx] = acc;
}

// ---------------- PPEG -------------------------------------------------------
__global__ void k_cls(const float* __restrict__ hin, float* __restrict__ hout){
  int c = blockIdx.x*blockDim.x + threadIdx.x;
  if (c < DIM) hout[c] = hin[c];
}

__global__ __launch_bounds__(128) void k_ppeg(const float* __restrict__ hin,
    const float* __restrict__ w7, const float* __restrict__ b7,
    const float* __restrict__ w5, const float* __restrict__ b5,
    const float* __restrict__ w3, const float* __restrict__ b3,
    float* __restrict__ hout){
  int pos = blockIdx.x;                 // 0..9999
  int c = blockIdx.y*128 + threadIdx.x;
  int i = pos / HH, j = pos % HH;
  float acc = hin[(size_t)(1+pos)*DIM + c] + b7[c] + b5[c] + b3[c];
  #pragma unroll
  for (int a=0;a<7;a++){
    int ii = i + a - 3;
    if (ii < 0 || ii >= HH) continue;
    #pragma unroll
    for (int bb=0;bb<7;bb++){
      int jj = j + bb - 3;
      if (jj < 0 || jj >= HH) continue;
      acc += hin[(size_t)(1+ii*HH+jj)*DIM + c] * w7[(size_t)c*49 + a*7 + bb];
    }
  }
  #pragma unroll
  for (int a=0;a<5;a++){
    int ii = i + a - 2;
    if (ii < 0 || ii >= HH) continue;
    #pragma unroll
    for (int bb=0;bb<5;bb++){
      int jj = j + bb - 2;
      if (jj < 0 || jj >= HH) continue;
      acc += hin[(size_t)(1+ii*HH+jj)*DIM + c] * w5[(size_t)c*25 + a*5 + bb];
    }
  }
  #pragma unroll
  for (int a=0;a<3;a++){
    int ii = i + a - 1;
    if (ii < 0 || ii >= HH) continue;
    #pragma unroll
    for (int bb=0;bb<3;bb++){
      int jj = j + bb - 1;
      if (jj < 0 || jj >= HH) continue;
      acc += hin[(size_t)(1+ii*HH+jj)*DIM + c] * w3[(size_t)c*9 + a*3 + bb];
    }
  }
  hout[(size_t)(1+pos)*DIM + c] = acc;
}

// ---------------- heads ------------------------------------------------------
__global__ void k_heads(const float* __restrict__ hn,
    const float* __restrict__ fcw, const float* __restrict__ fcb,
    const float* __restrict__ pcw, const float* __restrict__ pcb,
    float* __restrict__ out){
  int warp = (blockIdx.x*blockDim.x + threadIdx.x) >> 5;
  int lane = threadIdx.x & 31;
  if (warp >= NTOK) return;
  const float* hr = hn + (size_t)warp*DIM;
  const float* Wm = (warp == 0) ? fcw : pcw;
  float d0=0.f, d1=0.f;
  for (int k=lane;k<DIM;k+=32){
    float v = hr[k];
    d0 += v*Wm[2*k];
    d1 += v*Wm[2*k+1];
  }
  d0 = warpRedSum(d0);
  d1 = warpRedSum(d1);
  if (lane == 0){
    if (warp == 0){
      out[0] = d0 + fcb[0];
      out[1] = d1 + fcb[1];
    } else {
      float l0 = d0 + pcb[0], l1 = d1 + pcb[1];
      int r = warp - 1;
      out[2 + 2*r]     = l0;
      out[2 + 2*r + 1] = l1;
      float m = fmaxf(l0,l1);
      float e0 = expf(l0-m), e1 = expf(l1-m);
      float inv = 1.f/(e0+e1);
      out[2 + 2*N0 + 2*r]     = e0*inv;
      out[2 + 2*N0 + 2*r + 1] = e1*inv;
    }
  }
}

// ---------------- host side --------------------------------------------------
static void run_attn_block(const float* ln_w, const float* ln_b, const float* qkv_w,
    const float* out_w, const float* out_b, const float* res_w,
    float* h, float* S){
  float* XP  = S + O_XP;
  float* QKV = S + O_QKV;
  float* AO  = S + O_AO;
  float* QL  = S + O_QL;
  float* KL  = S + O_KL;
  float* X   = S + O_X;
  float* Z0  = S + O_Z0;
  float* Z1  = S + O_Z1;
  float* TA  = S + O_TA;   // attn3v oacc
  float* TU  = S + O_TU;   // attn3v rsum
  float* TT  = S + O_TT;
  float* T3  = S + O_T3;
  float* Wb  = S + O_W;
  float* RED = S + O_RED;

  k_lnpad<<<NPAD, 256>>>(h, XP, ln_w, ln_b, PADR);
  k_mma_gemm<<<dim3(1536/128, NPAD/128), 256, GEMM_SMEM>>>(XP, qkv_w, nullptr, nullptr,
                                                           QKV, NPAD, 1536, DIM);
  k_land<<<dim3(MLM, HEADS), 64>>>(QKV, QL, KL);
  k_attn2<<<dim3(MLM, HEADS), 256>>>(QL, KL, X);
  k_zero2<<<1, 32>>>(RED);
  k_absmax<<<dim3(MLM, HEADS), 256>>>(X, RED, 0);
  k_absmax<<<dim3(MLM, HEADS), 256>>>(X, RED, 1);
  k_zinit<<<(HEADS*MLM*MLM + 255)/256, 256>>>(X, Z0, RED);

  const long long sM = (long long)MLM*MLM;
  float* zc = Z0; float* zn = Z1;
  for (int it=0; it<6; it++){
    k_bgemm64<<<dim3(4,4,HEADS), 256>>>(X,  zc, TA, MLM, sM, sM, sM, 0.f,  1.f, 1.f);
    k_bgemm64<<<dim3(4,4,HEADS), 256>>>(TA, TA, TU, MLM, sM, sM, sM, 7.f, -1.f, 1.f);
    k_bgemm64<<<dim3(4,4,HEADS), 256>>>(TA, TU, TT, MLM, sM, sM, sM, 15.f,-1.f, 1.f);
    k_bgemm64<<<dim3(4,4,HEADS), 256>>>(zc, TT, zn, MLM, sM, sM, sM, 13.f,-1.f, 0.25f);
    float* tmp = zc; zc = zn; zn = tmp;
  }

  // attn3 @ v via split-TF32 tensor cores, key-sliced partials
  k_zeroacc<<<(HEADS*MLM*DH + 255)/256, 256>>>(TA, TU);
  k_attn3v_mma<<<dim3(16, HEADS), 256, ATT3_SMEM>>>(QKV, QL, TA, TU);
  k_t3fin<<<(HEADS*MLM*DH + 255)/256, 256>>>(TA, TU, T3);

  const long long sS = (long long)MLM*DH;
  k_bgemm64<<<dim3(1,4,HEADS), 256>>>(zc, T3, Wb, DH, sM, sS, sS, 0.f, 1.f, 1.f);
  k_attn1W_mma<<<dim3(NPAD/128, HEADS), 256, ATT3_SMEM>>>(QKV, KL, Wb, AO);
  k_convres<<<(NPAD*DIM + 255)/256, 256>>>(QKV, res_w, AO);
  // out proj + residual into h (rows PADR.. of AO map to h rows 0..)
  k_mma_gemm<<<dim3(DIM/128, (NTOK+127)/128), 256, GEMM_SMEM>>>(AO + (size_t)PADR*DIM,
                                                  out_w, out_b, h, h, NTOK, DIM, DIM);
}

extern "C" void kernel_launch(void* const* d_in, const int* in_sizes, int n_in,
                              void* d_out, int out_size){
  const float* x      = (const float*)d_in[0];
  const float* cls    = (const float*)d_in[1];
  const float* ln1_w  = (const float*)d_in[2];
  const float* ln1_b  = (const float*)d_in[3];
  const float* qkv1_w = (const float*)d_in[4];
  const float* out1_w = (const float*)d_in[5];
  const float* out1_b = (const float*)d_in[6];
  const float* res1_w = (const float*)d_in[7];
  const float* p7_w   = (const float*)d_in[8];
  const float* p7_b   = (const float*)d_in[9];
  const float* p5_w   = (const float*)d_in[10];
  const float* p5_b   = (const float*)d_in[11];
  const float* p3_w   = (const float*)d_in[12];
  const float* p3_b   = (const float*)d_in[13];
  const float* ln2_w  = (const float*)d_in[14];
  const float* ln2_b  = (const float*)d_in[15];
  const float* qkv2_w = (const float*)d_in[16];
  const float* out2_w = (const float*)d_in[17];
  const float* out2_b = (const float*)d_in[18];
  const float* res2_w = (const float*)d_in[19];
  const float* norm_w = (const float*)d_in[20];
  const float* norm_b = (const float*)d_in[21];
  const float* fc2_w  = (const float*)d_in[22];
  const float* fc2_b  = (const float*)d_in[23];
  const float* pc_w   = (const float*)d_in[24];
  const float* pc_b   = (const float*)d_in[25];

  float* S = nullptr;
  cudaGetSymbolAddress((void**)&S, g_scratch);
  cudaFuncSetAttribute(k_attn3v_mma, cudaFuncAttributeMaxDynamicSharedMemorySize,
                       ATT3_SMEM);
  cudaFuncSetAttribute(k_attn1W_mma, cudaFuncAttributeMaxDynamicSharedMemorySize,
                       ATT3_SMEM);
  cudaFuncSetAttribute(k_mma_gemm, cudaFuncAttributeMaxDynamicSharedMemorySize,
                       GEMM_SMEM);

  float* H0 = S + O_H0;
  float* H1 = S + O_H1;
  float* XP = S + O_XP;

  k_build<<<(NTOK*DIM + 255)/256, 256>>>(x, cls, H0);

  run_attn_block(ln1_w, ln1_b, qkv1_w, out1_w, out1_b, res1_w, H0, S);

  k_cls<<<2, 256>>>(H0, H1);
  k_ppeg<<<dim3(N0, DIM/128), 128>>>(H0, p7_w, p7_b, p5_w, p5_b, p3_w, p3_b, H1);

  run_attn_block(ln2_w, ln2_b, qkv2_w, out2_w, out2_b, res2_w, H1, S);

  k_lnpad<<<NTOK, 256>>>(H1, XP, norm_w, norm_b, 0);
  k_heads<<<(NTOK + 7)/8, 256>>>(XP, fc2_w, fc2_b, pc_w, pc_b, (float*)d_out);
}

// round 16
// speedup vs baseline: 2.5826x; 1.1768x over previous
#include <cuda_runtime.h>
#include <math.h>

#define N0    10000
#define NTOK  10001
#define DIM   512
#define NPAD  10240
#define PADR  239
#define HEADS 8
#define DH    64
#define MLM   256
#define HH    100

// ---------------- scratch (single device global, no allocations) -------------
constexpr size_t O_H0 = 0;                                  // NTOK*DIM
constexpr size_t O_H1 = O_H0 + (size_t)NTOK*DIM;
constexpr size_t O_XP = O_H1 + (size_t)NTOK*DIM;            // NPAD*DIM (LN+pad; final hn)
constexpr size_t O_QKV= O_XP + (size_t)NPAD*DIM;            // NPAD*1536
constexpr size_t O_AO = O_QKV+ (size_t)NPAD*3*DIM;          // NPAD*DIM
constexpr size_t O_QL = O_AO + (size_t)NPAD*DIM;
constexpr size_t O_KL = O_QL + (size_t)HEADS*MLM*DH;
constexpr size_t O_X  = O_KL + (size_t)HEADS*MLM*DH;        // attn2
constexpr size_t O_Z0 = O_X  + (size_t)HEADS*MLM*MLM;
constexpr size_t O_Z1 = O_Z0 + (size_t)HEADS*MLM*MLM;
constexpr size_t O_TA = O_Z1 + (size_t)HEADS*MLM*MLM;       // doubles as attn3v oacc
constexpr size_t O_TU = O_TA + (size_t)HEADS*MLM*MLM;       // doubles as attn3v rsum
constexpr size_t O_TT = O_TU + (size_t)HEADS*MLM*MLM;
constexpr size_t O_T3 = O_TT + (size_t)HEADS*MLM*MLM;       // attn3@v : H*256*64
constexpr size_t O_W  = O_T3 + (size_t)HEADS*MLM*DH;        // Z@(attn3@v)
constexpr size_t O_RED= O_W  + (size_t)HEADS*MLM*DH;
constexpr size_t O_WC = O_RED+ 8;                           // combined ppeg weights 512*49
constexpr size_t O_BC = O_WC + (size_t)512*49;              // combined bias 512
constexpr size_t SCRATCH_TOTAL = O_BC + 512;

__device__ float g_scratch[SCRATCH_TOTAL];

// smem layout (both mma-attention kernels):
#define ATT3_SMEM ((4*(128*68) + 4*(64*68)) * 4)
// double-buffered GEMM smem: 2 x A(128x36) + 2 x B(32x136)
#define GEMM_SMEM ((2*128*36 + 2*32*136) * 4)
// convres smem: 64 rows x 512 ch
#define CONV_SMEM (64*512*4)
// ppeg smem: 7x16 window x 128 ch
#define PPEG_SMEM (7*16*128*4)

// ---------------- helpers ----------------------------------------------------
__device__ __forceinline__ unsigned f2tf(float x){
  unsigned u; asm("cvt.rna.tf32.f32 %0, %1;" : "=r"(u) : "f"(x)); return u;
}

#define MMA_TF32(d, a, b0v, b1v) \
  asm("mma.sync.aligned.m16n8k8.row.col.f32.tf32.tf32.f32 " \
      "{%0,%1,%2,%3}, {%4,%5,%6,%7}, {%8,%9}, {%0,%1,%2,%3};\n" \
      : "+f"(d[0]),"+f"(d[1]),"+f"(d[2]),"+f"(d[3]) \
      : "r"(a[0]),"r"(a[1]),"r"(a[2]),"r"(a[3]),"r"(b0v),"r"(b1v))

__device__ __forceinline__ float warpRedSum(float v){
  #pragma unroll
  for (int s=16;s;s>>=1) v += __shfl_xor_sync(0xffffffffu, v, s);
  return v;
}
__device__ __forceinline__ float warpRedMax(float v){
  #pragma unroll
  for (int s=16;s;s>>=1) v = fmaxf(v, __shfl_xor_sync(0xffffffffu, v, s));
  return v;
}
__device__ __forceinline__ float blockRedSum(float v, float* red){
  int lane=threadIdx.x&31, wid=threadIdx.x>>5;
  v = warpRedSum(v);
  if (lane==0) red[wid]=v;
  __syncthreads();
  if (wid==0){
    float t = (lane<8)? red[lane] : 0.f;
    t = warpRedSum(t);
    if (lane==0) red[0]=t;
  }
  __syncthreads();
  float r = red[0];
  __syncthreads();
  return r;
}
__device__ __forceinline__ float blockRedMax(float v, float* red){
  int lane=threadIdx.x&31, wid=threadIdx.x>>5;
  v = warpRedMax(v);
  if (lane==0) red[wid]=v;
  __syncthreads();
  if (wid==0){
    float t = (lane<8)? red[lane] : -1e30f;
    t = warpRedMax(t);            // FIXED: was warpRedSum in R12 (caused NaN)
    if (lane==0) red[0]=t;
  }
  __syncthreads();
  float r = red[0];
  __syncthreads();
  return r;
}

// ---------------- build h0 ---------------------------------------------------
__global__ void k_build(const float* __restrict__ x, const float* __restrict__ cls,
                        float* __restrict__ h){
  int idx = blockIdx.x*blockDim.x + threadIdx.x;
  if (idx >= NTOK*DIM) return;
  int r = idx >> 9, c = idx & 511;
  h[idx] = (r == 0) ? cls[c] : x[(size_t)(r-1)*DIM + c];
}

// ---------------- layernorm (+ optional front zero-pad) ----------------------
__global__ __launch_bounds__(256) void k_lnpad(const float* __restrict__ src,
    float* __restrict__ dst, const float* __restrict__ w, const float* __restrict__ b,
    int pad){
  __shared__ float red[32];
  int r = blockIdx.x, tid = threadIdx.x;
  if (r < pad){
    dst[(size_t)r*DIM + tid] = 0.f;
    dst[(size_t)r*DIM + tid + 256] = 0.f;
    return;
  }
  const float* row = src + (size_t)(r-pad)*DIM;
  float v0 = row[tid], v1 = row[tid+256];
  float mu = blockRedSum(v0+v1, red) * (1.f/DIM);
  float d0 = v0-mu, d1 = v1-mu;
  float var = blockRedSum(d0*d0 + d1*d1, red) * (1.f/DIM);
  float rs = 1.f / sqrtf(var + 1e-5f);
  dst[(size_t)r*DIM + tid]       = d0*rs*w[tid]     + b[tid];
  dst[(size_t)r*DIM + tid + 256] = d1*rs*w[tid+256] + b[tid+256];
}

// ------ TF32 tensor-core GEMM, double-buffered: C = A@B [+bias][+Cres] -------
__global__ __launch_bounds__(256) void k_mma_gemm(
    const float* __restrict__ A, const float* __restrict__ B,
    const float* __restrict__ bias, const float* __restrict__ Cres,
    float* __restrict__ C, int M, int N, int K){
  extern __shared__ unsigned gsm[];
  unsigned* AsBase = gsm;                 // 2 stages of 128*36
  unsigned* BsBase = gsm + 2*128*36;      // 2 stages of 32*136
  const int bm = blockIdx.y * 128;
  const int bn = blockIdx.x * 128;
  const int tid = threadIdx.x;
  const int w = tid >> 5, lane = tid & 31;
  const int wm = (w & 3) * 32, wn = (w >> 2) * 64;
  const int g = lane >> 2, t = lane & 3;

  float acc[2][8][4];
  #pragma unroll
  for (int i=0;i<2;i++)
    #pragma unroll
    for (int j=0;j<8;j++)
      #pragma unroll
      for (int q=0;q<4;q++) acc[i][j][q]=0.f;

  float4 pa[4], pb[4];
  #pragma unroll
  for (int i=0;i<4;i++){
    int s = tid + i*256;
    int row = s>>3, kq = (s&7)*4;
    float4 v = make_float4(0.f,0.f,0.f,0.f);
    if (bm+row < M) v = *(const float4*)(A + (size_t)(bm+row)*K + kq);
    pa[i]=v;
    int rowb = s>>5, nq = (s&31)*4;
    float4 vb = make_float4(0.f,0.f,0.f,0.f);
    if (bn+nq < N) vb = *(const float4*)(B + (size_t)rowb*N + bn + nq);
    pb[i]=vb;
  }
  {
    unsigned* As_ = AsBase;
    unsigned* Bs_ = BsBase;
    #pragma unroll
    for (int i=0;i<4;i++){
      int s = tid + i*256;
      int row = s>>3, kq = (s&7)*4;
      uint4 u; u.x=f2tf(pa[i].x); u.y=f2tf(pa[i].y); u.z=f2tf(pa[i].z); u.w=f2tf(pa[i].w);
      *(uint4*)&As_[row*36 + kq] = u;
      int rowb = s>>5, nq = (s&31)*4;
      uint4 ub; ub.x=f2tf(pb[i].x); ub.y=f2tf(pb[i].y); ub.z=f2tf(pb[i].z); ub.w=f2tf(pb[i].w);
      *(uint4*)&Bs_[rowb*136 + nq] = ub;
    }
  }
  __syncthreads();

  int cur = 0;
  for (int k0 = 0; k0 < K; k0 += 32){
    if (k0 + 32 < K){
      #pragma unroll
      for (int i=0;i<4;i++){
        int s = tid + i*256;
        int row = s>>3, kq = (s&7)*4;
        float4 v = make_float4(0.f,0.f,0.f,0.f);
        if (bm+row < M) v = *(const float4*)(A + (size_t)(bm+row)*K + k0+32 + kq);
        pa[i]=v;
        int rowb = s>>5, nq = (s&31)*4;
        float4 vb = make_float4(0.f,0.f,0.f,0.f);
        if (bn+nq < N) vb = *(const float4*)(B + (size_t)(k0+32+rowb)*N + bn + nq);
        pb[i]=vb;
      }
    }
    {
      unsigned* As_ = AsBase + cur*(128*36);
      unsigned* Bs_ = BsBase + cur*(32*136);
      #pragma unroll
      for (int kk=0; kk<32; kk+=8){
        unsigned af[2][4];
        #pragma unroll
        for (int mt=0; mt<2; mt++){
          int r = wm + mt*16 + g;
          af[mt][0]=As_[r*36 + kk+t];       af[mt][1]=As_[(r+8)*36 + kk+t];
          af[mt][2]=As_[r*36 + kk+t+4];     af[mt][3]=As_[(r+8)*36 + kk+t+4];
        }
        #pragma unroll
        for (int nt=0; nt<8; nt++){
          int c = wn + nt*8 + g;
          unsigned b0 = Bs_[(kk+t)*136 + c], b1 = Bs_[(kk+t+4)*136 + c];
          MMA_TF32(acc[0][nt], af[0], b0, b1);
          MMA_TF32(acc[1][nt], af[1], b0, b1);
        }
      }
    }
    if (k0 + 32 < K){
      unsigned* As_ = AsBase + (cur^1)*(128*36);
      unsigned* Bs_ = BsBase + (cur^1)*(32*136);
      #pragma unroll
      for (int i=0;i<4;i++){
        int s = tid + i*256;
        int row = s>>3, kq = (s&7)*4;
        uint4 u; u.x=f2tf(pa[i].x); u.y=f2tf(pa[i].y); u.z=f2tf(pa[i].z); u.w=f2tf(pa[i].w);
        *(uint4*)&As_[row*36 + kq] = u;
        int rowb = s>>5, nq = (s&31)*4;
        uint4 ub; ub.x=f2tf(pb[i].x); ub.y=f2tf(pb[i].y); ub.z=f2tf(pb[i].z); ub.w=f2tf(pb[i].w);
        *(uint4*)&Bs_[rowb*136 + nq] = ub;
      }
    }
    __syncthreads();
    cur ^= 1;
  }
  #pragma unroll
  for (int mt=0; mt<2; mt++){
    #pragma unroll
    for (int nt=0; nt<8; nt++){
      int r0 = bm + wm + mt*16 + g;
      int c0 = bn + wn + nt*8 + t*2;
      #pragma unroll
      for (int q=0;q<4;q++){
        int row = r0 + (q>>1)*8;
        int col = c0 + (q&1);
        if (row < M && col < N){
          float v = acc[mt][nt][q];
          if (bias) v += bias[col];
          if (Cres) v += Cres[(size_t)row*N + col];
          C[(size_t)row*N + col] = v;
        }
      }
    }
  }
}

// ----- batched TF32 gemm, 64x64 tile: C[z] = scale*A[z]@(bI*I + bS*B[z]) -----
__global__ __launch_bounds__(256) void k_bgemm64(
    const float* __restrict__ A, const float* __restrict__ B, float* __restrict__ C,
    int N, long long sA, long long sB, long long sC,
    float bI, float bS, float scale){
  __shared__ unsigned As[64][20];
  __shared__ unsigned Bs[16][68];
  const float* Ah = A + blockIdx.z * sA;
  const float* Bh = B + blockIdx.z * sB;
  float* Ch = C + blockIdx.z * sC;
  const int K = 256;
  const int bm = blockIdx.y * 64;
  const int bn = blockIdx.x * 64;
  const int tid = threadIdx.x;
  const int w = tid >> 5, lane = tid & 31;
  const int wm = (w & 3) * 16, wn = (w >> 2) * 32;
  const int g = lane >> 2, t = lane & 3;

  float acc[4][4];
  #pragma unroll
  for (int j=0;j<4;j++)
    #pragma unroll
    for (int q=0;q<4;q++) acc[j][q]=0.f;

  for (int k0 = 0; k0 < K; k0 += 16){
    {
      int row = tid >> 2, kq = (tid & 3) * 4;
      float4 v = *(const float4*)(Ah + (size_t)(bm+row)*K + k0 + kq);
      As[row][kq+0]=f2tf(v.x); As[row][kq+1]=f2tf(v.y);
      As[row][kq+2]=f2tf(v.z); As[row][kq+3]=f2tf(v.w);
    }
    {
      int rowb = tid >> 4, cq = (tid & 15) * 4;
      float4 vb = *(const float4*)(Bh + (size_t)(k0+rowb)*N + bn + cq);
      int gk = k0 + rowb;
      float bv[4] = {vb.x, vb.y, vb.z, vb.w};
      #pragma unroll
      for (int q=0;q<4;q++){
        float vv = bS * bv[q];
        if (gk == bn + cq + q) vv += bI;
        Bs[rowb][cq+q] = f2tf(vv);
      }
    }
    __syncthreads();
    #pragma unroll
    for (int kk=0; kk<16; kk+=8){
      unsigned af[4];
      af[0]=As[wm+g][kk+t];   af[1]=As[wm+g+8][kk+t];
      af[2]=As[wm+g][kk+t+4]; af[3]=As[wm+g+8][kk+t+4];
      #pragma unroll
      for (int nt=0; nt<4; nt++){
        int c = wn + nt*8 + g;
        unsigned b0 = Bs[kk+t][c], b1 = Bs[kk+t+4][c];
        MMA_TF32(acc[nt], af, b0, b1);
      }
    }
    __syncthreads();
  }
  #pragma unroll
  for (int nt=0; nt<4; nt++){
    #pragma unroll
    for (int q=0;q<4;q++){
      int row = bm + wm + g + (q>>1)*8;
      int col = bn + wn + nt*8 + t*2 + (q&1);
      Ch[(size_t)row*N + col] = scale * acc[nt][q];
    }
  }
}

// ---------------- landmarks --------------------------------------------------
__global__ __launch_bounds__(64) void k_land(const float* __restrict__ qkv,
    float* __restrict__ ql, float* __restrict__ kl){
  int m = blockIdx.x, h = blockIdx.y, d = threadIdx.x;
  float sq = 0.f, sk = 0.f;
  #pragma unroll 8
  for (int j=0;j<40;j++){
    size_t base = (size_t)(m*40+j)*1536 + h*64 + d;
    sq += qkv[base];
    sk += qkv[base + 512];
  }
  ql[(size_t)(h*MLM+m)*64 + d] = sq * (0.125f/40.f);  // DH^-0.5 folded in
  kl[(size_t)(h*MLM+m)*64 + d] = sk * (1.f/40.f);
}

// ---------------- attn2 = softmax(ql @ kl^T) ---------------------------------
__global__ __launch_bounds__(256) void k_attn2(const float* __restrict__ ql,
    const float* __restrict__ kl, float* __restrict__ X){
  __shared__ float4 q4[16];
  __shared__ float red[32];
  int i = blockIdx.x, h = blockIdx.y, j = threadIdx.x;
  if (j < 16) q4[j] = ((const float4*)(ql + (size_t)(h*MLM+i)*64))[j];
  __syncthreads();
  const float4* kp = (const float4*)(kl + (size_t)(h*MLM+j)*64);
  float s = 0.f;
  #pragma unroll
  for (int t=0;t<16;t++){
    float4 kv = kp[t], q = q4[t];
    s += q.x*kv.x + q.y*kv.y + q.z*kv.z + q.w*kv.w;
  }
  float mx = blockRedMax(s, red);
  float e = expf(s - mx);
  float sm = blockRedSum(e, red);
  X[(size_t)(h*MLM+i)*MLM + j] = e / sm;
}

// ---------------- pinv init: abs row/col max ---------------------------------
__global__ void k_zero2(float* red){ if (threadIdx.x < 2) red[threadIdx.x] = 0.f; }

__global__ __launch_bounds__(256) void k_absmax(const float* __restrict__ X,
    float* __restrict__ red_out, int mode){
  __shared__ float red[32];
  int a = blockIdx.x, h = blockIdx.y, t = threadIdx.x;
  float v;
  if (mode == 0) v = fabsf(X[(size_t)(h*MLM+a)*MLM + t]);   // row sums
  else           v = fabsf(X[(size_t)(h*MLM+t)*MLM + a]);   // col sums
  float s = blockRedSum(v, red);
  if (t == 0) atomicMax((int*)(red_out + mode), __float_as_int(s));
}

__global__ void k_zinit(const float* __restrict__ X, float* __restrict__ Z,
                        const float* __restrict__ red){
  int idx = blockIdx.x*blockDim.x + threadIdx.x;
  if (idx >= HEADS*MLM*MLM) return;
  int h = idx >> 16, r = (idx >> 8) & 255, c = idx & 255;
  float inv = 1.f / (red[0] * red[1]);
  Z[idx] = X[(size_t)h*MLM*MLM + (size_t)c*MLM + r] * inv;
}

// ---------------- zero accumulators for attn3v -------------------------------
__global__ void k_zeroacc(float* oacc, float* rsum){
  int idx = blockIdx.x*blockDim.x + threadIdx.x;
  if (idx < HEADS*MLM*DH) oacc[idx] = 0.f;
  if (idx < HEADS*MLM) rsum[idx] = 0.f;
}

// ---- t3v partials: exp(ql@K^T) @ V over a 1280-key slice, split-TF32 mma ----
__global__ __launch_bounds__(256, 1) void k_attn3v_mma(
    const float* __restrict__ qkv, const float* __restrict__ ql,
    float* __restrict__ oacc, float* __restrict__ rsum){
  extern __shared__ unsigned dyn3[];
  unsigned* Qh = dyn3;                 // [128][68]
  unsigned* Qlo = Qh + 128*68;         // [128][68]
  unsigned* Kh = Qlo + 128*68;         // [64][68]
  unsigned* Kl = Kh + 64*68;
  unsigned* Vh = Kl + 64*68;
  unsigned* Vl = Vh + 64*68;
  unsigned* Ph = Vl + 64*68;           // [128][68]
  unsigned* Pl = Ph + 128*68;

  const int h = blockIdx.y;
  const int m0 = (blockIdx.x & 1) * 128;
  const int slice = blockIdx.x >> 1;   // 0..7, 1280 keys each
  const int tid = threadIdx.x;
  const int w = tid >> 5, lane = tid & 31;
  const int g = lane >> 2, t = lane & 3;
  const int wm = w * 16;

  #pragma unroll
  for (int l=0;l<8;l++){
    int s = tid + l*256;
    int row = s>>4, dq = (s&15)*4;
    float4 v = *(const float4*)(ql + (size_t)(h*MLM + m0 + row)*64 + dq);
    float av[4] = {v.x, v.y, v.z, v.w};
    #pragma unroll
    for (int q=0;q<4;q++){
      unsigned hi = f2tf(av[q]);
      Qh[row*68+dq+q]  = hi;
      Qlo[row*68+dq+q] = f2tf(av[q] - __uint_as_float(hi));
    }
  }

  float acc_o[8][4];
  #pragma unroll
  for (int j=0;j<8;j++)
    #pragma unroll
    for (int q=0;q<4;q++) acc_o[j][q]=0.f;
  float rs0 = 0.f, rs1 = 0.f;

  const int key_base = slice * 1280;
  for (int cn = 0; cn < 20; cn++){
    int key0 = key_base + cn*64;
    __syncthreads();
    #pragma unroll
    for (int l=0;l<4;l++){
      int s = tid + l*256;
      int row = s>>4, dq = (s&15)*4;
      const float* base = qkv + (size_t)(key0+row)*1536 + h*64 + dq;
      float4 kv = *(const float4*)(base + 512);
      float4 vv = *(const float4*)(base + 1024);
      float ka[4] = {kv.x, kv.y, kv.z, kv.w};
      float va[4] = {vv.x, vv.y, vv.z, vv.w};
      #pragma unroll
      for (int q=0;q<4;q++){
        unsigned hi = f2tf(ka[q]);
        Kh[row*68+dq+q] = hi;
        Kl[row*68+dq+q] = f2tf(ka[q] - __uint_as_float(hi));
        unsigned hv = f2tf(va[q]);
        Vh[row*68+dq+q] = hv;
        Vl[row*68+dq+q] = f2tf(va[q] - __uint_as_float(hv));
      }
    }
    __syncthreads();
    float sacc[8][4];
    #pragma unroll
    for (int nt=0;nt<8;nt++)
      #pragma unroll
      for (int q=0;q<4;q++) sacc[nt][q]=0.f;
    #pragma unroll
    for (int kk=0; kk<64; kk+=8){
      unsigned ah[4], al[4];
      ah[0]=Qh[(wm+g)*68+kk+t];    ah[1]=Qh[(wm+g+8)*68+kk+t];
      ah[2]=Qh[(wm+g)*68+kk+t+4];  ah[3]=Qh[(wm+g+8)*68+kk+t+4];
      al[0]=Qlo[(wm+g)*68+kk+t];   al[1]=Qlo[(wm+g+8)*68+kk+t];
      al[2]=Qlo[(wm+g)*68+kk+t+4]; al[3]=Qlo[(wm+g+8)*68+kk+t+4];
      #pragma unroll
      for (int nt=0; nt<8; nt++){
        int c = nt*8 + g;
        unsigned bh0 = Kh[c*68+kk+t], bh1 = Kh[c*68+kk+t+4];
        unsigned bl0 = Kl[c*68+kk+t], bl1 = Kl[c*68+kk+t+4];
        MMA_TF32(sacc[nt], ah, bh0, bh1);
        MMA_TF32(sacc[nt], al, bh0, bh1);
        MMA_TF32(sacc[nt], ah, bl0, bl1);
      }
    }
    #pragma unroll
    for (int nt=0; nt<8; nt++){
      float e0 = expf(sacc[nt][0]), e1 = expf(sacc[nt][1]);
      float e2 = expf(sacc[nt][2]), e3 = expf(sacc[nt][3]);
      rs0 += e0 + e1; rs1 += e2 + e3;
      int c0 = nt*8 + t*2;
      unsigned h0 = f2tf(e0), h1 = f2tf(e1), h2 = f2tf(e2), h3 = f2tf(e3);
      Ph[(wm+g)*68 + c0]     = h0;
      Ph[(wm+g)*68 + c0+1]   = h1;
      Ph[(wm+g+8)*68 + c0]   = h2;
      Ph[(wm+g+8)*68 + c0+1] = h3;
      Pl[(wm+g)*68 + c0]     = f2tf(e0 - __uint_as_float(h0));
      Pl[(wm+g)*68 + c0+1]   = f2tf(e1 - __uint_as_float(h1));
      Pl[(wm+g+8)*68 + c0]   = f2tf(e2 - __uint_as_float(h2));
      Pl[(wm+g+8)*68 + c0+1] = f2tf(e3 - __uint_as_float(h3));
    }
    __syncwarp();
    #pragma unroll
    for (int kk=0; kk<64; kk+=8){
      unsigned ah[4], al[4];
      ah[0]=Ph[(wm+g)*68+kk+t];    ah[1]=Ph[(wm+g+8)*68+kk+t];
      ah[2]=Ph[(wm+g)*68+kk+t+4];  ah[3]=Ph[(wm+g+8)*68+kk+t+4];
      al[0]=Pl[(wm+g)*68+kk+t];    al[1]=Pl[(wm+g+8)*68+kk+t];
      al[2]=Pl[(wm+g)*68+kk+t+4]; al[3]=Pl[(wm+g+8)*68+kk+t+4];
      #pragma unroll
      for (int nt=0; nt<8; nt++){
        int c = nt*8 + g;
        unsigned bh0 = Vh[(kk+t)*68+c], bh1 = Vh[(kk+t+4)*68+c];
        unsigned bl0 = Vl[(kk+t)*68+c], bl1 = Vl[(kk+t+4)*68+c];
        MMA_TF32(acc_o[nt], ah, bh0, bh1);
        MMA_TF32(acc_o[nt], al, bh0, bh1);
        MMA_TF32(acc_o[nt], ah, bl0, bl1);
      }
    }
  }
  rs0 += __shfl_xor_sync(0xffffffffu, rs0, 1);
  rs0 += __shfl_xor_sync(0xffffffffu, rs0, 2);
  rs1 += __shfl_xor_sync(0xffffffffu, rs1, 1);
  rs1 += __shfl_xor_sync(0xffffffffu, rs1, 2);
  if (t == 0){
    atomicAdd(&rsum[h*MLM + m0 + wm + g], rs0);
    atomicAdd(&rsum[h*MLM + m0 + wm + g + 8], rs1);
  }
  #pragma unroll
  for (int nt=0; nt<8; nt++){
    #pragma unroll
    for (int q=0;q<4;q++){
      int row = m0 + wm + g + (q>>1)*8;
      int col = nt*8 + t*2 + (q&1);
      atomicAdd(&oacc[(size_t)(h*MLM + row)*64 + col], acc_o[nt][q]);
    }
  }
}

__global__ void k_t3fin(const float* __restrict__ oacc, const float* __restrict__ rsum,
                        float* __restrict__ t3v){
  int idx = blockIdx.x*blockDim.x + threadIdx.x;
  if (idx >= HEADS*MLM*DH) return;
  t3v[idx] = oacc[idx] / rsum[idx >> 6];
}

// ---- attn1W: softmax(q@kl^T) @ W, split-TF32 mma, flash-style ---------------
__global__ __launch_bounds__(256, 1) void k_attn1W_mma(
    const float* __restrict__ qkv, const float* __restrict__ kl,
    const float* __restrict__ W, float* __restrict__ ao){
  extern __shared__ unsigned dyn1[];
  unsigned* Qh = dyn1;                 // [128][68]
  unsigned* Qlo = Qh + 128*68;         // [128][68]
  unsigned* Kh = Qlo + 128*68;         // [64][68] (kl chunk)
  unsigned* Kl = Kh + 64*68;
  unsigned* Vh = Kl + 64*68;           // [64][68] (W chunk)
  unsigned* Vl = Vh + 64*68;
  unsigned* Ph = Vl + 64*68;           // [128][68]
  unsigned* Pl = Ph + 128*68;

  const int h = blockIdx.y;
  const int t0 = blockIdx.x * 128;
  const int tid = threadIdx.x;
  const int w = tid >> 5, lane = tid & 31;
  const int g = lane >> 2, t = lane & 3;
  const int wm = w * 16;

  #pragma unroll
  for (int l=0;l<8;l++){
    int s = tid + l*256;
    int row = s>>4, dq = (s&15)*4;
    float4 v = *(const float4*)(qkv + (size_t)(t0+row)*1536 + h*64 + dq);
    float av[4] = {v.x*0.125f, v.y*0.125f, v.z*0.125f, v.w*0.125f};
    #pragma unroll
    for (int q=0;q<4;q++){
      unsigned hi = f2tf(av[q]);
      Qh[row*68+dq+q]  = hi;
      Qlo[row*68+dq+q] = f2tf(av[q] - __uint_as_float(hi));
    }
  }

  float acc_o[8][4];
  #pragma unroll
  for (int j=0;j<8;j++)
    #pragma unroll
    for (int q=0;q<4;q++) acc_o[j][q]=0.f;
  float rs0 = 0.f, rs1 = 0.f;

  for (int cn = 0; cn < 4; cn++){
    int m0 = cn*64;
    __syncthreads();
    #pragma unroll
    for (int l=0;l<4;l++){
      int s = tid + l*256;
      int row = s>>4, dq = (s&15)*4;
      float4 kv = *(const float4*)(kl + (size_t)(h*MLM + m0 + row)*64 + dq);
      float4 vv = *(const float4*)(W  + (size_t)(h*MLM + m0 + row)*64 + dq);
      float ka[4] = {kv.x, kv.y, kv.z, kv.w};
      float va[4] = {vv.x, vv.y, vv.z, vv.w};
      #pragma unroll
      for (int q=0;q<4;q++){
        unsigned hi = f2tf(ka[q]);
        Kh[row*68+dq+q] = hi;
        Kl[row*68+dq+q] = f2tf(ka[q] - __uint_as_float(hi));
        unsigned hv = f2tf(va[q]);
        Vh[row*68+dq+q] = hv;
        Vl[row*68+dq+q] = f2tf(va[q] - __uint_as_float(hv));
      }
    }
    __syncthreads();
    float sacc[8][4];
    #pragma unroll
    for (int nt=0;nt<8;nt++)
      #pragma unroll
      for (int q=0;q<4;q++) sacc[nt][q]=0.f;
    #pragma unroll
    for (int kk=0; kk<64; kk+=8){
      unsigned ah[4], al[4];
      ah[0]=Qh[(wm+g)*68+kk+t];    ah[1]=Qh[(wm+g+8)*68+kk+t];
      ah[2]=Qh[(wm+g)*68+kk+t+4];  ah[3]=Qh[(wm+g+8)*68+kk+t+4];
      al[0]=Qlo[(wm+g)*68+kk+t];   al[1]=Qlo[(wm+g+8)*68+kk+t];
      al[2]=Qlo[(wm+g)*68+kk+t+4]; al[3]=Qlo[(wm+g+8)*68+kk+t+4];
      #pragma unroll
      for (int nt=0; nt<8; nt++){
        int c = nt*8 + g;
        unsigned bh0 = Kh[c*68+kk+t], bh1 = Kh[c*68+kk+t+4];
        unsigned bl0 = Kl[c*68+kk+t], bl1 = Kl[c*68+kk+t+4];
        MMA_TF32(sacc[nt], ah, bh0, bh1);
        MMA_TF32(sacc[nt], al, bh0, bh1);
        MMA_TF32(sacc[nt], ah, bl0, bl1);
      }
    }
    #pragma unroll
    for (int nt=0; nt<8; nt++){
      float e0 = expf(sacc[nt][0]), e1 = expf(sacc[nt][1]);
      float e2 = expf(sacc[nt][2]), e3 = expf(sacc[nt][3]);
      rs0 += e0 + e1; rs1 += e2 + e3;
      int c0 = nt*8 + t*2;
      unsigned h0 = f2tf(e0), h1 = f2tf(e1), h2 = f2tf(e2), h3 = f2tf(e3);
      Ph[(wm+g)*68 + c0]     = h0;
      Ph[(wm+g)*68 + c0+1]   = h1;
      Ph[(wm+g+8)*68 + c0]   = h2;
      Ph[(wm+g+8)*68 + c0+1] = h3;
      Pl[(wm+g)*68 + c0]     = f2tf(e0 - __uint_as_float(h0));
      Pl[(wm+g)*68 + c0+1]   = f2tf(e1 - __uint_as_float(h1));
      Pl[(wm+g+8)*68 + c0]   = f2tf(e2 - __uint_as_float(h2));
      Pl[(wm+g+8)*68 + c0+1] = f2tf(e3 - __uint_as_float(h3));
    }
    __syncwarp();
    #pragma unroll
    for (int kk=0; kk<64; kk+=8){
      unsigned ah[4], al[4];
      ah[0]=Ph[(wm+g)*68+kk+t];    ah[1]=Ph[(wm+g+8)*68+kk+t];
      ah[2]=Ph[(wm+g)*68+kk+t+4];  ah[3]=Ph[(wm+g+8)*68+kk+t+4];
      al[0]=Pl[(wm+g)*68+kk+t];    al[1]=Pl[(wm+g+8)*68+kk+t];
      al[2]=Pl[(wm+g)*68+kk+t+4]; al[3]=Pl[(wm+g+8)*68+kk+t+4];
      #pragma unroll
      for (int nt=0; nt<8; nt++){
        int c = nt*8 + g;
        unsigned bh0 = Vh[(kk+t)*68+c], bh1 = Vh[(kk+t+4)*68+c];
        unsigned bl0 = Vl[(kk+t)*68+c], bl1 = Vl[(kk+t+4)*68+c];
        MMA_TF32(acc_o[nt], ah, bh0, bh1);
        MMA_TF32(acc_o[nt], al, bh0, bh1);
        MMA_TF32(acc_o[nt], ah, bl0, bl1);
      }
    }
  }
  rs0 += __shfl_xor_sync(0xffffffffu, rs0, 1);
  rs0 += __shfl_xor_sync(0xffffffffu, rs0, 2);
  rs1 += __shfl_xor_sync(0xffffffffu, rs1, 1);
  rs1 += __shfl_xor_sync(0xffffffffu, rs1, 2);
  float inv0 = 1.f / rs0, inv1 = 1.f / rs1;
  #pragma unroll
  for (int nt=0; nt<8; nt++){
    #pragma unroll
    for (int q=0;q<4;q++){
      int rl = wm + g + (q>>1)*8;
      int col = nt*8 + t*2 + (q&1);
      float inv = (q>>1) ? inv1 : inv0;
      ao[(size_t)(t0+rl)*DIM + h*64 + col] = acc_o[nt][q] * inv;
    }
  }
}

// ---------------- residual depthwise conv (33 taps), smem tiled --------------
// Weight load strided (264 > 256 threads) — R5's bug fixed.
__global__ __launch_bounds__(256) void k_convres(const float* __restrict__ qkv,
    const float* __restrict__ rw, float* __restrict__ ao){
  extern __shared__ float vsm[];        // [64][512]
  __shared__ float rws[264];
  const int n0 = blockIdx.x * 32;
  const int tid = threadIdx.x;
  for (int i = tid; i < 264; i += 256) rws[i] = rw[i];
  #pragma unroll
  for (int l=0;l<32;l++){
    int s = tid + l*256;
    int row = s>>7, cq = (s&127)*4;
    int n = n0 - 16 + row;
    float4 v = make_float4(0.f,0.f,0.f,0.f);
    if (n >= 0 && n < NPAD)
      v = *(const float4*)(qkv + (size_t)n*1536 + 1024 + cq);
    *(float4*)&vsm[row*512 + cq] = v;
  }
  __syncthreads();
  #pragma unroll
  for (int l=0;l<64;l++){
    int o = tid + l*256;
    int nl = o>>9, c = o&511;
    int h = c >> 6;
    float acc = 0.f;
    #pragma unroll
    for (int t=0;t<33;t++)
      acc += rws[h*33+t] * vsm[(nl+t)*512 + c];
    ao[(size_t)(n0+nl)*512 + c] += acc;
  }
}

// ---------------- PPEG: combined 49-tap depthwise conv -----------------------
__global__ void k_combw(const float* __restrict__ w7, const float* __restrict__ b7,
    const float* __restrict__ w5, const float* __restrict__ b5,
    const float* __restrict__ w3, const float* __restrict__ b3,
    float* __restrict__ wc, float* __restrict__ bc){
  int c = blockIdx.x;
  int t = threadIdx.x;
  if (t < 49){
    int a = t / 7, b = t % 7;
    float v = w7[c*49 + t];
    if (a >= 1 && a <= 5 && b >= 1 && b <= 5) v += w5[c*25 + (a-1)*5 + (b-1)];
    if (a >= 2 && a <= 4 && b >= 2 && b <= 4) v += w3[c*9 + (a-2)*3 + (b-2)];
    if (t == 24) v += 1.f;               // identity (f term)
    wc[c*49 + t] = v;
  }
  if (t == 63) bc[c] = b7[c] + b5[c] + b3[c];
}

__global__ void k_cls(const float* __restrict__ hin, float* __restrict__ hout){
  int c = blockIdx.x*blockDim.x + threadIdx.x;
  if (c < DIM) hout[c] = hin[c];
}

// grid (1000, 4), 128 threads; block = row i, 10 j-positions, 128 channels
__global__ __launch_bounds__(128) void k_ppeg(const float* __restrict__ hin,
    const float* __restrict__ wc, const float* __restrict__ bc,
    float* __restrict__ hout){
  extern __shared__ float ps[];          // [7*16][128]
  const int i  = blockIdx.x / 10;
  const int j0 = (blockIdx.x % 10) * 10;
  const int c  = blockIdx.y*128 + threadIdx.x;
  const int tid = threadIdx.x;
  #pragma unroll
  for (int a=0;a<7;a++){
    int ii = i + a - 3;
    #pragma unroll
    for (int x=0;x<16;x++){
      int jj = j0 + x - 3;
      float v = 0.f;
      if (ii >= 0 && ii < HH && jj >= 0 && jj < HH)
        v = hin[(size_t)(1 + ii*HH + jj)*DIM + c];
      ps[(a*16 + x)*128 + tid] = v;
    }
  }
  __syncthreads();
  float wreg[49];
  #pragma unroll
  for (int t=0;t<49;t++) wreg[t] = wc[(size_t)c*49 + t];
  float base = bc[c];
  #pragma unroll
  for (int p=0;p<10;p++){
    float acc = base;
    #pragma unroll
    for (int a=0;a<7;a++)
      #pragma unroll
      for (int b=0;b<7;b++)
        acc += wreg[a*7+b] * ps[(a*16 + p + b)*128 + tid];
    hout[(size_t)(1 + i*HH + j0 + p)*DIM + c] = acc;
  }
}

// ---------------- heads ------------------------------------------------------
__global__ void k_heads(const float* __restrict__ hn,
    const float* __restrict__ fcw, const float* __restrict__ fcb,
    const float* __restrict__ pcw, const float* __restrict__ pcb,
    float* __restrict__ out){
  int warp = (blockIdx.x*blockDim.x + threadIdx.x) >> 5;
  int lane = threadIdx.x & 31;
  if (warp >= NTOK) return;
  const float* hr = hn + (size_t)warp*DIM;
  const float* Wm = (warp == 0) ? fcw : pcw;
  float d0=0.f, d1=0.f;
  for (int k=lane;k<DIM;k+=32){
    float v = hr[k];
    d0 += v*Wm[2*k];
    d1 += v*Wm[2*k+1];
  }
  d0 = warpRedSum(d0);
  d1 = warpRedSum(d1);
  if (lane == 0){
    if (warp == 0){
      out[0] = d0 + fcb[0];
      out[1] = d1 + fcb[1];
    } else {
      float l0 = d0 + pcb[0], l1 = d1 + pcb[1];
      int r = warp - 1;
      out[2 + 2*r]     = l0;
      out[2 + 2*r + 1] = l1;
      float m = fmaxf(l0,l1);
      float e0 = expf(l0-m), e1 = expf(l1-m);
      float inv = 1.f/(e0+e1);
      out[2 + 2*N0 + 2*r]     = e0*inv;
      out[2 + 2*N0 + 2*r + 1] = e1*inv;
    }
  }
}

// ---------------- host side --------------------------------------------------
static void run_attn_block(const float* ln_w, const float* ln_b, const float* qkv_w,
    const float* out_w, const float* out_b, const float* res_w,
    float* h, float* S){
  float* XP  = S + O_XP;
  float* QKV = S + O_QKV;
  float* AO  = S + O_AO;
  float* QL  = S + O_QL;
  float* KL  = S + O_KL;
  float* X   = S + O_X;
  float* Z0  = S + O_Z0;
  float* Z1  = S + O_Z1;
  float* TA  = S + O_TA;   // attn3v oacc
  float* TU  = S + O_TU;   // attn3v rsum
  float* TT  = S + O_TT;
  float* T3  = S + O_T3;
  float* Wb  = S + O_W;
  float* RED = S + O_RED;

  k_lnpad<<<NPAD, 256>>>(h, XP, ln_w, ln_b, PADR);
  k_mma_gemm<<<dim3(1536/128, NPAD/128), 256, GEMM_SMEM>>>(XP, qkv_w, nullptr, nullptr,
                                                           QKV, NPAD, 1536, DIM);
  k_land<<<dim3(MLM, HEADS), 64>>>(QKV, QL, KL);
  k_attn2<<<dim3(MLM, HEADS), 256>>>(QL, KL, X);
  k_zero2<<<1, 32>>>(RED);
  k_absmax<<<dim3(MLM, HEADS), 256>>>(X, RED, 0);
  k_absmax<<<dim3(MLM, HEADS), 256>>>(X, RED, 1);
  k_zinit<<<(HEADS*MLM*MLM + 255)/256, 256>>>(X, Z0, RED);

  const long long sM = (long long)MLM*MLM;
  float* zc = Z0; float* zn = Z1;
  for (int it=0; it<6; it++){
    k_bgemm64<<<dim3(4,4,HEADS), 256>>>(X,  zc, TA, MLM, sM, sM, sM, 0.f,  1.f, 1.f);
    k_bgemm64<<<dim3(4,4,HEADS), 256>>>(TA, TA, TU, MLM, sM, sM, sM, 7.f, -1.f, 1.f);
    k_bgemm64<<<dim3(4,4,HEADS), 256>>>(TA, TU, TT, MLM, sM, sM, sM, 15.f,-1.f, 1.f);
    k_bgemm64<<<dim3(4,4,HEADS), 256>>>(zc, TT, zn, MLM, sM, sM, sM, 13.f,-1.f, 0.25f);
    float* tmp = zc; zc = zn; zn = tmp;
  }

  // attn3 @ v via split-TF32 tensor cores, key-sliced partials
  k_zeroacc<<<(HEADS*MLM*DH + 255)/256, 256>>>(TA, TU);
  k_attn3v_mma<<<dim3(16, HEADS), 256, ATT3_SMEM>>>(QKV, QL, TA, TU);
  k_t3fin<<<(HEADS*MLM*DH + 255)/256, 256>>>(TA, TU, T3);

  const long long sS = (long long)MLM*DH;
  k_bgemm64<<<dim3(1,4,HEADS), 256>>>(zc, T3, Wb, DH, sM, sS, sS, 0.f, 1.f, 1.f);
  k_attn1W_mma<<<dim3(NPAD/128, HEADS), 256, ATT3_SMEM>>>(QKV, KL, Wb, AO);
  k_convres<<<NPAD/32, 256, CONV_SMEM>>>(QKV, res_w, AO);
  // out proj + residual into h (rows PADR.. of AO map to h rows 0..)
  k_mma_gemm<<<dim3(DIM/128, (NTOK+127)/128), 256, GEMM_SMEM>>>(AO + (size_t)PADR*DIM,
                                                  out_w, out_b, h, h, NTOK, DIM, DIM);
}

extern "C" void kernel_launch(void* const* d_in, const int* in_sizes, int n_in,
                              void* d_out, int out_size){
  const float* x      = (const float*)d_in[0];
  const float* cls    = (const float*)d_in[1];
  const float* ln1_w  = (const float*)d_in[2];
  const float* ln1_b  = (const float*)d_in[3];
  const float* qkv1_w = (const float*)d_in[4];
  const float* out1_w = (const float*)d_in[5];
  const float* out1_b = (const float*)d_in[6];
  const float* res1_w = (const float*)d_in[7];
  const float* p7_w   = (const float*)d_in[8];
  const float* p7_b   = (const float*)d_in[9];
  const float* p5_w   = (const float*)d_in[10];
  const float* p5_b   = (const float*)d_in[11];
  const float* p3_w   = (const float*)d_in[12];
  const float* p3_b   = (const float*)d_in[13];
  const float* ln2_w  = (const float*)d_in[14];
  const float* ln2_b  = (const float*)d_in[15];
  const float* qkv2_w = (const float*)d_in[16];
  const float* out2_w = (const float*)d_in[17];
  const float* out2_b = (const float*)d_in[18];
  const float* res2_w = (const float*)d_in[19];
  const float* norm_w = (const float*)d_in[20];
  const float* norm_b = (const float*)d_in[21];
  const float* fc2_w  = (const float*)d_in[22];
  const float* fc2_b  = (const float*)d_in[23];
  const float* pc_w   = (const float*)d_in[24];
  const float* pc_b   = (const float*)d_in[25];

  float* S = nullptr;
  cudaGetSymbolAddress((void**)&S, g_scratch);
  cudaFuncSetAttribute(k_attn3v_mma, cudaFuncAttributeMaxDynamicSharedMemorySize,
                       ATT3_SMEM);
  cudaFuncSetAttribute(k_attn1W_mma, cudaFuncAttributeMaxDynamicSharedMemorySize,
                       ATT3_SMEM);
  cudaFuncSetAttribute(k_mma_gemm, cudaFuncAttributeMaxDynamicSharedMemorySize,
                       GEMM_SMEM);
  cudaFuncSetAttribute(k_convres, cudaFuncAttributeMaxDynamicSharedMemorySize,
                       CONV_SMEM);
  cudaFuncSetAttribute(k_ppeg, cudaFuncAttributeMaxDynamicSharedMemorySize,
                       PPEG_SMEM);

  float* H0 = S + O_H0;
  float* H1 = S + O_H1;
  float* XP = S + O_XP;
  float* WC = S + O_WC;
  float* BC = S + O_BC;

  k_build<<<(NTOK*DIM + 255)/256, 256>>>(x, cls, H0);

  run_attn_block(ln1_w, ln1_b, qkv1_w, out1_w, out1_b, res1_w, H0, S);

  k_combw<<<512, 64>>>(p7_w, p7_b, p5_w, p5_b, p3_w, p3_b, WC, BC);
  k_cls<<<2, 256>>>(H0, H1);
  k_ppeg<<<dim3(1000, 4), 128, PPEG_SMEM>>>(H0, WC, BC, H1);

  run_attn_block(ln2_w, ln2_b, qkv2_w, out2_w, out2_b, res2_w, H1, S);

  k_lnpad<<<NTOK, 256>>>(H1, XP, norm_w, norm_b, 0);
  k_heads<<<(NTOK + 7)/8, 256>>>(XP, fc2_w, fc2_b, pc_w, pc_b, (float*)d_out);
}